// round 2
// baseline (speedup 1.0000x reference)
#include <cuda_runtime.h>
#include <cuda_bf16.h>
#include <math.h>

// ---------------------------------------------------------------------------
// CrossScaleAttention  (B=2, hidden=256, heads=8, head_dim=32)
// R2: packed fp32x2 FMA (FFMA2) in attention + conv1x1 inner loops.
// ---------------------------------------------------------------------------

#define B 2
#define HID 256
#define NHEAD 8
#define HD 32
#define SCALE 0.17677669529663687f  // 32^-0.5

typedef unsigned long long u64;

__device__ __forceinline__ u64 fma2(u64 a, u64 b, u64 c) {
    u64 d;
    asm("fma.rn.f32x2 %0, %1, %2, %3;" : "=l"(d) : "l"(a), "l"(b), "l"(c));
    return d;
}
__device__ __forceinline__ u64 mul2(u64 a, u64 b) {
    u64 d;
    asm("mul.rn.f32x2 %0, %1, %2;" : "=l"(d) : "l"(a), "l"(b));
    return d;
}
__device__ __forceinline__ u64 pack2(float x, float y) {
    u64 r;
    asm("mov.b64 %0, {%1, %2};" : "=l"(r) : "f"(x), "f"(y));
    return r;
}
__device__ __forceinline__ void unpack2(u64 v, float& x, float& y) {
    asm("mov.b64 {%0, %1}, %2;" : "=f"(x), "=f"(y) : "l"(v));
}

// scratch layout (floats)
#define OFF_QH   0UL
#define OFF_KL   2097152UL
#define OFF_VL   4194304UL
#define OFF_AH   6291456UL
#define OFF_KLS  8388608UL
#define OFF_VLS  8912896UL
#define OFF_QL   9437184UL
#define OFF_KH   9961472UL
#define OFF_VH   10485760UL
#define OFF_HD   11010048UL
#define OFF_AL   11272192UL
#define SCRATCH_FLOATS 11796480UL

__device__ float g_scratch[SCRATCH_FLOATS];

// ---------------------------------------------------------------------------
// Bilinear resize (jax.image.resize bilinear, antialias=False semantics)
// ---------------------------------------------------------------------------
__global__ void resize_bilinear_k(const float* __restrict__ src, float* __restrict__ dst,
                                  int BC, int Hs, int Ws, int Hd, int Wd) {
    int idx = blockIdx.x * blockDim.x + threadIdx.x;
    int total = BC * Hd * Wd;
    if (idx >= total) return;
    int x = idx % Wd;
    int y = (idx / Wd) % Hd;
    int c = idx / (Wd * Hd);

    float sy = (y + 0.5f) * (float)Hs / (float)Hd - 0.5f;
    float sx = (x + 0.5f) * (float)Ws / (float)Wd - 0.5f;
    float fy = floorf(sy), fx = floorf(sx);
    float wy = sy - fy, wx = sx - fx;
    int y0 = (int)fy, x0 = (int)fx;
    int y0c = min(max(y0, 0), Hs - 1);
    int y1c = min(max(y0 + 1, 0), Hs - 1);
    int x0c = min(max(x0, 0), Ws - 1);
    int x1c = min(max(x0 + 1, 0), Ws - 1);

    const float* s = src + (size_t)c * Hs * Ws;
    float v00 = s[y0c * Ws + x0c];
    float v01 = s[y0c * Ws + x1c];
    float v10 = s[y1c * Ws + x0c];
    float v11 = s[y1c * Ws + x1c];
    float top = v00 + wx * (v01 - v00);
    float bot = v10 + wx * (v11 - v10);
    dst[idx] = top + wy * (bot - top);
}

// ---------------------------------------------------------------------------
// conv1x1 as GEMM with FFMA2: y[b,o,p] = sum_c w[o,c]*x[b,c,p] + bias[o]
// BM=128 (O), BN=64 (P), BK=16, 256 threads, per-thread 8m x 4n register tile,
// acc pairs along m so W operand pairs come straight from LDS.128.
// Requires O%128==0? No: O must be multiple of BM only per grid; we launch
// gridDim.y = O/128 (O is 128 or 256 here). C%16==0, P%64==0.
// ---------------------------------------------------------------------------
__global__ __launch_bounds__(256) void conv1x1_k(const float* __restrict__ x,
                                                 const float* __restrict__ w,
                                                 const float* __restrict__ bias,
                                                 float* __restrict__ y,
                                                 int C, int O, int P) {
    const int BM = 128, BN = 64, BK = 16;
    int b = blockIdx.z;
    x += (size_t)b * C * P;
    y += (size_t)b * O * P;
    int m0 = blockIdx.y * BM;
    int n0 = blockIdx.x * BN;

    __shared__ __align__(16) float Ws[BK][BM];   // 8KB
    __shared__ __align__(16) float Xs[BK][BN];   // 4KB

    int tid = threadIdx.x;
    int tx = tid & 15;       // n sub-tile (4 wide)
    int ty = tid >> 4;       // m sub-tile (8 wide)

    u64 acc2[4][4];          // [m-pair][n]
    #pragma unroll
    for (int i = 0; i < 4; i++)
        #pragma unroll
        for (int j = 0; j < 4; j++) acc2[i][j] = 0ULL;

    for (int c0 = 0; c0 < C; c0 += BK) {
        // W tile: Ws[k][m] = w[(m0+m)*C + c0+k]  (2048 elems, 8/thread)
        #pragma unroll
        for (int i = 0; i < 8; i++) {
            int idx = tid + i * 256;
            int m = idx >> 4, k = idx & 15;
            Ws[k][m] = w[(size_t)(m0 + m) * C + c0 + k];
        }
        // X tile: Xs[k][n] = x[(c0+k)*P + n0+n]  (1024 elems, 4/thread)
        #pragma unroll
        for (int i = 0; i < 4; i++) {
            int idx = tid + i * 256;
            int k = idx >> 6, n = idx & 63;
            Xs[k][n] = x[(size_t)(c0 + k) * P + n0 + n];
        }
        __syncthreads();
        #pragma unroll
        for (int k = 0; k < BK; k++) {
            // 8 consecutive W values for this thread's m range -> 4 natural pairs
            const ulonglong2* wp = reinterpret_cast<const ulonglong2*>(&Ws[k][ty * 8]);
            ulonglong2 wa = wp[0], wb = wp[1];
            u64 am2[4] = {wa.x, wa.y, wb.x, wb.y};
            float4 xn = *reinterpret_cast<const float4*>(&Xs[k][tx * 4]);
            u64 an2[4] = {pack2(xn.x, xn.x), pack2(xn.y, xn.y),
                          pack2(xn.z, xn.z), pack2(xn.w, xn.w)};
            #pragma unroll
            for (int i = 0; i < 4; i++)
                #pragma unroll
                for (int j = 0; j < 4; j++)
                    acc2[i][j] = fma2(am2[i], an2[j], acc2[i][j]);
        }
        __syncthreads();
    }
    #pragma unroll
    for (int i = 0; i < 4; i++) {
        int m = m0 + ty * 8 + i * 2;
        float b0 = bias[m], b1 = bias[m + 1];
        size_t r0 = (size_t)m * P + n0 + tx * 4;
        size_t r1 = r0 + P;
        #pragma unroll
        for (int j = 0; j < 4; j++) {
            float u, v;
            unpack2(acc2[i][j], u, v);
            y[r0 + j] = u + b0;
            y[r1 + j] = v + b1;
        }
    }
}

// ---------------------------------------------------------------------------
// Multi-head attention with FFMA2. Layout [B, 256, N]; 1 thread = 1 query,
// online softmax, KV tiles of 128 in smem, ulonglong2 (LDS.128) reads.
// grid: (N/128, B*NHEAD), block: 128
// ---------------------------------------------------------------------------
__global__ __launch_bounds__(128) void attn_k(const float* __restrict__ q,
                                              const float* __restrict__ kk,
                                              const float* __restrict__ vv,
                                              float* __restrict__ out, int N) {
    int bh = blockIdx.y;
    int b = bh >> 3, h = bh & 7;
    size_t base = ((size_t)b * HID + h * HD) * N;
    int qi = blockIdx.x * 128 + threadIdx.x;

    __shared__ __align__(16) float Ks[128][36];  // row stride 144B (16B aligned)
    __shared__ __align__(16) float Vs[128][36];

    u64 q2[16];
    #pragma unroll
    for (int c = 0; c < 16; c++) {
        float a = q[base + (size_t)(2 * c) * N + qi] * SCALE;
        float bq = q[base + (size_t)(2 * c + 1) * N + qi] * SCALE;
        q2[c] = pack2(a, bq);
    }

    float m = -1e30f, l = 0.f;
    u64 acc2[16];
    #pragma unroll
    for (int c = 0; c < 16; c++) acc2[c] = 0ULL;

    for (int kv0 = 0; kv0 < N; kv0 += 128) {
        #pragma unroll
        for (int c = 0; c < HD; c++) {
            Ks[threadIdx.x][c] = kk[base + (size_t)c * N + kv0 + threadIdx.x];
            Vs[threadIdx.x][c] = vv[base + (size_t)c * N + kv0 + threadIdx.x];
        }
        __syncthreads();

        for (int j = 0; j < 128; j++) {
            const ulonglong2* K2 = reinterpret_cast<const ulonglong2*>(&Ks[j][0]);
            u64 s2a = 0ULL, s2b = 0ULL;
            #pragma unroll
            for (int cc = 0; cc < 4; cc++) {
                ulonglong2 ka = K2[2 * cc];
                ulonglong2 kb = K2[2 * cc + 1];
                s2a = fma2(q2[4 * cc + 0], ka.x, s2a);
                s2b = fma2(q2[4 * cc + 1], ka.y, s2b);
                s2a = fma2(q2[4 * cc + 2], kb.x, s2a);
                s2b = fma2(q2[4 * cc + 3], kb.y, s2b);
            }
            float sa0, sa1, sb0, sb1;
            unpack2(s2a, sa0, sa1);
            unpack2(s2b, sb0, sb1);
            float s = (sa0 + sa1) + (sb0 + sb1);

            if (s > m) {
                float corr = __expf(m - s);
                u64 c2 = pack2(corr, corr);
                #pragma unroll
                for (int c = 0; c < 16; c++) acc2[c] = mul2(c2, acc2[c]);
                l *= corr;
                m = s;
            }
            float p = __expf(s - m);
            l += p;
            u64 pp = pack2(p, p);
            const ulonglong2* V2 = reinterpret_cast<const ulonglong2*>(&Vs[j][0]);
            #pragma unroll
            for (int cc = 0; cc < 8; cc++) {
                ulonglong2 v = V2[cc];
                acc2[2 * cc + 0] = fma2(pp, v.x, acc2[2 * cc + 0]);
                acc2[2 * cc + 1] = fma2(pp, v.y, acc2[2 * cc + 1]);
            }
        }
        __syncthreads();
    }

    float inv = 1.0f / l;
    #pragma unroll
    for (int c = 0; c < 16; c++) {
        float u, v;
        unpack2(acc2[c], u, v);
        out[base + (size_t)(2 * c) * N + qi] = u * inv;
        out[base + (size_t)(2 * c + 1) * N + qi] = v * inv;
    }
}

// ---------------------------------------------------------------------------
extern "C" void kernel_launch(void* const* d_in, const int* in_sizes, int n_in,
                              void* d_out, int out_size) {
    const float* high = (const float*)d_in[0];   // [2,128,64,64]
    const float* low  = (const float*)d_in[1];   // [2,256,32,32]
    const float* qhw = (const float*)d_in[2];  const float* qhb = (const float*)d_in[3];
    const float* khw = (const float*)d_in[4];  const float* khb = (const float*)d_in[5];
    const float* vhw = (const float*)d_in[6];  const float* vhb = (const float*)d_in[7];
    const float* qlw = (const float*)d_in[8];  const float* qlb = (const float*)d_in[9];
    const float* klw = (const float*)d_in[10]; const float* klb = (const float*)d_in[11];
    const float* vlw = (const float*)d_in[12]; const float* vlb = (const float*)d_in[13];
    const float* ohw = (const float*)d_in[14]; const float* ohb = (const float*)d_in[15];
    const float* olw = (const float*)d_in[16]; const float* olb = (const float*)d_in[17];
    float* out = (float*)d_out;

    float* scr = nullptr;
    cudaGetSymbolAddress((void**)&scr, g_scratch);
    float* qh  = scr + OFF_QH;
    float* kl  = scr + OFF_KL;
    float* vl  = scr + OFF_VL;
    float* ah  = scr + OFF_AH;
    float* kls = scr + OFF_KLS;
    float* vls = scr + OFF_VLS;
    float* ql  = scr + OFF_QL;
    float* kh  = scr + OFF_KH;
    float* vh  = scr + OFF_VH;
    float* hd  = scr + OFF_HD;
    float* al  = scr + OFF_AL;

    // ---------------- high path ----------------
    // k_l/v_l at 32x32 (conv commutes with bilinear resize), then upsample
    conv1x1_k<<<dim3(16, 2, B), 256>>>(low, klw, klb, kls, 256, 256, 1024);
    conv1x1_k<<<dim3(16, 2, B), 256>>>(low, vlw, vlb, vls, 256, 256, 1024);
    resize_bilinear_k<<<(B * 256 * 64 * 64 + 255) / 256, 256>>>(kls, kl, B * 256, 32, 32, 64, 64);
    resize_bilinear_k<<<(B * 256 * 64 * 64 + 255) / 256, 256>>>(vls, vl, B * 256, 32, 32, 64, 64);
    conv1x1_k<<<dim3(64, 2, B), 256>>>(high, qhw, qhb, qh, 128, 256, 4096);
    attn_k<<<dim3(32, B * NHEAD), 128>>>(qh, kl, vl, ah, 4096);
    conv1x1_k<<<dim3(64, 1, B), 256>>>(ah, ohw, ohb, out, 256, 128, 4096);

    // ---------------- low path ----------------
    resize_bilinear_k<<<(B * 128 * 32 * 32 + 255) / 256, 256>>>(high, hd, B * 128, 64, 64, 32, 32);
    conv1x1_k<<<dim3(16, 2, B), 256>>>(hd, khw, khb, kh, 128, 256, 1024);
    conv1x1_k<<<dim3(16, 2, B), 256>>>(hd, vhw, vhb, vh, 128, 256, 1024);
    conv1x1_k<<<dim3(16, 2, B), 256>>>(low, qlw, qlb, ql, 256, 256, 1024);
    attn_k<<<dim3(8, B * NHEAD), 128>>>(ql, kh, vh, al, 1024);
    conv1x1_k<<<dim3(16, 2, B), 256>>>(al, olw, olb, out + (size_t)B * 128 * 4096, 256, 256, 1024);
}

// round 4
// speedup vs baseline: 2.8455x; 2.8455x over previous
#include <cuda_runtime.h>
#include <cuda_bf16.h>
#include <cstdint>
#include <math.h>

// ---------------------------------------------------------------------------
// CrossScaleAttention  (B=2, hidden=256, heads=8, head_dim=32)
// R4: attention via mma.sync.m16n8k16 bf16 with 3-term hi/lo split (~fp32
//     precision), no-max online softmax (O,l accumulate; no rescale).
// ---------------------------------------------------------------------------

#define B 2
#define HID 256
#define NHEAD 8
#define HD 32
#define SCALE 0.17677669529663687f  // 32^-0.5
#define KT 64

// ---------------- scratch (floats) ----------------
#define OFF_QH   0UL
#define OFF_KL   2097152UL
#define OFF_VL   4194304UL
#define OFF_AH   6291456UL
#define OFF_KLS  8388608UL
#define OFF_VLS  8912896UL
#define OFF_QL   9437184UL
#define OFF_KH   9961472UL
#define OFF_VH   10485760UL
#define OFF_HD   11010048UL
#define OFF_AL   11272192UL
#define SCRATCH_FLOATS 11796480UL
__device__ float g_scratch[SCRATCH_FLOATS];

// ---------------- helpers ----------------
// pack (f0,f1) -> bf16x2 hi (lo half = f0), and residual lo pair
__device__ __forceinline__ void split2(float f0, float f1, uint32_t& hi, uint32_t& lo) {
    asm("cvt.rn.bf16x2.f32 %0, %1, %2;" : "=r"(hi) : "f"(f1), "f"(f0));
    float h0 = __uint_as_float(hi << 16);
    float h1 = __uint_as_float(hi & 0xFFFF0000u);
    float r0 = f0 - h0, r1 = f1 - h1;
    asm("cvt.rn.bf16x2.f32 %0, %1, %2;" : "=r"(lo) : "f"(r1), "f"(r0));
}

__device__ __forceinline__ void mma_bf16(float* c, const uint32_t* a,
                                         uint32_t b0, uint32_t b1) {
    asm volatile(
        "mma.sync.aligned.m16n8k16.row.col.f32.bf16.bf16.f32 "
        "{%0,%1,%2,%3}, {%4,%5,%6,%7}, {%8,%9}, {%0,%1,%2,%3};"
        : "+f"(c[0]), "+f"(c[1]), "+f"(c[2]), "+f"(c[3])
        : "r"(a[0]), "r"(a[1]), "r"(a[2]), "r"(a[3]), "r"(b0), "r"(b1));
}

// ---------------------------------------------------------------------------
// Flash attention. q/k/v layout [B,256,N] channel-major.
// grid: (N/128, B*NHEAD), block 128 (4 warps, 32 query rows each).
// ---------------------------------------------------------------------------
__global__ __launch_bounds__(128) void attn_mma_k(const float* __restrict__ q,
                                                  const float* __restrict__ kk,
                                                  const float* __restrict__ vv,
                                                  float* __restrict__ out, int N) {
    // K tile: [buf][plane][key 64][d-pair 16, pad->20] as u32 (bf16x2 along d)
    // V tile: [buf][plane][d 32][key-pair 32, pad->36] as u32 (bf16x2 along key)
    __shared__ uint32_t Ksm[2][2][64 * 20];
    __shared__ uint32_t Vsm[2][2][32 * 36];

    int tid = threadIdx.x;
    int w = tid >> 5, lane = tid & 31;
    int g = lane >> 2, tg = lane & 3;
    int bh = blockIdx.y;
    size_t base = ((size_t)(bh >> 3) * HID + (size_t)(bh & 7) * HD) * N;
    int q0 = blockIdx.x * 128;

    // ---- Q fragments (A operand, m16n8k16), hi/lo split, scale folded ----
    uint32_t qh[2][2][4], ql[2][2][4];
    #pragma unroll
    for (int mt = 0; mt < 2; mt++)
        #pragma unroll
        for (int kt = 0; kt < 2; kt++)
            #pragma unroll
            for (int r = 0; r < 4; r++) {
                int row = q0 + w * 32 + mt * 16 + g + (r & 1) * 8;
                int d0 = kt * 16 + tg * 2 + (r >> 1) * 8;
                float f0 = q[base + (size_t)d0 * N + row] * SCALE;
                float f1 = q[base + (size_t)(d0 + 1) * N + row] * SCALE;
                split2(f0, f1, qh[mt][kt][r], ql[mt][kt][r]);
            }

    auto load_tile = [&](int buf, int kv0) {
        #pragma unroll
        for (int i = 0; i < 8; i++) {           // K: 64 keys x 16 d-pairs
            int idx = tid + i * 128;
            int key = idx & 63, dp = idx >> 6;
            float f0 = kk[base + (size_t)(2 * dp) * N + kv0 + key];
            float f1 = kk[base + (size_t)(2 * dp + 1) * N + kv0 + key];
            uint32_t hi, lo;
            split2(f0, f1, hi, lo);
            Ksm[buf][0][key * 20 + dp] = hi;
            Ksm[buf][1][key * 20 + dp] = lo;
        }
        #pragma unroll
        for (int i = 0; i < 8; i++) {           // V: 32 d x 32 key-pairs
            int idx = tid + i * 128;
            int pp = idx & 31, c = idx >> 5;
            const float* vp = &vv[base + (size_t)c * N + kv0 + 2 * pp];
            float f0 = vp[0], f1 = vp[1];
            uint32_t hi, lo;
            split2(f0, f1, hi, lo);
            Vsm[buf][0][c * 36 + pp] = hi;
            Vsm[buf][1][c * 36 + pp] = lo;
        }
    };

    float O[2][4][4] = {};
    float lacc[2][2] = {};

    load_tile(0, 0);
    __syncthreads();

    int T = N / KT;
    for (int it = 0; it < T; it++) {
        int buf = it & 1;
        const uint32_t* Kh = Ksm[buf][0];
        const uint32_t* Kl = Ksm[buf][1];
        const uint32_t* Vh = Vsm[buf][0];
        const uint32_t* Vl = Vsm[buf][1];

        #pragma unroll
        for (int mt = 0; mt < 2; mt++) {
            uint32_t pah[4], pal[4];
            #pragma unroll
            for (int j = 0; j < 8; j++) {
                float S[4] = {0.f, 0.f, 0.f, 0.f};
                #pragma unroll
                for (int kt = 0; kt < 2; kt++) {
                    int bi = (j * 8 + g) * 20 + kt * 8 + tg;
                    uint32_t bh0 = Kh[bi], bh1 = Kh[bi + 4];
                    uint32_t bl0 = Kl[bi], bl1 = Kl[bi + 4];
                    mma_bf16(S, qh[mt][kt], bh0, bh1);
                    mma_bf16(S, qh[mt][kt], bl0, bl1);
                    mma_bf16(S, ql[mt][kt], bh0, bh1);
                }
                float p0 = __expf(S[0]), p1 = __expf(S[1]);
                float p2 = __expf(S[2]), p3 = __expf(S[3]);
                lacc[mt][0] += p0 + p1;
                lacc[mt][1] += p2 + p3;
                int odd = j & 1;
                split2(p0, p1, pah[odd * 2], pal[odd * 2]);
                split2(p2, p3, pah[odd * 2 + 1], pal[odd * 2 + 1]);
                if (odd) {
                    int kt2 = j >> 1;
                    #pragma unroll
                    for (int jd = 0; jd < 4; jd++) {
                        int bi = (jd * 8 + g) * 36 + kt2 * 8 + tg;
                        uint32_t vh0 = Vh[bi], vh1 = Vh[bi + 4];
                        uint32_t vl0 = Vl[bi], vl1 = Vl[bi + 4];
                        mma_bf16(O[mt][jd], pah, vh0, vh1);
                        mma_bf16(O[mt][jd], pah, vl0, vl1);
                        mma_bf16(O[mt][jd], pal, vh0, vh1);
                    }
                }
            }
        }

        if (it + 1 < T) load_tile(buf ^ 1, (it + 1) * KT);
        __syncthreads();
    }

    // reduce l across the 4 lanes sharing a row (quad: lanes 4g..4g+3)
    #pragma unroll
    for (int mt = 0; mt < 2; mt++)
        #pragma unroll
        for (int r = 0; r < 2; r++) {
            float l = lacc[mt][r];
            l += __shfl_xor_sync(0xffffffffu, l, 1);
            l += __shfl_xor_sync(0xffffffffu, l, 2);
            lacc[mt][r] = 1.0f / l;
        }

    #pragma unroll
    for (int mt = 0; mt < 2; mt++) {
        int row0 = q0 + w * 32 + mt * 16 + g;
        #pragma unroll
        for (int jd = 0; jd < 4; jd++) {
            int d0 = jd * 8 + tg * 2;
            out[base + (size_t)d0 * N + row0]           = O[mt][jd][0] * lacc[mt][0];
            out[base + (size_t)(d0 + 1) * N + row0]     = O[mt][jd][1] * lacc[mt][0];
            out[base + (size_t)d0 * N + row0 + 8]       = O[mt][jd][2] * lacc[mt][1];
            out[base + (size_t)(d0 + 1) * N + row0 + 8] = O[mt][jd][3] * lacc[mt][1];
        }
    }
}

// ---------------------------------------------------------------------------
// Bilinear resize (jax.image.resize bilinear, antialias=False)
// ---------------------------------------------------------------------------
__global__ void resize_bilinear_k(const float* __restrict__ src, float* __restrict__ dst,
                                  int BC, int Hs, int Ws, int Hd, int Wd) {
    int idx = blockIdx.x * blockDim.x + threadIdx.x;
    int total = BC * Hd * Wd;
    if (idx >= total) return;
    int x = idx % Wd;
    int y = (idx / Wd) % Hd;
    int c = idx / (Wd * Hd);

    float sy = (y + 0.5f) * (float)Hs / (float)Hd - 0.5f;
    float sx = (x + 0.5f) * (float)Ws / (float)Wd - 0.5f;
    float fy = floorf(sy), fx = floorf(sx);
    float wy = sy - fy, wx = sx - fx;
    int y0 = (int)fy, x0 = (int)fx;
    int y0c = min(max(y0, 0), Hs - 1);
    int y1c = min(max(y0 + 1, 0), Hs - 1);
    int x0c = min(max(x0, 0), Ws - 1);
    int x1c = min(max(x0 + 1, 0), Ws - 1);

    const float* s = src + (size_t)c * Hs * Ws;
    float v00 = s[y0c * Ws + x0c];
    float v01 = s[y0c * Ws + x1c];
    float v10 = s[y1c * Ws + x0c];
    float v11 = s[y1c * Ws + x1c];
    float top = v00 + wx * (v01 - v00);
    float bot = v10 + wx * (v11 - v10);
    dst[idx] = top + wy * (bot - top);
}

// ---------------------------------------------------------------------------
// conv1x1 (R1 proven): y[b,o,p] = sum_c w[o,c] x[b,c,p] + bias[o]
// ---------------------------------------------------------------------------
__global__ void conv1x1_k(const float* __restrict__ x, const float* __restrict__ w,
                          const float* __restrict__ bias, float* __restrict__ y,
                          int C, int O, int P) {
    const int BM = 64, BN = 64, BK = 16;
    int b = blockIdx.z;
    x += (size_t)b * C * P;
    y += (size_t)b * O * P;
    int m0 = blockIdx.y * BM;
    int n0 = blockIdx.x * BN;

    __shared__ __align__(16) float Ws[BK][BM];
    __shared__ __align__(16) float Xs[BK][BN];

    int tid = threadIdx.x;
    int tx = tid & 15, ty = tid >> 4;
    float acc[4][4] = {};

    for (int c0 = 0; c0 < C; c0 += BK) {
        #pragma unroll
        for (int i = 0; i < 4; i++) {
            int idx = tid + i * 256;
            int m = idx >> 4, k = idx & 15;
            Ws[k][m] = w[(size_t)(m0 + m) * C + c0 + k];
        }
        #pragma unroll
        for (int i = 0; i < 4; i++) {
            int idx = tid + i * 256;
            int k = idx >> 6, n = idx & 63;
            Xs[k][n] = x[(size_t)(c0 + k) * P + n0 + n];
        }
        __syncthreads();
        #pragma unroll
        for (int k = 0; k < BK; k++) {
            float4 rm = *reinterpret_cast<const float4*>(&Ws[k][ty * 4]);
            float4 rn = *reinterpret_cast<const float4*>(&Xs[k][tx * 4]);
            float am[4] = {rm.x, rm.y, rm.z, rm.w};
            float an[4] = {rn.x, rn.y, rn.z, rn.w};
            #pragma unroll
            for (int i = 0; i < 4; i++)
                #pragma unroll
                for (int j = 0; j < 4; j++)
                    acc[i][j] += am[i] * an[j];
        }
        __syncthreads();
    }
    #pragma unroll
    for (int i = 0; i < 4; i++) {
        float bb = bias[m0 + ty * 4 + i];
        size_t row = (size_t)(m0 + ty * 4 + i) * P + n0 + tx * 4;
        #pragma unroll
        for (int j = 0; j < 4; j++)
            y[row + j] = acc[i][j] + bb;
    }
}

// ---------------------------------------------------------------------------
extern "C" void kernel_launch(void* const* d_in, const int* in_sizes, int n_in,
                              void* d_out, int out_size) {
    const float* high = (const float*)d_in[0];
    const float* low  = (const float*)d_in[1];
    const float* qhw = (const float*)d_in[2];  const float* qhb = (const float*)d_in[3];
    const float* khw = (const float*)d_in[4];  const float* khb = (const float*)d_in[5];
    const float* vhw = (const float*)d_in[6];  const float* vhb = (const float*)d_in[7];
    const float* qlw = (const float*)d_in[8];  const float* qlb = (const float*)d_in[9];
    const float* klw = (const float*)d_in[10]; const float* klb = (const float*)d_in[11];
    const float* vlw = (const float*)d_in[12]; const float* vlb = (const float*)d_in[13];
    const float* ohw = (const float*)d_in[14]; const float* ohb = (const float*)d_in[15];
    const float* olw = (const float*)d_in[16]; const float* olb = (const float*)d_in[17];
    float* out = (float*)d_out;

    float* scr = nullptr;
    cudaGetSymbolAddress((void**)&scr, g_scratch);
    float* qh  = scr + OFF_QH;
    float* kl  = scr + OFF_KL;
    float* vl  = scr + OFF_VL;
    float* ah  = scr + OFF_AH;
    float* kls = scr + OFF_KLS;
    float* vls = scr + OFF_VLS;
    float* ql  = scr + OFF_QL;
    float* kh  = scr + OFF_KH;
    float* vh  = scr + OFF_VH;
    float* hd  = scr + OFF_HD;
    float* al  = scr + OFF_AL;

    // ---------------- high path ----------------
    conv1x1_k<<<dim3(16, 4, B), 256>>>(low, klw, klb, kls, 256, 256, 1024);
    conv1x1_k<<<dim3(16, 4, B), 256>>>(low, vlw, vlb, vls, 256, 256, 1024);
    resize_bilinear_k<<<(B * 256 * 64 * 64 + 255) / 256, 256>>>(kls, kl, B * 256, 32, 32, 64, 64);
    resize_bilinear_k<<<(B * 256 * 64 * 64 + 255) / 256, 256>>>(vls, vl, B * 256, 32, 32, 64, 64);
    conv1x1_k<<<dim3(64, 4, B), 256>>>(high, qhw, qhb, qh, 128, 256, 4096);
    attn_mma_k<<<dim3(32, B * NHEAD), 128>>>(qh, kl, vl, ah, 4096);
    conv1x1_k<<<dim3(64, 2, B), 256>>>(ah, ohw, ohb, out, 256, 128, 4096);

    // ---------------- low path ----------------
    resize_bilinear_k<<<(B * 128 * 32 * 32 + 255) / 256, 256>>>(high, hd, B * 128, 64, 64, 32, 32);
    conv1x1_k<<<dim3(16, 4, B), 256>>>(hd, khw, khb, kh, 128, 256, 1024);
    conv1x1_k<<<dim3(16, 4, B), 256>>>(hd, vhw, vhb, vh, 128, 256, 1024);
    conv1x1_k<<<dim3(16, 4, B), 256>>>(low, qlw, qlb, ql, 256, 256, 1024);
    attn_mma_k<<<dim3(8, B * NHEAD), 128>>>(ql, kh, vh, al, 1024);
    conv1x1_k<<<dim3(16, 4, B), 256>>>(al, olw, olb, out + (size_t)B * 128 * 4096, 256, 256, 1024);
}

// round 5
// speedup vs baseline: 3.2301x; 1.1352x over previous
#include <cuda_runtime.h>
#include <cuda_bf16.h>
#include <cstdint>
#include <math.h>

// ---------------------------------------------------------------------------
// CrossScaleAttention  (B=2, hidden=256, heads=8, head_dim=32)
// R5: attention via mma.sync bf16 3-term split (R4, proven) + conv1x1 moved to
//     mma.sync bf16 3-term split + fused multi-output conv launches +
//     specialized 2x resize kernels (shift/mask index math).
// ---------------------------------------------------------------------------

#define B 2
#define HID 256
#define NHEAD 8
#define HD 32
#define SCALE 0.17677669529663687f  // 32^-0.5
#define KT 64

// ---------------- scratch (floats) ----------------
#define OFF_QH   0UL
#define OFF_KL   2097152UL
#define OFF_VL   4194304UL
#define OFF_AH   6291456UL
#define OFF_KLS  8388608UL
#define OFF_VLS  8912896UL
#define OFF_QL   9437184UL
#define OFF_KH   9961472UL
#define OFF_VH   10485760UL
#define OFF_HD   11010048UL
#define OFF_AL   11272192UL
#define SCRATCH_FLOATS 11796480UL
__device__ float g_scratch[SCRATCH_FLOATS];

// ---------------- helpers ----------------
__device__ __forceinline__ void split2(float f0, float f1, uint32_t& hi, uint32_t& lo) {
    asm("cvt.rn.bf16x2.f32 %0, %1, %2;" : "=r"(hi) : "f"(f1), "f"(f0));
    float h0 = __uint_as_float(hi << 16);
    float h1 = __uint_as_float(hi & 0xFFFF0000u);
    float r0 = f0 - h0, r1 = f1 - h1;
    asm("cvt.rn.bf16x2.f32 %0, %1, %2;" : "=r"(lo) : "f"(r1), "f"(r0));
}

__device__ __forceinline__ void mma_bf16(float* c, const uint32_t* a,
                                         uint32_t b0, uint32_t b1) {
    asm volatile(
        "mma.sync.aligned.m16n8k16.row.col.f32.bf16.bf16.f32 "
        "{%0,%1,%2,%3}, {%4,%5,%6,%7}, {%8,%9}, {%0,%1,%2,%3};"
        : "+f"(c[0]), "+f"(c[1]), "+f"(c[2]), "+f"(c[3])
        : "r"(a[0]), "r"(a[1]), "r"(a[2]), "r"(a[3]), "r"(b0), "r"(b1));
}

// ---------------------------------------------------------------------------
// Flash attention (R4, unchanged). q/k/v layout [B,256,N] channel-major.
// grid: (N/128, B*NHEAD), block 128 (4 warps, 32 query rows each).
// ---------------------------------------------------------------------------
__global__ __launch_bounds__(128) void attn_mma_k(const float* __restrict__ q,
                                                  const float* __restrict__ kk,
                                                  const float* __restrict__ vv,
                                                  float* __restrict__ out, int N) {
    __shared__ uint32_t Ksm[2][2][64 * 20];
    __shared__ uint32_t Vsm[2][2][32 * 36];

    int tid = threadIdx.x;
    int w = tid >> 5, lane = tid & 31;
    int g = lane >> 2, tg = lane & 3;
    int bh = blockIdx.y;
    size_t base = ((size_t)(bh >> 3) * HID + (size_t)(bh & 7) * HD) * N;
    int q0 = blockIdx.x * 128;

    uint32_t qh[2][2][4], ql[2][2][4];
    #pragma unroll
    for (int mt = 0; mt < 2; mt++)
        #pragma unroll
        for (int kt = 0; kt < 2; kt++)
            #pragma unroll
            for (int r = 0; r < 4; r++) {
                int row = q0 + w * 32 + mt * 16 + g + (r & 1) * 8;
                int d0 = kt * 16 + tg * 2 + (r >> 1) * 8;
                float f0 = q[base + (size_t)d0 * N + row] * SCALE;
                float f1 = q[base + (size_t)(d0 + 1) * N + row] * SCALE;
                split2(f0, f1, qh[mt][kt][r], ql[mt][kt][r]);
            }

    auto load_tile = [&](int buf, int kv0) {
        #pragma unroll
        for (int i = 0; i < 8; i++) {
            int idx = tid + i * 128;
            int key = idx & 63, dp = idx >> 6;
            float f0 = kk[base + (size_t)(2 * dp) * N + kv0 + key];
            float f1 = kk[base + (size_t)(2 * dp + 1) * N + kv0 + key];
            uint32_t hi, lo;
            split2(f0, f1, hi, lo);
            Ksm[buf][0][key * 20 + dp] = hi;
            Ksm[buf][1][key * 20 + dp] = lo;
        }
        #pragma unroll
        for (int i = 0; i < 8; i++) {
            int idx = tid + i * 128;
            int pp = idx & 31, c = idx >> 5;
            const float* vp = &vv[base + (size_t)c * N + kv0 + 2 * pp];
            float f0 = vp[0], f1 = vp[1];
            uint32_t hi, lo;
            split2(f0, f1, hi, lo);
            Vsm[buf][0][c * 36 + pp] = hi;
            Vsm[buf][1][c * 36 + pp] = lo;
        }
    };

    float O[2][4][4] = {};
    float lacc[2][2] = {};

    load_tile(0, 0);
    __syncthreads();

    int T = N / KT;
    for (int it = 0; it < T; it++) {
        int buf = it & 1;
        const uint32_t* Kh = Ksm[buf][0];
        const uint32_t* Kl = Ksm[buf][1];
        const uint32_t* Vh = Vsm[buf][0];
        const uint32_t* Vl = Vsm[buf][1];

        #pragma unroll
        for (int mt = 0; mt < 2; mt++) {
            uint32_t pah[4], pal[4];
            #pragma unroll
            for (int j = 0; j < 8; j++) {
                float S[4] = {0.f, 0.f, 0.f, 0.f};
                #pragma unroll
                for (int kt = 0; kt < 2; kt++) {
                    int bi = (j * 8 + g) * 20 + kt * 8 + tg;
                    uint32_t bh0 = Kh[bi], bh1 = Kh[bi + 4];
                    uint32_t bl0 = Kl[bi], bl1 = Kl[bi + 4];
                    mma_bf16(S, qh[mt][kt], bh0, bh1);
                    mma_bf16(S, qh[mt][kt], bl0, bl1);
                    mma_bf16(S, ql[mt][kt], bh0, bh1);
                }
                float p0 = __expf(S[0]), p1 = __expf(S[1]);
                float p2 = __expf(S[2]), p3 = __expf(S[3]);
                lacc[mt][0] += p0 + p1;
                lacc[mt][1] += p2 + p3;
                int odd = j & 1;
                split2(p0, p1, pah[odd * 2], pal[odd * 2]);
                split2(p2, p3, pah[odd * 2 + 1], pal[odd * 2 + 1]);
                if (odd) {
                    int kt2 = j >> 1;
                    #pragma unroll
                    for (int jd = 0; jd < 4; jd++) {
                        int bi = (jd * 8 + g) * 36 + kt2 * 8 + tg;
                        uint32_t vh0 = Vh[bi], vh1 = Vh[bi + 4];
                        uint32_t vl0 = Vl[bi], vl1 = Vl[bi + 4];
                        mma_bf16(O[mt][jd], pah, vh0, vh1);
                        mma_bf16(O[mt][jd], pah, vl0, vl1);
                        mma_bf16(O[mt][jd], pal, vh0, vh1);
                    }
                }
            }
        }

        if (it + 1 < T) load_tile(buf ^ 1, (it + 1) * KT);
        __syncthreads();
    }

    #pragma unroll
    for (int mt = 0; mt < 2; mt++)
        #pragma unroll
        for (int r = 0; r < 2; r++) {
            float l = lacc[mt][r];
            l += __shfl_xor_sync(0xffffffffu, l, 1);
            l += __shfl_xor_sync(0xffffffffu, l, 2);
            lacc[mt][r] = 1.0f / l;
        }

    #pragma unroll
    for (int mt = 0; mt < 2; mt++) {
        int row0 = q0 + w * 32 + mt * 16 + g;
        #pragma unroll
        for (int jd = 0; jd < 4; jd++) {
            int d0 = jd * 8 + tg * 2;
            out[base + (size_t)d0 * N + row0]           = O[mt][jd][0] * lacc[mt][0];
            out[base + (size_t)(d0 + 1) * N + row0]     = O[mt][jd][1] * lacc[mt][0];
            out[base + (size_t)d0 * N + row0 + 8]       = O[mt][jd][2] * lacc[mt][1];
            out[base + (size_t)(d0 + 1) * N + row0 + 8] = O[mt][jd][3] * lacc[mt][1];
        }
    }
}

// ---------------------------------------------------------------------------
// conv1x1 via bf16-split mma.sync. Supports up to 3 output "segments" (convs
// sharing the same input x), selected by blockIdx.y (256 O-rows per segment).
// y[seg][b,o,p] = sum_c w[seg][o,c] * x[b,c,p] + bias[seg][o]
// grid: (P/128, sum_seg O/128, B), block 256 (8 warps = 2m x 4n).
// ---------------------------------------------------------------------------
struct ConvArgs {
    const float* x;
    const float* w[3];
    const float* bias[3];
    float* y[3];
    int C, P, Ob;   // Ob = channels per segment output buffer (batch stride)
};

__global__ __launch_bounds__(256) void conv_mma_k(ConvArgs a) {
    // [tensor W/X][buf][plane hi/lo][128 rows * 12 kpair-stride]
    __shared__ uint32_t sm[2][2][2][1536];   // 48KB exactly

    int tid = threadIdx.x;
    int w = tid >> 5, lane = tid & 31, g = lane >> 2, tg = lane & 3;
    int wm = w >> 2, wn = w & 3;
    int seg = blockIdx.y >> 1;
    int m0 = (blockIdx.y & 1) << 7;
    int n0 = blockIdx.x << 7;
    int b = blockIdx.z;
    int C = a.C, P = a.P;
    const float* X = a.x + (size_t)b * C * P;
    const float* W = a.w[seg];
    const float* Bi = a.bias[seg];
    float* Y = a.y[seg] + (size_t)b * a.Ob * P;
    int nch = C >> 4;

    auto load = [&](int ch, int buf) {
        int c0 = ch << 4;
        {   // W tile: 128 m x 16 c
            int m = tid >> 1, half = tid & 1;
            const float4* src = reinterpret_cast<const float4*>(
                W + (size_t)(m0 + m) * C + c0 + half * 8);
            float4 f0 = src[0], f1 = src[1];
            uint32_t* dh = &sm[0][buf][0][m * 12 + half * 4];
            uint32_t* dl = &sm[0][buf][1][m * 12 + half * 4];
            uint32_t h, l;
            split2(f0.x, f0.y, h, l); dh[0] = h; dl[0] = l;
            split2(f0.z, f0.w, h, l); dh[1] = h; dl[1] = l;
            split2(f1.x, f1.y, h, l); dh[2] = h; dl[2] = l;
            split2(f1.z, f1.w, h, l); dh[3] = h; dl[3] = l;
        }
        // X tile: 16 c x 128 n
        #pragma unroll
        for (int i = 0; i < 4; i++) {
            int idx = tid + (i << 8);
            int kp = idx >> 7, n = idx & 127;
            float f0 = X[(size_t)(c0 + 2 * kp) * P + n0 + n];
            float f1 = X[(size_t)(c0 + 2 * kp + 1) * P + n0 + n];
            uint32_t h, l;
            split2(f0, f1, h, l);
            sm[1][buf][0][n * 12 + kp] = h;
            sm[1][buf][1][n * 12 + kp] = l;
        }
    };

    float acc[4][4][4] = {};

    load(0, 0);
    __syncthreads();

    for (int ch = 0; ch < nch; ch++) {
        int buf = ch & 1;
        if (ch + 1 < nch) load(ch + 1, buf ^ 1);

        uint32_t ah[4][4], al[4][4];
        #pragma unroll
        for (int mt = 0; mt < 4; mt++)
            #pragma unroll
            for (int r = 0; r < 4; r++) {
                int row = wm * 64 + mt * 16 + g + ((r & 1) << 3);
                int kp = tg + ((r >> 1) << 2);
                ah[mt][r] = sm[0][buf][0][row * 12 + kp];
                al[mt][r] = sm[0][buf][1][row * 12 + kp];
            }
        #pragma unroll
        for (int nt = 0; nt < 4; nt++) {
            int nrow = wn * 32 + nt * 8 + g;
            uint32_t bh0 = sm[1][buf][0][nrow * 12 + tg];
            uint32_t bh1 = sm[1][buf][0][nrow * 12 + tg + 4];
            uint32_t bl0 = sm[1][buf][1][nrow * 12 + tg];
            uint32_t bl1 = sm[1][buf][1][nrow * 12 + tg + 4];
            #pragma unroll
            for (int mt = 0; mt < 4; mt++) {
                mma_bf16(acc[mt][nt], ah[mt], bh0, bh1);
                mma_bf16(acc[mt][nt], ah[mt], bl0, bl1);
                mma_bf16(acc[mt][nt], al[mt], bh0, bh1);
            }
        }
        __syncthreads();
    }

    #pragma unroll
    for (int mt = 0; mt < 4; mt++) {
        int mrow = m0 + wm * 64 + mt * 16 + g;
        float bb0 = Bi[mrow], bb1 = Bi[mrow + 8];
        #pragma unroll
        for (int nt = 0; nt < 4; nt++) {
            int col = n0 + wn * 32 + nt * 8 + tg * 2;
            float2 v0 = {acc[mt][nt][0] + bb0, acc[mt][nt][1] + bb0};
            float2 v1 = {acc[mt][nt][2] + bb1, acc[mt][nt][3] + bb1};
            *(float2*)&Y[(size_t)mrow * P + col] = v0;
            *(float2*)&Y[(size_t)(mrow + 8) * P + col] = v1;
        }
    }
}

// ---------------------------------------------------------------------------
// 2x downsample (64x64 -> 32x32): exact 2x2 mean (bilinear align_corners=False)
// ---------------------------------------------------------------------------
__global__ void down2x_k(const float* __restrict__ src, float* __restrict__ dst,
                         int total) {
    int idx = blockIdx.x * blockDim.x + threadIdx.x;
    if (idx >= total) return;
    int x = idx & 31, y = (idx >> 5) & 31, c = idx >> 10;
    const float* s = src + ((size_t)c << 12) + (y << 7) + (x << 1);
    float2 a0 = *(const float2*)s;
    float2 a1 = *(const float2*)(s + 64);
    dst[idx] = 0.25f * ((a0.x + a0.y) + (a1.x + a1.y));
}

// ---------------------------------------------------------------------------
// 2x upsample (32x32 -> 64x64): weights 0.75/0.25, clamped at edges.
// ---------------------------------------------------------------------------
__global__ void up2x_k(const float* __restrict__ src, float* __restrict__ dst,
                       int total) {
    int idx = blockIdx.x * blockDim.x + threadIdx.x;
    if (idx >= total) return;
    int x = idx & 63, y = (idx >> 6) & 63, c = idx >> 12;
    int y0 = max((y - 1) >> 1, 0), y1 = min((y + 1) >> 1, 31);
    int x0 = max((x - 1) >> 1, 0), x1 = min((x + 1) >> 1, 31);
    float wy = (y & 1) ? 0.25f : 0.75f;   // weight on y1
    float wx = (x & 1) ? 0.25f : 0.75f;   // weight on x1
    const float* s = src + ((size_t)c << 10);
    float v00 = s[(y0 << 5) + x0];
    float v01 = s[(y0 << 5) + x1];
    float v10 = s[(y1 << 5) + x0];
    float v11 = s[(y1 << 5) + x1];
    float top = v00 + wx * (v01 - v00);
    float bot = v10 + wx * (v11 - v10);
    dst[idx] = top + wy * (bot - top);
}

// ---------------------------------------------------------------------------
extern "C" void kernel_launch(void* const* d_in, const int* in_sizes, int n_in,
                              void* d_out, int out_size) {
    const float* high = (const float*)d_in[0];
    const float* low  = (const float*)d_in[1];
    const float* qhw = (const float*)d_in[2];  const float* qhb = (const float*)d_in[3];
    const float* khw = (const float*)d_in[4];  const float* khb = (const float*)d_in[5];
    const float* vhw = (const float*)d_in[6];  const float* vhb = (const float*)d_in[7];
    const float* qlw = (const float*)d_in[8];  const float* qlb = (const float*)d_in[9];
    const float* klw = (const float*)d_in[10]; const float* klb = (const float*)d_in[11];
    const float* vlw = (const float*)d_in[12]; const float* vlb = (const float*)d_in[13];
    const float* ohw = (const float*)d_in[14]; const float* ohb = (const float*)d_in[15];
    const float* olw = (const float*)d_in[16]; const float* olb = (const float*)d_in[17];
    float* out = (float*)d_out;

    float* scr = nullptr;
    cudaGetSymbolAddress((void**)&scr, g_scratch);
    float* qh  = scr + OFF_QH;
    float* kl  = scr + OFF_KL;
    float* vl  = scr + OFF_VL;
    float* ah  = scr + OFF_AH;
    float* kls = scr + OFF_KLS;
    float* vls = scr + OFF_VLS;
    float* ql  = scr + OFF_QL;
    float* kh  = scr + OFF_KH;
    float* vh  = scr + OFF_VH;
    float* hd  = scr + OFF_HD;
    float* al  = scr + OFF_AL;

    // 1) fused low-input convs: k_low, v_low, q_low  (C=256, P=1024, 3 segs)
    {
        ConvArgs a;
        a.x = low;
        a.w[0] = klw; a.w[1] = vlw; a.w[2] = qlw;
        a.bias[0] = klb; a.bias[1] = vlb; a.bias[2] = qlb;
        a.y[0] = kls; a.y[1] = vls; a.y[2] = ql;
        a.C = 256; a.P = 1024; a.Ob = 256;
        conv_mma_k<<<dim3(8, 6, B), 256>>>(a);
    }
    // 2) downsample high 64->32 (low path KV input)
    down2x_k<<<(B * 128 * 1024 + 255) / 256, 256>>>(high, hd, B * 128 * 1024);
    // 3) fused hd convs: k_high, v_high (C=128, P=1024, 2 segs)
    {
        ConvArgs a;
        a.x = hd;
        a.w[0] = khw; a.w[1] = vhw; a.w[2] = khw;
        a.bias[0] = khb; a.bias[1] = vhb; a.bias[2] = khb;
        a.y[0] = kh; a.y[1] = vh; a.y[2] = kh;
        a.C = 128; a.P = 1024; a.Ob = 256;
        conv_mma_k<<<dim3(8, 4, B), 256>>>(a);
    }
    // 4) upsample k_low/v_low 32->64
    up2x_k<<<(B * 256 * 4096 + 255) / 256, 256>>>(kls, kl, B * 256 * 4096);
    up2x_k<<<(B * 256 * 4096 + 255) / 256, 256>>>(vls, vl, B * 256 * 4096);
    // 5) q_high conv (C=128, P=4096)
    {
        ConvArgs a;
        a.x = high;
        a.w[0] = qhw; a.w[1] = qhw; a.w[2] = qhw;
        a.bias[0] = qhb; a.bias[1] = qhb; a.bias[2] = qhb;
        a.y[0] = qh; a.y[1] = qh; a.y[2] = qh;
        a.C = 128; a.P = 4096; a.Ob = 256;
        conv_mma_k<<<dim3(32, 2, B), 256>>>(a);
    }
    // 6) high attention (N=4096)
    attn_mma_k<<<dim3(32, B * NHEAD), 128>>>(qh, kl, vl, ah, 4096);
    // 7) low attention (N=1024)
    attn_mma_k<<<dim3(8, B * NHEAD), 128>>>(ql, kh, vh, al, 1024);
    // 8) output projections
    {
        ConvArgs a;
        a.x = ah;
        a.w[0] = ohw; a.w[1] = ohw; a.w[2] = ohw;
        a.bias[0] = ohb; a.bias[1] = ohb; a.bias[2] = ohb;
        a.y[0] = out; a.y[1] = out; a.y[2] = out;
        a.C = 256; a.P = 4096; a.Ob = 128;
        conv_mma_k<<<dim3(32, 1, B), 256>>>(a);
    }
    {
        ConvArgs a;
        a.x = al;
        a.w[0] = olw; a.w[1] = olw; a.w[2] = olw;
        a.bias[0] = olb; a.bias[1] = olb; a.bias[2] = olb;
        a.y[0] = out + (size_t)B * 128 * 4096;
        a.y[1] = a.y[0]; a.y[2] = a.y[0];
        a.C = 256; a.P = 1024; a.Ob = 256;
        conv_mma_k<<<dim3(8, 2, B), 256>>>(a);
    }
}

// round 6
// speedup vs baseline: 3.7803x; 1.1703x over previous
#include <cuda_runtime.h>
#include <cuda_bf16.h>
#include <cstdint>
#include <math.h>

// ---------------------------------------------------------------------------
// CrossScaleAttention  (B=2, hidden=256, heads=8, head_dim=32)
// R6: K/V pre-split to bf16 hi/lo planes in attention-native layouts by a
//     single prep kernel (fused with 2x upsample for the high path);
//     attention tile loads via cp.async; exp via raw ex2 (log2e folded in Q);
//     high+low attention merged into one launch.
// ---------------------------------------------------------------------------

#define B 2
#define HID 256
#define NHEAD 8
#define HD 32
#define SCALE 0.17677669529663687f   // 32^-0.5
#define QSCALE (SCALE * 1.4426950408889634f)   // fold log2(e): p = ex2(S)
#define KT 64

// ---------------- fp32 scratch (floats) ----------------
#define OFF_QH   0UL                 // [2,256,4096]
#define OFF_AH   2097152UL           // [2,256,4096]
#define OFF_KLS  4194304UL           // [2,256,1024]
#define OFF_VLS  4718592UL
#define OFF_QL   5242880UL
#define OFF_KH   5767168UL
#define OFF_VH   6291456UL
#define OFF_HD   6815744UL           // [2,128,1024]
#define OFF_AL   7077888UL           // [2,256,1024]
#define SCRATCH_FLOATS 7602176UL
__device__ float g_scratch[SCRATCH_FLOATS];

// ---------------- bf16 hi/lo KV planes (u32 = bf16x2) ----------------
// High: K [bh=16][key=4096][dp=16], V [bh=16][d=32][kp=2048]  (65536/bh each)
// Low:  K [bh=16][key=1024][dp=16], V [bh=16][d=32][kp=512]   (16384/bh each)
#define OKhH 0UL
#define OKlH 1048576UL
#define OVhH 2097152UL
#define OVlH 3145728UL
#define OKhL 4194304UL
#define OKlL 4456448UL
#define OVhL 4718592UL
#define OVlL 4980736UL
#define KVU_TOTAL 5242880UL
__device__ uint32_t g_kvu[KVU_TOTAL];

// ---------------- helpers ----------------
__device__ __forceinline__ void split2(float f0, float f1, uint32_t& hi, uint32_t& lo) {
    asm("cvt.rn.bf16x2.f32 %0, %1, %2;" : "=r"(hi) : "f"(f1), "f"(f0));
    float h0 = __uint_as_float(hi << 16);
    float h1 = __uint_as_float(hi & 0xFFFF0000u);
    float r0 = f0 - h0, r1 = f1 - h1;
    asm("cvt.rn.bf16x2.f32 %0, %1, %2;" : "=r"(lo) : "f"(r1), "f"(r0));
}

__device__ __forceinline__ void mma_bf16(float* c, const uint32_t* a,
                                         uint32_t b0, uint32_t b1) {
    asm volatile(
        "mma.sync.aligned.m16n8k16.row.col.f32.bf16.bf16.f32 "
        "{%0,%1,%2,%3}, {%4,%5,%6,%7}, {%8,%9}, {%0,%1,%2,%3};"
        : "+f"(c[0]), "+f"(c[1]), "+f"(c[2]), "+f"(c[3])
        : "r"(a[0]), "r"(a[1]), "r"(a[2]), "r"(a[3]), "r"(b0), "r"(b1));
}

__device__ __forceinline__ float ex2f(float x) {
    float y;
    asm("ex2.approx.f32 %0, %1;" : "=f"(y) : "f"(x));
    return y;
}

__device__ __forceinline__ uint32_t smem_u32p(const void* p) {
    uint32_t a;
    asm("{ .reg .u64 t; cvta.to.shared.u64 t, %1; cvt.u32.u64 %0, t; }" : "=r"(a) : "l"(p));
    return a;
}

__device__ __forceinline__ void cp16(uint32_t saddr, const void* g) {
    asm volatile("cp.async.ca.shared.global [%0], [%1], 16;" :: "r"(saddr), "l"(g) : "memory");
}
#define CP_COMMIT() asm volatile("cp.async.commit_group;" ::: "memory")
#define CP_WAIT0()  asm volatile("cp.async.wait_group 0;" ::: "memory")

// bilinear 2x upsample sample (32x32 -> 64x64, align_corners=False), proven R5
__device__ __forceinline__ float up_sample(const float* __restrict__ s, int y, int x) {
    int y0 = max((y - 1) >> 1, 0), y1 = min((y + 1) >> 1, 31);
    int x0 = max((x - 1) >> 1, 0), x1 = min((x + 1) >> 1, 31);
    float wy = (y & 1) ? 0.25f : 0.75f;
    float wx = (x & 1) ? 0.25f : 0.75f;
    float v00 = s[(y0 << 5) + x0], v01 = s[(y0 << 5) + x1];
    float v10 = s[(y1 << 5) + x0], v11 = s[(y1 << 5) + x1];
    float top = v00 + wx * (v01 - v00);
    float bot = v10 + wx * (v11 - v10);
    return top + wy * (bot - top);
}

// ---------------------------------------------------------------------------
// prep_kv: build all four KV hi/lo plane sets.
//  seg1: high K (upsample kls)   seg2: high V (upsample vls)
//  seg3: low K (repack kh)       seg4: low V (repack vh)
// ---------------------------------------------------------------------------
__global__ __launch_bounds__(256) void prep_kv_k() {
    const float* kls = g_scratch + OFF_KLS;
    const float* vls = g_scratch + OFF_VLS;
    const float* kh  = g_scratch + OFF_KH;
    const float* vh  = g_scratch + OFF_VH;
    int gid = blockIdx.x * 256 + threadIdx.x;
    uint32_t hi, lo;

    if (gid < 1048576) {                 // high K: [bh][key 4096][dp 16]
        int dp = gid & 15, key = (gid >> 4) & 4095, bh = gid >> 16;
        int y = key >> 6, x = key & 63;
        const float* s = kls + (((size_t)(bh >> 3) * 256) + (bh & 7) * 32 + 2 * dp) * 1024;
        float f0 = up_sample(s, y, x);
        float f1 = up_sample(s + 1024, y, x);
        split2(f0, f1, hi, lo);
        g_kvu[OKhH + gid] = hi;
        g_kvu[OKlH + gid] = lo;
    } else if (gid < 2097152) {          // high V: [bh][d 32][kp 2048]
        int g2 = gid - 1048576;
        int kp = g2 & 2047, d = (g2 >> 11) & 31, bh = g2 >> 16;
        int key = kp << 1;
        int y = key >> 6, x = key & 63;
        const float* s = vls + (((size_t)(bh >> 3) * 256) + (bh & 7) * 32 + d) * 1024;
        float f0 = up_sample(s, y, x);
        float f1 = up_sample(s, y, x + 1);
        split2(f0, f1, hi, lo);
        g_kvu[OVhH + g2] = hi;
        g_kvu[OVlH + g2] = lo;
    } else if (gid < 2359296) {          // low K: [bh][key 1024][dp 16]
        int g3 = gid - 2097152;
        int dp = g3 & 15, key = (g3 >> 4) & 1023, bh = g3 >> 14;
        const float* s = kh + (((size_t)(bh >> 3) * 256) + (bh & 7) * 32 + 2 * dp) * 1024 + key;
        split2(s[0], s[1024], hi, lo);
        g_kvu[OKhL + g3] = hi;
        g_kvu[OKlL + g3] = lo;
    } else if (gid < 2621440) {          // low V: [bh][d 32][kp 512]
        int g4 = gid - 2359296;
        int kp = g4 & 511, d = (g4 >> 9) & 31, bh = g4 >> 14;
        const float* s = vh + (((size_t)(bh >> 3) * 256) + (bh & 7) * 32 + d) * 1024 + 2 * kp;
        split2(s[0], s[1], hi, lo);
        g_kvu[OVhL + g4] = hi;
        g_kvu[OVlL + g4] = lo;
    }
}

// ---------------------------------------------------------------------------
// Merged flash attention (high: CTAs [0,512), low: [512,640)).
// KV from pre-split planes via cp.async; no-max softmax with ex2.
// block 128 (4 warps x 32 query rows).
// ---------------------------------------------------------------------------
__global__ __launch_bounds__(128) void attn2_k(const float* __restrict__ qH,
                                               float* __restrict__ oH,
                                               const float* __restrict__ qL,
                                               float* __restrict__ oL) {
    __shared__ __align__(16) uint32_t Ksm[2][2][64 * 20];
    __shared__ __align__(16) uint32_t Vsm[2][2][32 * 36];

    int tid = threadIdx.x;
    int w = tid >> 5, lane = tid & 31;
    int g = lane >> 2, tg = lane & 3;

    int cta = blockIdx.x;
    const float* q;
    float* out;
    const uint32_t *Kgh, *Kgl, *Vgh, *Vgl;
    int N, q0, bh;
    if (cta < 512) {
        N = 4096; bh = cta >> 5; q0 = (cta & 31) << 7;
        q = qH; out = oH;
        size_t po = (size_t)bh << 16;
        Kgh = g_kvu + OKhH + po; Kgl = g_kvu + OKlH + po;
        Vgh = g_kvu + OVhH + po; Vgl = g_kvu + OVlH + po;
    } else {
        int idx = cta - 512;
        N = 1024; bh = idx >> 3; q0 = (idx & 7) << 7;
        q = qL; out = oL;
        size_t po = (size_t)bh << 14;
        Kgh = g_kvu + OKhL + po; Kgl = g_kvu + OKlL + po;
        Vgh = g_kvu + OVhL + po; Vgl = g_kvu + OVlL + po;
    }
    size_t base = (size_t)32 * bh * N;
    int halfN = N >> 1;

    uint32_t ks0 = smem_u32p(&Ksm[0][0][0]);
    uint32_t vs0 = smem_u32p(&Vsm[0][0][0]);

    // ---- Q fragments (hi/lo split, SCALE*log2e folded) ----
    uint32_t qh[2][2][4], ql[2][2][4];
    #pragma unroll
    for (int mt = 0; mt < 2; mt++)
        #pragma unroll
        for (int kt = 0; kt < 2; kt++)
            #pragma unroll
            for (int r = 0; r < 4; r++) {
                int row = q0 + w * 32 + mt * 16 + g + (r & 1) * 8;
                int d0 = kt * 16 + tg * 2 + (r >> 1) * 8;
                float f0 = q[base + (size_t)d0 * N + row] * QSCALE;
                float f1 = q[base + (size_t)(d0 + 1) * N + row] * QSCALE;
                split2(f0, f1, qh[mt][kt][r], ql[mt][kt][r]);
            }

    auto load_tile = [&](int buf, int kv0) {
        int kp0 = kv0 >> 1;
        #pragma unroll
        for (int i = 0; i < 4; i++) {        // K: 512 x 16B
            int id = tid + (i << 7);
            int plane = id >> 8, r = id & 255;
            int key = r >> 2, c4 = (r & 3) << 2;
            const uint32_t* gp = (plane ? Kgl : Kgh) + (size_t)(kv0 + key) * 16 + c4;
            uint32_t sa = ks0 + (uint32_t)(((buf * 2 + plane) * 1280) + key * 20 + c4) * 4;
            cp16(sa, gp);
        }
        #pragma unroll
        for (int i = 0; i < 4; i++) {        // V: 512 x 16B
            int id = tid + (i << 7);
            int plane = id >> 8, r = id & 255;
            int d = r >> 3, c = (r & 7) << 2;
            const uint32_t* gp = (plane ? Vgl : Vgh) + (size_t)d * halfN + kp0 + c;
            uint32_t sa = vs0 + (uint32_t)(((buf * 2 + plane) * 1152) + d * 36 + c) * 4;
            cp16(sa, gp);
        }
        CP_COMMIT();
    };

    float O[2][4][4] = {};
    float lacc[2][2] = {};

    load_tile(0, 0);
    CP_WAIT0();
    __syncthreads();

    int T = N / KT;
    for (int it = 0; it < T; it++) {
        int buf = it & 1;
        if (it + 1 < T) load_tile(buf ^ 1, (it + 1) * KT);

        const uint32_t* Kh = Ksm[buf][0];
        const uint32_t* Kl = Ksm[buf][1];
        const uint32_t* Vh = Vsm[buf][0];
        const uint32_t* Vl = Vsm[buf][1];

        #pragma unroll
        for (int mt = 0; mt < 2; mt++) {
            uint32_t pah[4], pal[4];
            #pragma unroll
            for (int j = 0; j < 8; j++) {
                float S[4] = {0.f, 0.f, 0.f, 0.f};
                #pragma unroll
                for (int kt = 0; kt < 2; kt++) {
                    int bi = (j * 8 + g) * 20 + kt * 8 + tg;
                    uint32_t bh0 = Kh[bi], bh1 = Kh[bi + 4];
                    uint32_t bl0 = Kl[bi], bl1 = Kl[bi + 4];
                    mma_bf16(S, qh[mt][kt], bh0, bh1);
                    mma_bf16(S, qh[mt][kt], bl0, bl1);
                    mma_bf16(S, ql[mt][kt], bh0, bh1);
                }
                float p0 = ex2f(S[0]), p1 = ex2f(S[1]);
                float p2 = ex2f(S[2]), p3 = ex2f(S[3]);
                lacc[mt][0] += p0 + p1;
                lacc[mt][1] += p2 + p3;
                int odd = j & 1;
                split2(p0, p1, pah[odd * 2], pal[odd * 2]);
                split2(p2, p3, pah[odd * 2 + 1], pal[odd * 2 + 1]);
                if (odd) {
                    int kt2 = j >> 1;
                    #pragma unroll
                    for (int jd = 0; jd < 4; jd++) {
                        int bi = (jd * 8 + g) * 36 + kt2 * 8 + tg;
                        uint32_t vh0 = Vh[bi], vh1 = Vh[bi + 4];
                        uint32_t vl0 = Vl[bi], vl1 = Vl[bi + 4];
                        mma_bf16(O[mt][jd], pah, vh0, vh1);
                        mma_bf16(O[mt][jd], pah, vl0, vl1);
                        mma_bf16(O[mt][jd], pal, vh0, vh1);
                    }
                }
            }
        }

        if (it + 1 < T) CP_WAIT0();
        __syncthreads();
    }

    #pragma unroll
    for (int mt = 0; mt < 2; mt++)
        #pragma unroll
        for (int r = 0; r < 2; r++) {
            float l = lacc[mt][r];
            l += __shfl_xor_sync(0xffffffffu, l, 1);
            l += __shfl_xor_sync(0xffffffffu, l, 2);
            lacc[mt][r] = 1.0f / l;
        }

    #pragma unroll
    for (int mt = 0; mt < 2; mt++) {
        int row0 = q0 + w * 32 + mt * 16 + g;
        #pragma unroll
        for (int jd = 0; jd < 4; jd++) {
            int d0 = jd * 8 + tg * 2;
            out[base + (size_t)d0 * N + row0]           = O[mt][jd][0] * lacc[mt][0];
            out[base + (size_t)(d0 + 1) * N + row0]     = O[mt][jd][1] * lacc[mt][0];
            out[base + (size_t)d0 * N + row0 + 8]       = O[mt][jd][2] * lacc[mt][1];
            out[base + (size_t)(d0 + 1) * N + row0 + 8] = O[mt][jd][3] * lacc[mt][1];
        }
    }
}

// ---------------------------------------------------------------------------
// conv1x1 via bf16-split mma.sync (R5, proven). Up to 3 segments per launch.
// ---------------------------------------------------------------------------
struct ConvArgs {
    const float* x;
    const float* w[3];
    const float* bias[3];
    float* y[3];
    int C, P, Ob;
};

__global__ __launch_bounds__(256) void conv_mma_k(ConvArgs a) {
    __shared__ uint32_t sm[2][2][2][1536];   // 48KB

    int tid = threadIdx.x;
    int w = tid >> 5, lane = tid & 31, g = lane >> 2, tg = lane & 3;
    int wm = w >> 2, wn = w & 3;
    int seg = blockIdx.y >> 1;
    int m0 = (blockIdx.y & 1) << 7;
    int n0 = blockIdx.x << 7;
    int b = blockIdx.z;
    int C = a.C, P = a.P;
    const float* X = a.x + (size_t)b * C * P;
    const float* W = a.w[seg];
    const float* Bi = a.bias[seg];
    float* Y = a.y[seg] + (size_t)b * a.Ob * P;
    int nch = C >> 4;

    auto load = [&](int ch, int buf) {
        int c0 = ch << 4;
        {
            int m = tid >> 1, half = tid & 1;
            const float4* src = reinterpret_cast<const float4*>(
                W + (size_t)(m0 + m) * C + c0 + half * 8);
            float4 f0 = src[0], f1 = src[1];
            uint32_t* dh = &sm[0][buf][0][m * 12 + half * 4];
            uint32_t* dl = &sm[0][buf][1][m * 12 + half * 4];
            uint32_t h, l;
            split2(f0.x, f0.y, h, l); dh[0] = h; dl[0] = l;
            split2(f0.z, f0.w, h, l); dh[1] = h; dl[1] = l;
            split2(f1.x, f1.y, h, l); dh[2] = h; dl[2] = l;
            split2(f1.z, f1.w, h, l); dh[3] = h; dl[3] = l;
        }
        #pragma unroll
        for (int i = 0; i < 4; i++) {
            int idx = tid + (i << 8);
            int kp = idx >> 7, n = idx & 127;
            float f0 = X[(size_t)(c0 + 2 * kp) * P + n0 + n];
            float f1 = X[(size_t)(c0 + 2 * kp + 1) * P + n0 + n];
            uint32_t h, l;
            split2(f0, f1, h, l);
            sm[1][buf][0][n * 12 + kp] = h;
            sm[1][buf][1][n * 12 + kp] = l;
        }
    };

    float acc[4][4][4] = {};

    load(0, 0);
    __syncthreads();

    for (int ch = 0; ch < nch; ch++) {
        int buf = ch & 1;
        if (ch + 1 < nch) load(ch + 1, buf ^ 1);

        uint32_t ah[4][4], al[4][4];
        #pragma unroll
        for (int mt = 0; mt < 4; mt++)
            #pragma unroll
            for (int r = 0; r < 4; r++) {
                int row = wm * 64 + mt * 16 + g + ((r & 1) << 3);
                int kp = tg + ((r >> 1) << 2);
                ah[mt][r] = sm[0][buf][0][row * 12 + kp];
                al[mt][r] = sm[0][buf][1][row * 12 + kp];
            }
        #pragma unroll
        for (int nt = 0; nt < 4; nt++) {
            int nrow = wn * 32 + nt * 8 + g;
            uint32_t bh0 = sm[1][buf][0][nrow * 12 + tg];
            uint32_t bh1 = sm[1][buf][0][nrow * 12 + tg + 4];
            uint32_t bl0 = sm[1][buf][1][nrow * 12 + tg];
            uint32_t bl1 = sm[1][buf][1][nrow * 12 + tg + 4];
            #pragma unroll
            for (int mt = 0; mt < 4; mt++) {
                mma_bf16(acc[mt][nt], ah[mt], bh0, bh1);
                mma_bf16(acc[mt][nt], ah[mt], bl0, bl1);
                mma_bf16(acc[mt][nt], al[mt], bh0, bh1);
            }
        }
        __syncthreads();
    }

    #pragma unroll
    for (int mt = 0; mt < 4; mt++) {
        int mrow = m0 + wm * 64 + mt * 16 + g;
        float bb0 = Bi[mrow], bb1 = Bi[mrow + 8];
        #pragma unroll
        for (int nt = 0; nt < 4; nt++) {
            int col = n0 + wn * 32 + nt * 8 + tg * 2;
            float2 v0 = {acc[mt][nt][0] + bb0, acc[mt][nt][1] + bb0};
            float2 v1 = {acc[mt][nt][2] + bb1, acc[mt][nt][3] + bb1};
            *(float2*)&Y[(size_t)mrow * P + col] = v0;
            *(float2*)&Y[(size_t)(mrow + 8) * P + col] = v1;
        }
    }
}

// ---------------------------------------------------------------------------
// 2x downsample (64x64 -> 32x32): exact 2x2 mean
// ---------------------------------------------------------------------------
__global__ void down2x_k(const float* __restrict__ src, float* __restrict__ dst,
                         int total) {
    int idx = blockIdx.x * blockDim.x + threadIdx.x;
    if (idx >= total) return;
    int x = idx & 31, y = (idx >> 5) & 31, c = idx >> 10;
    const float* s = src + ((size_t)c << 12) + (y << 7) + (x << 1);
    float2 a0 = *(const float2*)s;
    float2 a1 = *(const float2*)(s + 64);
    dst[idx] = 0.25f * ((a0.x + a0.y) + (a1.x + a1.y));
}

// ---------------------------------------------------------------------------
extern "C" void kernel_launch(void* const* d_in, const int* in_sizes, int n_in,
                              void* d_out, int out_size) {
    const float* high = (const float*)d_in[0];
    const float* low  = (const float*)d_in[1];
    const float* qhw = (const float*)d_in[2];  const float* qhb = (const float*)d_in[3];
    const float* khw = (const float*)d_in[4];  const float* khb = (const float*)d_in[5];
    const float* vhw = (const float*)d_in[6];  const float* vhb = (const float*)d_in[7];
    const float* qlw = (const float*)d_in[8];  const float* qlb = (const float*)d_in[9];
    const float* klw = (const float*)d_in[10]; const float* klb = (const float*)d_in[11];
    const float* vlw = (const float*)d_in[12]; const float* vlb = (const float*)d_in[13];
    const float* ohw = (const float*)d_in[14]; const float* ohb = (const float*)d_in[15];
    const float* olw = (const float*)d_in[16]; const float* olb = (const float*)d_in[17];
    float* out = (float*)d_out;

    float* scr = nullptr;
    cudaGetSymbolAddress((void**)&scr, g_scratch);
    float* qh  = scr + OFF_QH;
    float* ah  = scr + OFF_AH;
    float* kls = scr + OFF_KLS;
    float* vls = scr + OFF_VLS;
    float* ql  = scr + OFF_QL;
    float* kh  = scr + OFF_KH;
    float* vh  = scr + OFF_VH;
    float* hd  = scr + OFF_HD;
    float* al  = scr + OFF_AL;

    // 1) fused low-input convs: k_low, v_low, q_low
    {
        ConvArgs a;
        a.x = low;
        a.w[0] = klw; a.w[1] = vlw; a.w[2] = qlw;
        a.bias[0] = klb; a.bias[1] = vlb; a.bias[2] = qlb;
        a.y[0] = kls; a.y[1] = vls; a.y[2] = ql;
        a.C = 256; a.P = 1024; a.Ob = 256;
        conv_mma_k<<<dim3(8, 6, B), 256>>>(a);
    }
    // 2) downsample high 64->32
    down2x_k<<<(B * 128 * 1024 + 255) / 256, 256>>>(high, hd, B * 128 * 1024);
    // 3) fused hd convs: k_high, v_high
    {
        ConvArgs a;
        a.x = hd;
        a.w[0] = khw; a.w[1] = vhw; a.w[2] = khw;
        a.bias[0] = khb; a.bias[1] = vhb; a.bias[2] = khb;
        a.y[0] = kh; a.y[1] = vh; a.y[2] = kh;
        a.C = 128; a.P = 1024; a.Ob = 256;
        conv_mma_k<<<dim3(8, 4, B), 256>>>(a);
    }
    // 4) q_high conv
    {
        ConvArgs a;
        a.x = high;
        a.w[0] = qhw; a.w[1] = qhw; a.w[2] = qhw;
        a.bias[0] = qhb; a.bias[1] = qhb; a.bias[2] = qhb;
        a.y[0] = qh; a.y[1] = qh; a.y[2] = qh;
        a.C = 128; a.P = 4096; a.Ob = 256;
        conv_mma_k<<<dim3(32, 2, B), 256>>>(a);
    }
    // 5) build all bf16 KV planes (fused upsample + split + repack)
    prep_kv_k<<<10240, 256>>>();
    // 6) merged attention (high 512 CTAs + low 128 CTAs)
    attn2_k<<<640, 128>>>(qh, ah, ql, al);
    // 7) output projections
    {
        ConvArgs a;
        a.x = ah;
        a.w[0] = ohw; a.w[1] = ohw; a.w[2] = ohw;
        a.bias[0] = ohb; a.bias[1] = ohb; a.bias[2] = ohb;
        a.y[0] = out; a.y[1] = out; a.y[2] = out;
        a.C = 256; a.P = 4096; a.Ob = 128;
        conv_mma_k<<<dim3(32, 1, B), 256>>>(a);
    }
    {
        ConvArgs a;
        a.x = al;
        a.w[0] = olw; a.w[1] = olw; a.w[2] = olw;
        a.bias[0] = olb; a.bias[1] = olb; a.bias[2] = olb;
        a.y[0] = out + (size_t)B * 128 * 4096;
        a.y[1] = a.y[0]; a.y[2] = a.y[0];
        a.C = 256; a.P = 1024; a.Ob = 256;
        conv_mma_k<<<dim3(8, 2, B), 256>>>(a);
    }
}

// round 7
// speedup vs baseline: 5.5334x; 1.4638x over previous
#include <cuda_runtime.h>
#include <cuda_bf16.h>
#include <cstdint>
#include <math.h>

// ---------------------------------------------------------------------------
// CrossScaleAttention  (B=2, hidden=256, heads=8, head_dim=32)
// R7: K/V/P in plain bf16 (Q keeps hi/lo split; exp/l/O-accum in fp32) ->
//     96 MMAs per tile instead of 192, half the cp.async traffic.
//     Conv tiles 128x64 for 2x CTA count (latency hiding).
// ---------------------------------------------------------------------------

#define B 2
#define HID 256
#define NHEAD 8
#define HD 32
#define SCALE 0.17677669529663687f
#define QSCALE (SCALE * 1.4426950408889634f)   // fold log2(e): p = ex2(S)
#define KT 64

// ---------------- fp32 scratch ----------------
#define OFF_QH   0UL                 // [2,256,4096]
#define OFF_AH   2097152UL           // [2,256,4096]
#define OFF_KLS  4194304UL           // [2,256,1024]
#define OFF_VLS  4718592UL
#define OFF_QL   5242880UL
#define OFF_KH   5767168UL
#define OFF_VH   6291456UL
#define OFF_HD   6815744UL           // [2,128,1024]
#define OFF_AL   7077888UL           // [2,256,1024]
#define SCRATCH_FLOATS 7602176UL
__device__ float g_scratch[SCRATCH_FLOATS];

// ---------------- bf16 KV planes (u32 = bf16x2) ----------------
// High: K [bh=16][key=4096][dp=16], V [bh=16][d=32][kp=2048]
// Low:  K [bh=16][key=1024][dp=16], V [bh=16][d=32][kp=512]
#define OKH_H 0UL
#define OVH_H 1048576UL
#define OKH_L 2097152UL
#define OVH_L 2359296UL
#define KVU_TOTAL 2621440UL
__device__ uint32_t g_kvu[KVU_TOTAL];

// ---------------- helpers ----------------
__device__ __forceinline__ uint32_t pack2rn(float f0, float f1) {
    uint32_t r;
    asm("cvt.rn.bf16x2.f32 %0, %1, %2;" : "=r"(r) : "f"(f1), "f"(f0));
    return r;
}
__device__ __forceinline__ void split2(float f0, float f1, uint32_t& hi, uint32_t& lo) {
    asm("cvt.rn.bf16x2.f32 %0, %1, %2;" : "=r"(hi) : "f"(f1), "f"(f0));
    float h0 = __uint_as_float(hi << 16);
    float h1 = __uint_as_float(hi & 0xFFFF0000u);
    float r0 = f0 - h0, r1 = f1 - h1;
    asm("cvt.rn.bf16x2.f32 %0, %1, %2;" : "=r"(lo) : "f"(r1), "f"(r0));
}

__device__ __forceinline__ void mma_bf16(float* c, const uint32_t* a,
                                         uint32_t b0, uint32_t b1) {
    asm volatile(
        "mma.sync.aligned.m16n8k16.row.col.f32.bf16.bf16.f32 "
        "{%0,%1,%2,%3}, {%4,%5,%6,%7}, {%8,%9}, {%0,%1,%2,%3};"
        : "+f"(c[0]), "+f"(c[1]), "+f"(c[2]), "+f"(c[3])
        : "r"(a[0]), "r"(a[1]), "r"(a[2]), "r"(a[3]), "r"(b0), "r"(b1));
}

__device__ __forceinline__ float ex2f(float x) {
    float y;
    asm("ex2.approx.f32 %0, %1;" : "=f"(y) : "f"(x));
    return y;
}

__device__ __forceinline__ uint32_t smem_u32p(const void* p) {
    uint32_t a;
    asm("{ .reg .u64 t; cvta.to.shared.u64 t, %1; cvt.u32.u64 %0, t; }" : "=r"(a) : "l"(p));
    return a;
}
__device__ __forceinline__ void cp16(uint32_t saddr, const void* g) {
    asm volatile("cp.async.ca.shared.global [%0], [%1], 16;" :: "r"(saddr), "l"(g) : "memory");
}
#define CP_COMMIT() asm volatile("cp.async.commit_group;" ::: "memory")
#define CP_WAIT0()  asm volatile("cp.async.wait_group 0;" ::: "memory")

// bilinear 2x upsample sample (32x32 -> 64x64, align_corners=False)
__device__ __forceinline__ float up_sample(const float* __restrict__ s, int y, int x) {
    int y0 = max((y - 1) >> 1, 0), y1 = min((y + 1) >> 1, 31);
    int x0 = max((x - 1) >> 1, 0), x1 = min((x + 1) >> 1, 31);
    float wy = (y & 1) ? 0.25f : 0.75f;
    float wx = (x & 1) ? 0.25f : 0.75f;
    float v00 = s[(y0 << 5) + x0], v01 = s[(y0 << 5) + x1];
    float v10 = s[(y1 << 5) + x0], v11 = s[(y1 << 5) + x1];
    float top = v00 + wx * (v01 - v00);
    float bot = v10 + wx * (v11 - v10);
    return top + wy * (bot - top);
}

// ---------------------------------------------------------------------------
// prep_kv: build bf16 KV planes (hi only).
// ---------------------------------------------------------------------------
__global__ __launch_bounds__(256) void prep_kv_k() {
    const float* kls = g_scratch + OFF_KLS;
    const float* vls = g_scratch + OFF_VLS;
    const float* kh  = g_scratch + OFF_KH;
    const float* vh  = g_scratch + OFF_VH;
    int gid = blockIdx.x * 256 + threadIdx.x;

    if (gid < 1048576) {                 // high K: [bh][key 4096][dp 16]
        int dp = gid & 15, key = (gid >> 4) & 4095, bh = gid >> 16;
        int y = key >> 6, x = key & 63;
        const float* s = kls + (((size_t)(bh >> 3) * 256) + (bh & 7) * 32 + 2 * dp) * 1024;
        g_kvu[OKH_H + gid] = pack2rn(up_sample(s, y, x), up_sample(s + 1024, y, x));
    } else if (gid < 2097152) {          // high V: [bh][d 32][kp 2048]
        int g2 = gid - 1048576;
        int kp = g2 & 2047, d = (g2 >> 11) & 31, bh = g2 >> 16;
        int key = kp << 1;
        int y = key >> 6, x = key & 63;
        const float* s = vls + (((size_t)(bh >> 3) * 256) + (bh & 7) * 32 + d) * 1024;
        g_kvu[OVH_H + g2] = pack2rn(up_sample(s, y, x), up_sample(s, y, x + 1));
    } else if (gid < 2359296) {          // low K: [bh][key 1024][dp 16]
        int g3 = gid - 2097152;
        int dp = g3 & 15, key = (g3 >> 4) & 1023, bh = g3 >> 14;
        const float* s = kh + (((size_t)(bh >> 3) * 256) + (bh & 7) * 32 + 2 * dp) * 1024 + key;
        g_kvu[OKH_L + g3] = pack2rn(s[0], s[1024]);
    } else if (gid < 2621440) {          // low V: [bh][d 32][kp 512]
        int g4 = gid - 2359296;
        int kp = g4 & 511, d = (g4 >> 9) & 31, bh = g4 >> 14;
        const float* s = vh + (((size_t)(bh >> 3) * 256) + (bh & 7) * 32 + d) * 1024 + 2 * kp;
        g_kvu[OVH_L + g4] = pack2rn(s[0], s[1]);
    }
}

// ---------------------------------------------------------------------------
// Merged flash attention (high: CTAs [0,512), low: [512,640)).
// K/V/P bf16, Q hi/lo split, fp32 exp/l/O. block 128 (4 warps x 32 rows).
// ---------------------------------------------------------------------------
__global__ __launch_bounds__(128) void attn2_k(const float* __restrict__ qH,
                                               float* __restrict__ oH,
                                               const float* __restrict__ qL,
                                               float* __restrict__ oL) {
    __shared__ __align__(16) uint32_t Ksm[2][64 * 20];
    __shared__ __align__(16) uint32_t Vsm[2][32 * 36];

    int tid = threadIdx.x;
    int w = tid >> 5, lane = tid & 31;
    int g = lane >> 2, tg = lane & 3;

    int cta = blockIdx.x;
    const float* q;
    float* out;
    const uint32_t *Kg, *Vg;
    int N, q0, bh;
    if (cta < 512) {
        N = 4096; bh = cta >> 5; q0 = (cta & 31) << 7;
        q = qH; out = oH;
        Kg = g_kvu + OKH_H + ((size_t)bh << 16);
        Vg = g_kvu + OVH_H + ((size_t)bh << 16);
    } else {
        int idx = cta - 512;
        N = 1024; bh = idx >> 3; q0 = (idx & 7) << 7;
        q = qL; out = oL;
        Kg = g_kvu + OKH_L + ((size_t)bh << 14);
        Vg = g_kvu + OVH_L + ((size_t)bh << 14);
    }
    size_t base = (size_t)32 * bh * N;
    int halfN = N >> 1;

    uint32_t ks0 = smem_u32p(&Ksm[0][0]);
    uint32_t vs0 = smem_u32p(&Vsm[0][0]);

    // ---- Q fragments (hi/lo split, QSCALE folded) ----
    uint32_t qh[2][2][4], ql[2][2][4];
    #pragma unroll
    for (int mt = 0; mt < 2; mt++)
        #pragma unroll
        for (int kt = 0; kt < 2; kt++)
            #pragma unroll
            for (int r = 0; r < 4; r++) {
                int row = q0 + w * 32 + mt * 16 + g + (r & 1) * 8;
                int d0 = kt * 16 + tg * 2 + (r >> 1) * 8;
                float f0 = q[base + (size_t)d0 * N + row] * QSCALE;
                float f1 = q[base + (size_t)(d0 + 1) * N + row] * QSCALE;
                split2(f0, f1, qh[mt][kt][r], ql[mt][kt][r]);
            }

    auto load_tile = [&](int buf, int kv0) {
        int kp0 = kv0 >> 1;
        #pragma unroll
        for (int i = 0; i < 2; i++) {        // K: 256 x 16B
            int id = tid + (i << 7);
            int key = id >> 2, c4 = (id & 3) << 2;
            cp16(ks0 + (uint32_t)(buf * 1280 + key * 20 + c4) * 4,
                 Kg + (size_t)(kv0 + key) * 16 + c4);
        }
        #pragma unroll
        for (int i = 0; i < 2; i++) {        // V: 256 x 16B
            int id = tid + (i << 7);
            int d = id >> 3, c = (id & 7) << 2;
            cp16(vs0 + (uint32_t)(buf * 1152 + d * 36 + c) * 4,
                 Vg + (size_t)d * halfN + kp0 + c);
        }
        CP_COMMIT();
    };

    float O[2][4][4] = {};
    float lacc[2][2] = {};

    load_tile(0, 0);
    CP_WAIT0();
    __syncthreads();

    int T = N / KT;
    for (int it = 0; it < T; it++) {
        int buf = it & 1;
        if (it + 1 < T) load_tile(buf ^ 1, (it + 1) * KT);

        const uint32_t* Kh = Ksm[buf];
        const uint32_t* Vh = Vsm[buf];

        #pragma unroll
        for (int mt = 0; mt < 2; mt++) {
            uint32_t pah[4];
            #pragma unroll
            for (int j = 0; j < 8; j++) {
                float S[4] = {0.f, 0.f, 0.f, 0.f};
                #pragma unroll
                for (int kt = 0; kt < 2; kt++) {
                    int bi = (j * 8 + g) * 20 + kt * 8 + tg;
                    uint32_t b0 = Kh[bi], b1 = Kh[bi + 4];
                    mma_bf16(S, qh[mt][kt], b0, b1);
                    mma_bf16(S, ql[mt][kt], b0, b1);
                }
                float p0 = ex2f(S[0]), p1 = ex2f(S[1]);
                float p2 = ex2f(S[2]), p3 = ex2f(S[3]);
                lacc[mt][0] += p0 + p1;
                lacc[mt][1] += p2 + p3;
                int odd = j & 1;
                pah[odd * 2]     = pack2rn(p0, p1);
                pah[odd * 2 + 1] = pack2rn(p2, p3);
                if (odd) {
                    int kt2 = j >> 1;
                    #pragma unroll
                    for (int jd = 0; jd < 4; jd++) {
                        int bi = (jd * 8 + g) * 36 + kt2 * 8 + tg;
                        mma_bf16(O[mt][jd], pah, Vh[bi], Vh[bi + 4]);
                    }
                }
            }
        }

        if (it + 1 < T) CP_WAIT0();
        __syncthreads();
    }

    #pragma unroll
    for (int mt = 0; mt < 2; mt++)
        #pragma unroll
        for (int r = 0; r < 2; r++) {
            float l = lacc[mt][r];
            l += __shfl_xor_sync(0xffffffffu, l, 1);
            l += __shfl_xor_sync(0xffffffffu, l, 2);
            lacc[mt][r] = 1.0f / l;
        }

    #pragma unroll
    for (int mt = 0; mt < 2; mt++) {
        int row0 = q0 + w * 32 + mt * 16 + g;
        #pragma unroll
        for (int jd = 0; jd < 4; jd++) {
            int d0 = jd * 8 + tg * 2;
            out[base + (size_t)d0 * N + row0]           = O[mt][jd][0] * lacc[mt][0];
            out[base + (size_t)(d0 + 1) * N + row0]     = O[mt][jd][1] * lacc[mt][0];
            out[base + (size_t)d0 * N + row0 + 8]       = O[mt][jd][2] * lacc[mt][1];
            out[base + (size_t)(d0 + 1) * N + row0 + 8] = O[mt][jd][3] * lacc[mt][1];
        }
    }
}

// ---------------------------------------------------------------------------
// conv1x1 via bf16-split mma.sync, 3-term (kept full precision).
// BM=128, BN=64, 256 threads (8 warps = 4m x 2n), K-chunk 16, double-buffered.
// Up to 3 output segments per launch via blockIdx.y.
// ---------------------------------------------------------------------------
struct ConvArgs {
    const float* x;
    const float* w[3];
    const float* bias[3];
    float* y[3];
    int C, P, Ob;
};

__global__ __launch_bounds__(256) void conv_mma_k(ConvArgs a) {
    __shared__ uint32_t smW[2][2][1536];   // [buf][plane][128m x 12]
    __shared__ uint32_t smX[2][2][768];    // [buf][plane][64n x 12]

    int tid = threadIdx.x;
    int w = tid >> 5, lane = tid & 31, g = lane >> 2, tg = lane & 3;
    int wm = w >> 1, wn = w & 1;
    int seg = blockIdx.y >> 1;
    int m0 = (blockIdx.y & 1) << 7;
    int n0 = blockIdx.x << 6;
    int b = blockIdx.z;
    int C = a.C, P = a.P;
    const float* X = a.x + (size_t)b * C * P;
    const float* W = a.w[seg];
    const float* Bi = a.bias[seg];
    float* Y = a.y[seg] + (size_t)b * a.Ob * P;
    int nch = C >> 4;

    auto load = [&](int ch, int buf) {
        int c0 = ch << 4;
        {   // W tile: 128 m x 16 c
            int m = tid >> 1, half = tid & 1;
            const float4* src = reinterpret_cast<const float4*>(
                W + (size_t)(m0 + m) * C + c0 + half * 8);
            float4 f0 = src[0], f1 = src[1];
            uint32_t* dh = &smW[buf][0][m * 12 + half * 4];
            uint32_t* dl = &smW[buf][1][m * 12 + half * 4];
            uint32_t h, l;
            split2(f0.x, f0.y, h, l); dh[0] = h; dl[0] = l;
            split2(f0.z, f0.w, h, l); dh[1] = h; dl[1] = l;
            split2(f1.x, f1.y, h, l); dh[2] = h; dl[2] = l;
            split2(f1.z, f1.w, h, l); dh[3] = h; dl[3] = l;
        }
        // X tile: 16 c x 64 n (512 pairs, 2/thread)
        #pragma unroll
        for (int i = 0; i < 2; i++) {
            int idx = tid + (i << 8);
            int kp = idx >> 6, n = idx & 63;
            float f0 = X[(size_t)(c0 + 2 * kp) * P + n0 + n];
            float f1 = X[(size_t)(c0 + 2 * kp + 1) * P + n0 + n];
            uint32_t h, l;
            split2(f0, f1, h, l);
            smX[buf][0][n * 12 + kp] = h;
            smX[buf][1][n * 12 + kp] = l;
        }
    };

    float acc[2][4][4] = {};

    load(0, 0);
    __syncthreads();

    for (int ch = 0; ch < nch; ch++) {
        int buf = ch & 1;
        if (ch + 1 < nch) load(ch + 1, buf ^ 1);

        uint32_t ah[2][4], al[2][4];
        #pragma unroll
        for (int mt = 0; mt < 2; mt++)
            #pragma unroll
            for (int r = 0; r < 4; r++) {
                int row = wm * 32 + mt * 16 + g + ((r & 1) << 3);
                int kp = tg + ((r >> 1) << 2);
                ah[mt][r] = smW[buf][0][row * 12 + kp];
                al[mt][r] = smW[buf][1][row * 12 + kp];
            }
        #pragma unroll
        for (int nt = 0; nt < 4; nt++) {
            int nrow = wn * 32 + nt * 8 + g;
            uint32_t bh0 = smX[buf][0][nrow * 12 + tg];
            uint32_t bh1 = smX[buf][0][nrow * 12 + tg + 4];
            uint32_t bl0 = smX[buf][1][nrow * 12 + tg];
            uint32_t bl1 = smX[buf][1][nrow * 12 + tg + 4];
            #pragma unroll
            for (int mt = 0; mt < 2; mt++) {
                mma_bf16(acc[mt][nt], ah[mt], bh0, bh1);
                mma_bf16(acc[mt][nt], ah[mt], bl0, bl1);
                mma_bf16(acc[mt][nt], al[mt], bh0, bh1);
            }
        }
        __syncthreads();
    }

    #pragma unroll
    for (int mt = 0; mt < 2; mt++) {
        int mrow = m0 + wm * 32 + mt * 16 + g;
        float bb0 = Bi[mrow], bb1 = Bi[mrow + 8];
        #pragma unroll
        for (int nt = 0; nt < 4; nt++) {
            int col = n0 + wn * 32 + nt * 8 + tg * 2;
            float2 v0 = {acc[mt][nt][0] + bb0, acc[mt][nt][1] + bb0};
            float2 v1 = {acc[mt][nt][2] + bb1, acc[mt][nt][3] + bb1};
            *(float2*)&Y[(size_t)mrow * P + col] = v0;
            *(float2*)&Y[(size_t)(mrow + 8) * P + col] = v1;
        }
    }
}

// ---------------------------------------------------------------------------
// 2x downsample (64x64 -> 32x32): exact 2x2 mean
// ---------------------------------------------------------------------------
__global__ void down2x_k(const float* __restrict__ src, float* __restrict__ dst,
                         int total) {
    int idx = blockIdx.x * blockDim.x + threadIdx.x;
    if (idx >= total) return;
    int x = idx & 31, y = (idx >> 5) & 31, c = idx >> 10;
    const float* s = src + ((size_t)c << 12) + (y << 7) + (x << 1);
    float2 a0 = *(const float2*)s;
    float2 a1 = *(const float2*)(s + 64);
    dst[idx] = 0.25f * ((a0.x + a0.y) + (a1.x + a1.y));
}

// ---------------------------------------------------------------------------
extern "C" void kernel_launch(void* const* d_in, const int* in_sizes, int n_in,
                              void* d_out, int out_size) {
    const float* high = (const float*)d_in[0];
    const float* low  = (const float*)d_in[1];
    const float* qhw = (const float*)d_in[2];  const float* qhb = (const float*)d_in[3];
    const float* khw = (const float*)d_in[4];  const float* khb = (const float*)d_in[5];
    const float* vhw = (const float*)d_in[6];  const float* vhb = (const float*)d_in[7];
    const float* qlw = (const float*)d_in[8];  const float* qlb = (const float*)d_in[9];
    const float* klw = (const float*)d_in[10]; const float* klb = (const float*)d_in[11];
    const float* vlw = (const float*)d_in[12]; const float* vlb = (const float*)d_in[13];
    const float* ohw = (const float*)d_in[14]; const float* ohb = (const float*)d_in[15];
    const float* olw = (const float*)d_in[16]; const float* olb = (const float*)d_in[17];
    float* out = (float*)d_out;

    float* scr = nullptr;
    cudaGetSymbolAddress((void**)&scr, g_scratch);
    float* qh  = scr + OFF_QH;
    float* ah  = scr + OFF_AH;
    float* kls = scr + OFF_KLS;
    float* vls = scr + OFF_VLS;
    float* ql  = scr + OFF_QL;
    float* kh  = scr + OFF_KH;
    float* vh  = scr + OFF_VH;
    float* hd  = scr + OFF_HD;
    float* al  = scr + OFF_AL;

    // 1) fused low-input convs: k_low, v_low, q_low
    {
        ConvArgs a;
        a.x = low;
        a.w[0] = klw; a.w[1] = vlw; a.w[2] = qlw;
        a.bias[0] = klb; a.bias[1] = vlb; a.bias[2] = qlb;
        a.y[0] = kls; a.y[1] = vls; a.y[2] = ql;
        a.C = 256; a.P = 1024; a.Ob = 256;
        conv_mma_k<<<dim3(16, 6, B), 256>>>(a);
    }
    // 2) downsample high 64->32
    down2x_k<<<(B * 128 * 1024 + 255) / 256, 256>>>(high, hd, B * 128 * 1024);
    // 3) fused hd convs: k_high, v_high
    {
        ConvArgs a;
        a.x = hd;
        a.w[0] = khw; a.w[1] = vhw; a.w[2] = khw;
        a.bias[0] = khb; a.bias[1] = vhb; a.bias[2] = khb;
        a.y[0] = kh; a.y[1] = vh; a.y[2] = kh;
        a.C = 128; a.P = 1024; a.Ob = 256;
        conv_mma_k<<<dim3(16, 4, B), 256>>>(a);
    }
    // 4) q_high conv
    {
        ConvArgs a;
        a.x = high;
        a.w[0] = qhw; a.w[1] = qhw; a.w[2] = qhw;
        a.bias[0] = qhb; a.bias[1] = qhb; a.bias[2] = qhb;
        a.y[0] = qh; a.y[1] = qh; a.y[2] = qh;
        a.C = 128; a.P = 4096; a.Ob = 256;
        conv_mma_k<<<dim3(64, 2, B), 256>>>(a);
    }
    // 5) bf16 KV planes (fused upsample + pack)
    prep_kv_k<<<10240, 256>>>();
    // 6) merged attention (high 512 + low 128 CTAs)
    attn2_k<<<640, 128>>>(qh, ah, ql, al);
    // 7) output projections
    {
        ConvArgs a;
        a.x = ah;
        a.w[0] = ohw; a.w[1] = ohw; a.w[2] = ohw;
        a.bias[0] = ohb; a.bias[1] = ohb; a.bias[2] = ohb;
        a.y[0] = out; a.y[1] = out; a.y[2] = out;
        a.C = 256; a.P = 4096; a.Ob = 128;
        conv_mma_k<<<dim3(64, 1, B), 256>>>(a);
    }
    {
        ConvArgs a;
        a.x = al;
        a.w[0] = olw; a.w[1] = olw; a.w[2] = olw;
        a.bias[0] = olb; a.bias[1] = olb; a.bias[2] = olb;
        a.y[0] = out + (size_t)B * 128 * 4096;
        a.y[1] = a.y[0]; a.y[2] = a.y[0];
        a.C = 256; a.P = 1024; a.Ob = 256;
        conv_mma_k<<<dim3(16, 2, B), 256>>>(a);
    }
}

// round 8
// speedup vs baseline: 6.1174x; 1.1055x over previous
#include <cuda_runtime.h>
#include <cuda_bf16.h>
#include <cstdint>
#include <math.h>

// ---------------------------------------------------------------------------
// CrossScaleAttention  (B=2, hidden=256, heads=8, head_dim=32)
// R8: all pre-attention convs merged into ONE launch (576 CTAs) and both
//     output projections into ONE launch (192 CTAs) via descriptor decode;
//     attention / prep / down2x unchanged from R7 (proven).
// ---------------------------------------------------------------------------

#define B 2
#define HID 256
#define NHEAD 8
#define HD 32
#define SCALE 0.17677669529663687f
#define QSCALE (SCALE * 1.4426950408889634f)   // fold log2(e): p = ex2(S)
#define KT 64

// ---------------- fp32 scratch ----------------
#define OFF_QH   0UL                 // [2,256,4096]
#define OFF_AH   2097152UL           // [2,256,4096]
#define OFF_KLS  4194304UL           // [2,256,1024]
#define OFF_VLS  4718592UL
#define OFF_QL   5242880UL
#define OFF_KH   5767168UL
#define OFF_VH   6291456UL
#define OFF_HD   6815744UL           // [2,128,1024]
#define OFF_AL   7077888UL           // [2,256,1024]
#define SCRATCH_FLOATS 7602176UL
__device__ float g_scratch[SCRATCH_FLOATS];

// ---------------- bf16 KV planes (u32 = bf16x2) ----------------
#define OKH_H 0UL
#define OVH_H 1048576UL
#define OKH_L 2097152UL
#define OVH_L 2359296UL
#define KVU_TOTAL 2621440UL
__device__ uint32_t g_kvu[KVU_TOTAL];

// ---------------- helpers ----------------
__device__ __forceinline__ uint32_t pack2rn(float f0, float f1) {
    uint32_t r;
    asm("cvt.rn.bf16x2.f32 %0, %1, %2;" : "=r"(r) : "f"(f1), "f"(f0));
    return r;
}
__device__ __forceinline__ void split2(float f0, float f1, uint32_t& hi, uint32_t& lo) {
    asm("cvt.rn.bf16x2.f32 %0, %1, %2;" : "=r"(hi) : "f"(f1), "f"(f0));
    float h0 = __uint_as_float(hi << 16);
    float h1 = __uint_as_float(hi & 0xFFFF0000u);
    float r0 = f0 - h0, r1 = f1 - h1;
    asm("cvt.rn.bf16x2.f32 %0, %1, %2;" : "=r"(lo) : "f"(r1), "f"(r0));
}

__device__ __forceinline__ void mma_bf16(float* c, const uint32_t* a,
                                         uint32_t b0, uint32_t b1) {
    asm volatile(
        "mma.sync.aligned.m16n8k16.row.col.f32.bf16.bf16.f32 "
        "{%0,%1,%2,%3}, {%4,%5,%6,%7}, {%8,%9}, {%0,%1,%2,%3};"
        : "+f"(c[0]), "+f"(c[1]), "+f"(c[2]), "+f"(c[3])
        : "r"(a[0]), "r"(a[1]), "r"(a[2]), "r"(a[3]), "r"(b0), "r"(b1));
}

__device__ __forceinline__ float ex2f(float x) {
    float y;
    asm("ex2.approx.f32 %0, %1;" : "=f"(y) : "f"(x));
    return y;
}

__device__ __forceinline__ uint32_t smem_u32p(const void* p) {
    uint32_t a;
    asm("{ .reg .u64 t; cvta.to.shared.u64 t, %1; cvt.u32.u64 %0, t; }" : "=r"(a) : "l"(p));
    return a;
}
__device__ __forceinline__ void cp16(uint32_t saddr, const void* g) {
    asm volatile("cp.async.ca.shared.global [%0], [%1], 16;" :: "r"(saddr), "l"(g) : "memory");
}
#define CP_COMMIT() asm volatile("cp.async.commit_group;" ::: "memory")
#define CP_WAIT0()  asm volatile("cp.async.wait_group 0;" ::: "memory")

// bilinear 2x upsample sample (32x32 -> 64x64, align_corners=False)
__device__ __forceinline__ float up_sample(const float* __restrict__ s, int y, int x) {
    int y0 = max((y - 1) >> 1, 0), y1 = min((y + 1) >> 1, 31);
    int x0 = max((x - 1) >> 1, 0), x1 = min((x + 1) >> 1, 31);
    float wy = (y & 1) ? 0.25f : 0.75f;
    float wx = (x & 1) ? 0.25f : 0.75f;
    float v00 = s[(y0 << 5) + x0], v01 = s[(y0 << 5) + x1];
    float v10 = s[(y1 << 5) + x0], v11 = s[(y1 << 5) + x1];
    float top = v00 + wx * (v01 - v00);
    float bot = v10 + wx * (v11 - v10);
    return top + wy * (bot - top);
}

// ---------------------------------------------------------------------------
// prep_kv: build bf16 KV planes (R7, proven).
// ---------------------------------------------------------------------------
__global__ __launch_bounds__(256) void prep_kv_k() {
    const float* kls = g_scratch + OFF_KLS;
    const float* vls = g_scratch + OFF_VLS;
    const float* kh  = g_scratch + OFF_KH;
    const float* vh  = g_scratch + OFF_VH;
    int gid = blockIdx.x * 256 + threadIdx.x;

    if (gid < 1048576) {                 // high K: [bh][key 4096][dp 16]
        int dp = gid & 15, key = (gid >> 4) & 4095, bh = gid >> 16;
        int y = key >> 6, x = key & 63;
        const float* s = kls + (((size_t)(bh >> 3) * 256) + (bh & 7) * 32 + 2 * dp) * 1024;
        g_kvu[OKH_H + gid] = pack2rn(up_sample(s, y, x), up_sample(s + 1024, y, x));
    } else if (gid < 2097152) {          // high V: [bh][d 32][kp 2048]
        int g2 = gid - 1048576;
        int kp = g2 & 2047, d = (g2 >> 11) & 31, bh = g2 >> 16;
        int key = kp << 1;
        int y = key >> 6, x = key & 63;
        const float* s = vls + (((size_t)(bh >> 3) * 256) + (bh & 7) * 32 + d) * 1024;
        g_kvu[OVH_H + g2] = pack2rn(up_sample(s, y, x), up_sample(s, y, x + 1));
    } else if (gid < 2359296) {          // low K: [bh][key 1024][dp 16]
        int g3 = gid - 2097152;
        int dp = g3 & 15, key = (g3 >> 4) & 1023, bh = g3 >> 14;
        const float* s = kh + (((size_t)(bh >> 3) * 256) + (bh & 7) * 32 + 2 * dp) * 1024 + key;
        g_kvu[OKH_L + g3] = pack2rn(s[0], s[1024]);
    } else if (gid < 2621440) {          // low V: [bh][d 32][kp 512]
        int g4 = gid - 2359296;
        int kp = g4 & 511, d = (g4 >> 9) & 31, bh = g4 >> 14;
        const float* s = vh + (((size_t)(bh >> 3) * 256) + (bh & 7) * 32 + d) * 1024 + 2 * kp;
        g_kvu[OVH_L + g4] = pack2rn(s[0], s[1]);
    }
}

// ---------------------------------------------------------------------------
// Merged flash attention (R7, proven). high: CTAs [0,512), low: [512,640).
// ---------------------------------------------------------------------------
__global__ __launch_bounds__(128) void attn2_k(const float* __restrict__ qH,
                                               float* __restrict__ oH,
                                               const float* __restrict__ qL,
                                               float* __restrict__ oL) {
    __shared__ __align__(16) uint32_t Ksm[2][64 * 20];
    __shared__ __align__(16) uint32_t Vsm[2][32 * 36];

    int tid = threadIdx.x;
    int w = tid >> 5, lane = tid & 31;
    int g = lane >> 2, tg = lane & 3;

    int cta = blockIdx.x;
    const float* q;
    float* out;
    const uint32_t *Kg, *Vg;
    int N, q0, bh;
    if (cta < 512) {
        N = 4096; bh = cta >> 5; q0 = (cta & 31) << 7;
        q = qH; out = oH;
        Kg = g_kvu + OKH_H + ((size_t)bh << 16);
        Vg = g_kvu + OVH_H + ((size_t)bh << 16);
    } else {
        int idx = cta - 512;
        N = 1024; bh = idx >> 3; q0 = (idx & 7) << 7;
        q = qL; out = oL;
        Kg = g_kvu + OKH_L + ((size_t)bh << 14);
        Vg = g_kvu + OVH_L + ((size_t)bh << 14);
    }
    size_t base = (size_t)32 * bh * N;
    int halfN = N >> 1;

    uint32_t ks0 = smem_u32p(&Ksm[0][0]);
    uint32_t vs0 = smem_u32p(&Vsm[0][0]);

    uint32_t qh[2][2][4], ql[2][2][4];
    #pragma unroll
    for (int mt = 0; mt < 2; mt++)
        #pragma unroll
        for (int kt = 0; kt < 2; kt++)
            #pragma unroll
            for (int r = 0; r < 4; r++) {
                int row = q0 + w * 32 + mt * 16 + g + (r & 1) * 8;
                int d0 = kt * 16 + tg * 2 + (r >> 1) * 8;
                float f0 = q[base + (size_t)d0 * N + row] * QSCALE;
                float f1 = q[base + (size_t)(d0 + 1) * N + row] * QSCALE;
                split2(f0, f1, qh[mt][kt][r], ql[mt][kt][r]);
            }

    auto load_tile = [&](int buf, int kv0) {
        int kp0 = kv0 >> 1;
        #pragma unroll
        for (int i = 0; i < 2; i++) {
            int id = tid + (i << 7);
            int key = id >> 2, c4 = (id & 3) << 2;
            cp16(ks0 + (uint32_t)(buf * 1280 + key * 20 + c4) * 4,
                 Kg + (size_t)(kv0 + key) * 16 + c4);
        }
        #pragma unroll
        for (int i = 0; i < 2; i++) {
            int id = tid + (i << 7);
            int d = id >> 3, c = (id & 7) << 2;
            cp16(vs0 + (uint32_t)(buf * 1152 + d * 36 + c) * 4,
                 Vg + (size_t)d * halfN + kp0 + c);
        }
        CP_COMMIT();
    };

    float O[2][4][4] = {};
    float lacc[2][2] = {};

    load_tile(0, 0);
    CP_WAIT0();
    __syncthreads();

    int T = N / KT;
    for (int it = 0; it < T; it++) {
        int buf = it & 1;
        if (it + 1 < T) load_tile(buf ^ 1, (it + 1) * KT);

        const uint32_t* Kh = Ksm[buf];
        const uint32_t* Vh = Vsm[buf];

        #pragma unroll
        for (int mt = 0; mt < 2; mt++) {
            uint32_t pah[4];
            #pragma unroll
            for (int j = 0; j < 8; j++) {
                float S[4] = {0.f, 0.f, 0.f, 0.f};
                #pragma unroll
                for (int kt = 0; kt < 2; kt++) {
                    int bi = (j * 8 + g) * 20 + kt * 8 + tg;
                    uint32_t b0 = Kh[bi], b1 = Kh[bi + 4];
                    mma_bf16(S, qh[mt][kt], b0, b1);
                    mma_bf16(S, ql[mt][kt], b0, b1);
                }
                float p0 = ex2f(S[0]), p1 = ex2f(S[1]);
                float p2 = ex2f(S[2]), p3 = ex2f(S[3]);
                lacc[mt][0] += p0 + p1;
                lacc[mt][1] += p2 + p3;
                int odd = j & 1;
                pah[odd * 2]     = pack2rn(p0, p1);
                pah[odd * 2 + 1] = pack2rn(p2, p3);
                if (odd) {
                    int kt2 = j >> 1;
                    #pragma unroll
                    for (int jd = 0; jd < 4; jd++) {
                        int bi = (jd * 8 + g) * 36 + kt2 * 8 + tg;
                        mma_bf16(O[mt][jd], pah, Vh[bi], Vh[bi + 4]);
                    }
                }
            }
        }

        if (it + 1 < T) CP_WAIT0();
        __syncthreads();
    }

    #pragma unroll
    for (int mt = 0; mt < 2; mt++)
        #pragma unroll
        for (int r = 0; r < 2; r++) {
            float l = lacc[mt][r];
            l += __shfl_xor_sync(0xffffffffu, l, 1);
            l += __shfl_xor_sync(0xffffffffu, l, 2);
            lacc[mt][r] = 1.0f / l;
        }

    #pragma unroll
    for (int mt = 0; mt < 2; mt++) {
        int row0 = q0 + w * 32 + mt * 16 + g;
        #pragma unroll
        for (int jd = 0; jd < 4; jd++) {
            int d0 = jd * 8 + tg * 2;
            out[base + (size_t)d0 * N + row0]           = O[mt][jd][0] * lacc[mt][0];
            out[base + (size_t)(d0 + 1) * N + row0]     = O[mt][jd][1] * lacc[mt][0];
            out[base + (size_t)d0 * N + row0 + 8]       = O[mt][jd][2] * lacc[mt][1];
            out[base + (size_t)(d0 + 1) * N + row0 + 8] = O[mt][jd][3] * lacc[mt][1];
        }
    }
}

// ---------------------------------------------------------------------------
// Batched conv1x1: up to 6 GEMM outputs per launch, per-CTA descriptor decode.
// Inner loop identical to R7 conv (bf16 3-term split, BM=128, BN=64, BK=16).
// grid: (total_ctas, 1, B)
// ---------------------------------------------------------------------------
struct ConvDesc {
    const float* x;
    const float* w;
    const float* bias;
    float* y;
    int C, P, nblocks, cta0, xbs, ybs;   // nblocks = P/64; cta count = mblocks*nblocks
};
struct ConvBatch {
    ConvDesc d[6];
    int nd;
};

__global__ __launch_bounds__(256) void conv_mma_k(ConvBatch args) {
    __shared__ uint32_t smW[2][2][1536];   // [buf][plane][128m x 12]
    __shared__ uint32_t smX[2][2][768];    // [buf][plane][64n x 12]

    // ---- decode ----
    int bx = blockIdx.x;
    int u = 0;
    #pragma unroll
    for (int i = 1; i < 6; i++)
        if (i < args.nd && bx >= args.d[i].cta0) u = i;
    const ConvDesc& D = args.d[u];
    int rem = bx - D.cta0;
    int m0 = (rem / D.nblocks) << 7;
    int n0 = (rem % D.nblocks) << 6;
    int b = blockIdx.z;
    int C = D.C, P = D.P;
    const float* X = D.x + (size_t)b * D.xbs;
    const float* W = D.w;
    const float* Bi = D.bias;
    float* Y = D.y + (size_t)b * D.ybs;
    int nch = C >> 4;

    int tid = threadIdx.x;
    int w = tid >> 5, lane = tid & 31, g = lane >> 2, tg = lane & 3;
    int wm = w >> 1, wn = w & 1;

    auto load = [&](int ch, int buf) {
        int c0 = ch << 4;
        {   // W tile: 128 m x 16 c
            int m = tid >> 1, half = tid & 1;
            const float4* src = reinterpret_cast<const float4*>(
                W + (size_t)(m0 + m) * C + c0 + half * 8);
            float4 f0 = src[0], f1 = src[1];
            uint32_t* dh = &smW[buf][0][m * 12 + half * 4];
            uint32_t* dl = &smW[buf][1][m * 12 + half * 4];
            uint32_t h, l;
            split2(f0.x, f0.y, h, l); dh[0] = h; dl[0] = l;
            split2(f0.z, f0.w, h, l); dh[1] = h; dl[1] = l;
            split2(f1.x, f1.y, h, l); dh[2] = h; dl[2] = l;
            split2(f1.z, f1.w, h, l); dh[3] = h; dl[3] = l;
        }
        #pragma unroll
        for (int i = 0; i < 2; i++) {
            int idx = tid + (i << 8);
            int kp = idx >> 6, n = idx & 63;
            float f0 = X[(size_t)(c0 + 2 * kp) * P + n0 + n];
            float f1 = X[(size_t)(c0 + 2 * kp + 1) * P + n0 + n];
            uint32_t h, l;
            split2(f0, f1, h, l);
            smX[buf][0][n * 12 + kp] = h;
            smX[buf][1][n * 12 + kp] = l;
        }
    };

    float acc[2][4][4] = {};

    load(0, 0);
    __syncthreads();

    for (int ch = 0; ch < nch; ch++) {
        int buf = ch & 1;
        if (ch + 1 < nch) load(ch + 1, buf ^ 1);

        uint32_t ah[2][4], al[2][4];
        #pragma unroll
        for (int mt = 0; mt < 2; mt++)
            #pragma unroll
            for (int r = 0; r < 4; r++) {
                int row = wm * 32 + mt * 16 + g + ((r & 1) << 3);
                int kp = tg + ((r >> 1) << 2);
                ah[mt][r] = smW[buf][0][row * 12 + kp];
                al[mt][r] = smW[buf][1][row * 12 + kp];
            }
        #pragma unroll
        for (int nt = 0; nt < 4; nt++) {
            int nrow = wn * 32 + nt * 8 + g;
            uint32_t bh0 = smX[buf][0][nrow * 12 + tg];
            uint32_t bh1 = smX[buf][0][nrow * 12 + tg + 4];
            uint32_t bl0 = smX[buf][1][nrow * 12 + tg];
            uint32_t bl1 = smX[buf][1][nrow * 12 + tg + 4];
            #pragma unroll
            for (int mt = 0; mt < 2; mt++) {
                mma_bf16(acc[mt][nt], ah[mt], bh0, bh1);
                mma_bf16(acc[mt][nt], ah[mt], bl0, bl1);
                mma_bf16(acc[mt][nt], al[mt], bh0, bh1);
            }
        }
        __syncthreads();
    }

    #pragma unroll
    for (int mt = 0; mt < 2; mt++) {
        int mrow = m0 + wm * 32 + mt * 16 + g;
        float bb0 = Bi[mrow], bb1 = Bi[mrow + 8];
        #pragma unroll
        for (int nt = 0; nt < 4; nt++) {
            int col = n0 + wn * 32 + nt * 8 + tg * 2;
            float2 v0 = {acc[mt][nt][0] + bb0, acc[mt][nt][1] + bb0};
            float2 v1 = {acc[mt][nt][2] + bb1, acc[mt][nt][3] + bb1};
            *(float2*)&Y[(size_t)mrow * P + col] = v0;
            *(float2*)&Y[(size_t)(mrow + 8) * P + col] = v1;
        }
    }
}

// ---------------------------------------------------------------------------
// 2x downsample (64x64 -> 32x32): exact 2x2 mean
// ---------------------------------------------------------------------------
__global__ void down2x_k(const float* __restrict__ src, float* __restrict__ dst,
                         int total) {
    int idx = blockIdx.x * blockDim.x + threadIdx.x;
    if (idx >= total) return;
    int x = idx & 31, y = (idx >> 5) & 31, c = idx >> 10;
    const float* s = src + ((size_t)c << 12) + (y << 7) + (x << 1);
    float2 a0 = *(const float2*)s;
    float2 a1 = *(const float2*)(s + 64);
    dst[idx] = 0.25f * ((a0.x + a0.y) + (a1.x + a1.y));
}

// ---------------------------------------------------------------------------
extern "C" void kernel_launch(void* const* d_in, const int* in_sizes, int n_in,
                              void* d_out, int out_size) {
    const float* high = (const float*)d_in[0];
    const float* low  = (const float*)d_in[1];
    const float* qhw = (const float*)d_in[2];  const float* qhb = (const float*)d_in[3];
    const float* khw = (const float*)d_in[4];  const float* khb = (const float*)d_in[5];
    const float* vhw = (const float*)d_in[6];  const float* vhb = (const float*)d_in[7];
    const float* qlw = (const float*)d_in[8];  const float* qlb = (const float*)d_in[9];
    const float* klw = (const float*)d_in[10]; const float* klb = (const float*)d_in[11];
    const float* vlw = (const float*)d_in[12]; const float* vlb = (const float*)d_in[13];
    const float* ohw = (const float*)d_in[14]; const float* ohb = (const float*)d_in[15];
    const float* olw = (const float*)d_in[16]; const float* olb = (const float*)d_in[17];
    float* out = (float*)d_out;

    float* scr = nullptr;
    cudaGetSymbolAddress((void**)&scr, g_scratch);
    float* qh  = scr + OFF_QH;
    float* ah  = scr + OFF_AH;
    float* kls = scr + OFF_KLS;
    float* vls = scr + OFF_VLS;
    float* ql  = scr + OFF_QL;
    float* kh  = scr + OFF_KH;
    float* vh  = scr + OFF_VH;
    float* hd  = scr + OFF_HD;
    float* al  = scr + OFF_AL;

    // 1) downsample high 64->32
    down2x_k<<<(B * 128 * 1024 + 255) / 256, 256>>>(high, hd, B * 128 * 1024);

    // 2) ALL pre-attention convs in one launch (576 CTAs x B)
    {
        ConvBatch cb;
        // k_low, v_low, q_low: x=low, C=256, P=1024, O=256 -> 32 CTAs each
        cb.d[0] = {low, klw, klb, kls, 256, 1024, 16, 0,   256 * 1024, 256 * 1024};
        cb.d[1] = {low, vlw, vlb, vls, 256, 1024, 16, 32,  256 * 1024, 256 * 1024};
        cb.d[2] = {low, qlw, qlb, ql,  256, 1024, 16, 64,  256 * 1024, 256 * 1024};
        // k_high, v_high: x=hd, C=128, P=1024, O=256 -> 32 CTAs each
        cb.d[3] = {hd, khw, khb, kh,   128, 1024, 16, 96,  128 * 1024, 256 * 1024};
        cb.d[4] = {hd, vhw, vhb, vh,   128, 1024, 16, 128, 128 * 1024, 256 * 1024};
        // q_high: x=high, C=128, P=4096, O=256 -> 128 CTAs
        cb.d[5] = {high, qhw, qhb, qh, 128, 4096, 64, 160, 128 * 4096, 256 * 4096};
        cb.nd = 6;
        conv_mma_k<<<dim3(288, 1, B), 256>>>(cb);
    }

    // 3) bf16 KV planes (fused upsample + pack)
    prep_kv_k<<<10240, 256>>>();

    // 4) merged attention (high 512 + low 128 CTAs)
    attn2_k<<<640, 128>>>(qh, ah, ql, al);

    // 5) both output projections in one launch (96 CTAs x B)
    {
        ConvBatch cb;
        // out_high: x=ah, C=256, P=4096, O=128 -> 64 CTAs
        cb.d[0] = {ah, ohw, ohb, out, 256, 4096, 64, 0, 256 * 4096, 128 * 4096};
        // out_low: x=al, C=256, P=1024, O=256 -> 32 CTAs
        cb.d[1] = {al, olw, olb, out + (size_t)B * 128 * 4096,
                   256, 1024, 16, 64, 256 * 1024, 256 * 1024};
        cb.nd = 2;
        conv_mma_k<<<dim3(96, 1, B), 256>>>(cb);
    }
}

// round 9
// speedup vs baseline: 7.1667x; 1.1715x over previous
#include <cuda_runtime.h>
#include <cuda_bf16.h>
#include <cstdint>
#include <math.h>

// ---------------------------------------------------------------------------
// CrossScaleAttention  (B=2, hidden=256, heads=8, head_dim=32)
// R9: attention fully bf16 on tensor pipe (Q/K/V/P bf16, fp32 accum/exp):
//     64 MMAs per tile (was 96), lower regs -> higher occupancy.
//     Convs keep the 3-term hi/lo split (full precision).
// ---------------------------------------------------------------------------

#define B 2
#define HID 256
#define NHEAD 8
#define HD 32
#define SCALE 0.17677669529663687f
#define QSCALE (SCALE * 1.4426950408889634f)   // fold log2(e): p = ex2(S)
#define KT 64

// ---------------- fp32 scratch ----------------
#define OFF_QH   0UL                 // [2,256,4096]
#define OFF_AH   2097152UL           // [2,256,4096]
#define OFF_KLS  4194304UL           // [2,256,1024]
#define OFF_VLS  4718592UL
#define OFF_QL   5242880UL
#define OFF_KH   5767168UL
#define OFF_VH   6291456UL
#define OFF_HD   6815744UL           // [2,128,1024]
#define OFF_AL   7077888UL           // [2,256,1024]
#define SCRATCH_FLOATS 7602176UL
__device__ float g_scratch[SCRATCH_FLOATS];

// ---------------- bf16 KV planes (u32 = bf16x2) ----------------
#define OKH_H 0UL
#define OVH_H 1048576UL
#define OKH_L 2097152UL
#define OVH_L 2359296UL
#define KVU_TOTAL 2621440UL
__device__ uint32_t g_kvu[KVU_TOTAL];

// ---------------- helpers ----------------
__device__ __forceinline__ uint32_t pack2rn(float f0, float f1) {
    uint32_t r;
    asm("cvt.rn.bf16x2.f32 %0, %1, %2;" : "=r"(r) : "f"(f1), "f"(f0));
    return r;
}
__device__ __forceinline__ void split2(float f0, float f1, uint32_t& hi, uint32_t& lo) {
    asm("cvt.rn.bf16x2.f32 %0, %1, %2;" : "=r"(hi) : "f"(f1), "f"(f0));
    float h0 = __uint_as_float(hi << 16);
    float h1 = __uint_as_float(hi & 0xFFFF0000u);
    float r0 = f0 - h0, r1 = f1 - h1;
    asm("cvt.rn.bf16x2.f32 %0, %1, %2;" : "=r"(lo) : "f"(r1), "f"(r0));
}

__device__ __forceinline__ void mma_bf16(float* c, const uint32_t* a,
                                         uint32_t b0, uint32_t b1) {
    asm volatile(
        "mma.sync.aligned.m16n8k16.row.col.f32.bf16.bf16.f32 "
        "{%0,%1,%2,%3}, {%4,%5,%6,%7}, {%8,%9}, {%0,%1,%2,%3};"
        : "+f"(c[0]), "+f"(c[1]), "+f"(c[2]), "+f"(c[3])
        : "r"(a[0]), "r"(a[1]), "r"(a[2]), "r"(a[3]), "r"(b0), "r"(b1));
}

__device__ __forceinline__ float ex2f(float x) {
    float y;
    asm("ex2.approx.f32 %0, %1;" : "=f"(y) : "f"(x));
    return y;
}

__device__ __forceinline__ uint32_t smem_u32p(const void* p) {
    uint32_t a;
    asm("{ .reg .u64 t; cvta.to.shared.u64 t, %1; cvt.u32.u64 %0, t; }" : "=r"(a) : "l"(p));
    return a;
}
__device__ __forceinline__ void cp16(uint32_t saddr, const void* g) {
    asm volatile("cp.async.ca.shared.global [%0], [%1], 16;" :: "r"(saddr), "l"(g) : "memory");
}
#define CP_COMMIT() asm volatile("cp.async.commit_group;" ::: "memory")
#define CP_WAIT0()  asm volatile("cp.async.wait_group 0;" ::: "memory")

// bilinear 2x upsample sample (32x32 -> 64x64, align_corners=False)
__device__ __forceinline__ float up_sample(const float* __restrict__ s, int y, int x) {
    int y0 = max((y - 1) >> 1, 0), y1 = min((y + 1) >> 1, 31);
    int x0 = max((x - 1) >> 1, 0), x1 = min((x + 1) >> 1, 31);
    float wy = (y & 1) ? 0.25f : 0.75f;
    float wx = (x & 1) ? 0.25f : 0.75f;
    float v00 = s[(y0 << 5) + x0], v01 = s[(y0 << 5) + x1];
    float v10 = s[(y1 << 5) + x0], v11 = s[(y1 << 5) + x1];
    float top = v00 + wx * (v01 - v00);
    float bot = v10 + wx * (v11 - v10);
    return top + wy * (bot - top);
}

// ---------------------------------------------------------------------------
// prep_kv: build bf16 KV planes (R7, proven).
// ---------------------------------------------------------------------------
__global__ __launch_bounds__(256) void prep_kv_k() {
    const float* kls = g_scratch + OFF_KLS;
    const float* vls = g_scratch + OFF_VLS;
    const float* kh  = g_scratch + OFF_KH;
    const float* vh  = g_scratch + OFF_VH;
    int gid = blockIdx.x * 256 + threadIdx.x;

    if (gid < 1048576) {                 // high K: [bh][key 4096][dp 16]
        int dp = gid & 15, key = (gid >> 4) & 4095, bh = gid >> 16;
        int y = key >> 6, x = key & 63;
        const float* s = kls + (((size_t)(bh >> 3) * 256) + (bh & 7) * 32 + 2 * dp) * 1024;
        g_kvu[OKH_H + gid] = pack2rn(up_sample(s, y, x), up_sample(s + 1024, y, x));
    } else if (gid < 2097152) {          // high V: [bh][d 32][kp 2048]
        int g2 = gid - 1048576;
        int kp = g2 & 2047, d = (g2 >> 11) & 31, bh = g2 >> 16;
        int key = kp << 1;
        int y = key >> 6, x = key & 63;
        const float* s = vls + (((size_t)(bh >> 3) * 256) + (bh & 7) * 32 + d) * 1024;
        g_kvu[OVH_H + g2] = pack2rn(up_sample(s, y, x), up_sample(s, y, x + 1));
    } else if (gid < 2359296) {          // low K: [bh][key 1024][dp 16]
        int g3 = gid - 2097152;
        int dp = g3 & 15, key = (g3 >> 4) & 1023, bh = g3 >> 14;
        const float* s = kh + (((size_t)(bh >> 3) * 256) + (bh & 7) * 32 + 2 * dp) * 1024 + key;
        g_kvu[OKH_L + g3] = pack2rn(s[0], s[1024]);
    } else if (gid < 2621440) {          // low V: [bh][d 32][kp 512]
        int g4 = gid - 2359296;
        int kp = g4 & 511, d = (g4 >> 9) & 31, bh = g4 >> 14;
        const float* s = vh + (((size_t)(bh >> 3) * 256) + (bh & 7) * 32 + d) * 1024 + 2 * kp;
        g_kvu[OVH_L + g4] = pack2rn(s[0], s[1]);
    }
}

// ---------------------------------------------------------------------------
// Merged flash attention. Q/K/V/P bf16, fp32 exp/l/O accumulation.
// high: CTAs [0,512), low: [512,640). block 128 (4 warps x 32 rows).
// ---------------------------------------------------------------------------
__global__ __launch_bounds__(128) void attn2_k(const float* __restrict__ qH,
                                               float* __restrict__ oH,
                                               const float* __restrict__ qL,
                                               float* __restrict__ oL) {
    __shared__ __align__(16) uint32_t Ksm[2][64 * 20];
    __shared__ __align__(16) uint32_t Vsm[2][32 * 36];

    int tid = threadIdx.x;
    int w = tid >> 5, lane = tid & 31;
    int g = lane >> 2, tg = lane & 3;

    int cta = blockIdx.x;
    const float* q;
    float* out;
    const uint32_t *Kg, *Vg;
    int N, q0, bh;
    if (cta < 512) {
        N = 4096; bh = cta >> 5; q0 = (cta & 31) << 7;
        q = qH; out = oH;
        Kg = g_kvu + OKH_H + ((size_t)bh << 16);
        Vg = g_kvu + OVH_H + ((size_t)bh << 16);
    } else {
        int idx = cta - 512;
        N = 1024; bh = idx >> 3; q0 = (idx & 7) << 7;
        q = qL; out = oL;
        Kg = g_kvu + OKH_L + ((size_t)bh << 14);
        Vg = g_kvu + OVH_L + ((size_t)bh << 14);
    }
    size_t base = (size_t)32 * bh * N;
    int halfN = N >> 1;

    uint32_t ks0 = smem_u32p(&Ksm[0][0]);
    uint32_t vs0 = smem_u32p(&Vsm[0][0]);

    // ---- Q fragments (plain bf16, QSCALE folded) ----
    uint32_t qf[2][2][4];
    #pragma unroll
    for (int mt = 0; mt < 2; mt++)
        #pragma unroll
        for (int kt = 0; kt < 2; kt++)
            #pragma unroll
            for (int r = 0; r < 4; r++) {
                int row = q0 + w * 32 + mt * 16 + g + (r & 1) * 8;
                int d0 = kt * 16 + tg * 2 + (r >> 1) * 8;
                float f0 = q[base + (size_t)d0 * N + row] * QSCALE;
                float f1 = q[base + (size_t)(d0 + 1) * N + row] * QSCALE;
                qf[mt][kt][r] = pack2rn(f0, f1);
            }

    auto load_tile = [&](int buf, int kv0) {
        int kp0 = kv0 >> 1;
        #pragma unroll
        for (int i = 0; i < 2; i++) {
            int id = tid + (i << 7);
            int key = id >> 2, c4 = (id & 3) << 2;
            cp16(ks0 + (uint32_t)(buf * 1280 + key * 20 + c4) * 4,
                 Kg + (size_t)(kv0 + key) * 16 + c4);
        }
        #pragma unroll
        for (int i = 0; i < 2; i++) {
            int id = tid + (i << 7);
            int d = id >> 3, c = (id & 7) << 2;
            cp16(vs0 + (uint32_t)(buf * 1152 + d * 36 + c) * 4,
                 Vg + (size_t)d * halfN + kp0 + c);
        }
        CP_COMMIT();
    };

    float O[2][4][4] = {};
    float lacc[2][2] = {};

    load_tile(0, 0);
    CP_WAIT0();
    __syncthreads();

    int T = N / KT;
    for (int it = 0; it < T; it++) {
        int buf = it & 1;
        if (it + 1 < T) load_tile(buf ^ 1, (it + 1) * KT);

        const uint32_t* Kh = Ksm[buf];
        const uint32_t* Vh = Vsm[buf];

        #pragma unroll
        for (int mt = 0; mt < 2; mt++) {
            uint32_t pah[4];
            #pragma unroll
            for (int j = 0; j < 8; j++) {
                float S[4] = {0.f, 0.f, 0.f, 0.f};
                #pragma unroll
                for (int kt = 0; kt < 2; kt++) {
                    int bi = (j * 8 + g) * 20 + kt * 8 + tg;
                    mma_bf16(S, qf[mt][kt], Kh[bi], Kh[bi + 4]);
                }
                float p0 = ex2f(S[0]), p1 = ex2f(S[1]);
                float p2 = ex2f(S[2]), p3 = ex2f(S[3]);
                lacc[mt][0] += p0 + p1;
                lacc[mt][1] += p2 + p3;
                int odd = j & 1;
                pah[odd * 2]     = pack2rn(p0, p1);
                pah[odd * 2 + 1] = pack2rn(p2, p3);
                if (odd) {
                    int kt2 = j >> 1;
                    #pragma unroll
                    for (int jd = 0; jd < 4; jd++) {
                        int bi = (jd * 8 + g) * 36 + kt2 * 8 + tg;
                        mma_bf16(O[mt][jd], pah, Vh[bi], Vh[bi + 4]);
                    }
                }
            }
        }

        if (it + 1 < T) CP_WAIT0();
        __syncthreads();
    }

    #pragma unroll
    for (int mt = 0; mt < 2; mt++)
        #pragma unroll
        for (int r = 0; r < 2; r++) {
            float l = lacc[mt][r];
            l += __shfl_xor_sync(0xffffffffu, l, 1);
            l += __shfl_xor_sync(0xffffffffu, l, 2);
            lacc[mt][r] = 1.0f / l;
        }

    #pragma unroll
    for (int mt = 0; mt < 2; mt++) {
        int row0 = q0 + w * 32 + mt * 16 + g;
        #pragma unroll
        for (int jd = 0; jd < 4; jd++) {
            int d0 = jd * 8 + tg * 2;
            out[base + (size_t)d0 * N + row0]           = O[mt][jd][0] * lacc[mt][0];
            out[base + (size_t)(d0 + 1) * N + row0]     = O[mt][jd][1] * lacc[mt][0];
            out[base + (size_t)d0 * N + row0 + 8]       = O[mt][jd][2] * lacc[mt][1];
            out[base + (size_t)(d0 + 1) * N + row0 + 8] = O[mt][jd][3] * lacc[mt][1];
        }
    }
}

// ---------------------------------------------------------------------------
// Batched conv1x1 (R8, proven): up to 6 GEMM outputs per launch.
// bf16 3-term split, BM=128, BN=64, BK=16, double-buffered.
// ---------------------------------------------------------------------------
struct ConvDesc {
    const float* x;
    const float* w;
    const float* bias;
    float* y;
    int C, P, nblocks, cta0, xbs, ybs;
};
struct ConvBatch {
    ConvDesc d[6];
    int nd;
};

__global__ __launch_bounds__(256) void conv_mma_k(ConvBatch args) {
    __shared__ uint32_t smW[2][2][1536];
    __shared__ uint32_t smX[2][2][768];

    int bx = blockIdx.x;
    int u = 0;
    #pragma unroll
    for (int i = 1; i < 6; i++)
        if (i < args.nd && bx >= args.d[i].cta0) u = i;
    const ConvDesc& D = args.d[u];
    int rem = bx - D.cta0;
    int m0 = (rem / D.nblocks) << 7;
    int n0 = (rem % D.nblocks) << 6;
    int b = blockIdx.z;
    int C = D.C, P = D.P;
    const float* X = D.x + (size_t)b * D.xbs;
    const float* W = D.w;
    const float* Bi = D.bias;
    float* Y = D.y + (size_t)b * D.ybs;
    int nch = C >> 4;

    int tid = threadIdx.x;
    int w = tid >> 5, lane = tid & 31, g = lane >> 2, tg = lane & 3;
    int wm = w >> 1, wn = w & 1;

    auto load = [&](int ch, int buf) {
        int c0 = ch << 4;
        {
            int m = tid >> 1, half = tid & 1;
            const float4* src = reinterpret_cast<const float4*>(
                W + (size_t)(m0 + m) * C + c0 + half * 8);
            float4 f0 = src[0], f1 = src[1];
            uint32_t* dh = &smW[buf][0][m * 12 + half * 4];
            uint32_t* dl = &smW[buf][1][m * 12 + half * 4];
            uint32_t h, l;
            split2(f0.x, f0.y, h, l); dh[0] = h; dl[0] = l;
            split2(f0.z, f0.w, h, l); dh[1] = h; dl[1] = l;
            split2(f1.x, f1.y, h, l); dh[2] = h; dl[2] = l;
            split2(f1.z, f1.w, h, l); dh[3] = h; dl[3] = l;
        }
        #pragma unroll
        for (int i = 0; i < 2; i++) {
            int idx = tid + (i << 8);
            int kp = idx >> 6, n = idx & 63;
            float f0 = X[(size_t)(c0 + 2 * kp) * P + n0 + n];
            float f1 = X[(size_t)(c0 + 2 * kp + 1) * P + n0 + n];
            uint32_t h, l;
            split2(f0, f1, h, l);
            smX[buf][0][n * 12 + kp] = h;
            smX[buf][1][n * 12 + kp] = l;
        }
    };

    float acc[2][4][4] = {};

    load(0, 0);
    __syncthreads();

    for (int ch = 0; ch < nch; ch++) {
        int buf = ch & 1;
        if (ch + 1 < nch) load(ch + 1, buf ^ 1);

        uint32_t ah[2][4], al[2][4];
        #pragma unroll
        for (int mt = 0; mt < 2; mt++)
            #pragma unroll
            for (int r = 0; r < 4; r++) {
                int row = wm * 32 + mt * 16 + g + ((r & 1) << 3);
                int kp = tg + ((r >> 1) << 2);
                ah[mt][r] = smW[buf][0][row * 12 + kp];
                al[mt][r] = smW[buf][1][row * 12 + kp];
            }
        #pragma unroll
        for (int nt = 0; nt < 4; nt++) {
            int nrow = wn * 32 + nt * 8 + g;
            uint32_t bh0 = smX[buf][0][nrow * 12 + tg];
            uint32_t bh1 = smX[buf][0][nrow * 12 + tg + 4];
            uint32_t bl0 = smX[buf][1][nrow * 12 + tg];
            uint32_t bl1 = smX[buf][1][nrow * 12 + tg + 4];
            #pragma unroll
            for (int mt = 0; mt < 2; mt++) {
                mma_bf16(acc[mt][nt], ah[mt], bh0, bh1);
                mma_bf16(acc[mt][nt], ah[mt], bl0, bl1);
                mma_bf16(acc[mt][nt], al[mt], bh0, bh1);
            }
        }
        __syncthreads();
    }

    #pragma unroll
    for (int mt = 0; mt < 2; mt++) {
        int mrow = m0 + wm * 32 + mt * 16 + g;
        float bb0 = Bi[mrow], bb1 = Bi[mrow + 8];
        #pragma unroll
        for (int nt = 0; nt < 4; nt++) {
            int col = n0 + wn * 32 + nt * 8 + tg * 2;
            float2 v0 = {acc[mt][nt][0] + bb0, acc[mt][nt][1] + bb0};
            float2 v1 = {acc[mt][nt][2] + bb1, acc[mt][nt][3] + bb1};
            *(float2*)&Y[(size_t)mrow * P + col] = v0;
            *(float2*)&Y[(size_t)(mrow + 8) * P + col] = v1;
        }
    }
}

// ---------------------------------------------------------------------------
// 2x downsample (64x64 -> 32x32): exact 2x2 mean
// ---------------------------------------------------------------------------
__global__ void down2x_k(const float* __restrict__ src, float* __restrict__ dst,
                         int total) {
    int idx = blockIdx.x * blockDim.x + threadIdx.x;
    if (idx >= total) return;
    int x = idx & 31, y = (idx >> 5) & 31, c = idx >> 10;
    const float* s = src + ((size_t)c << 12) + (y << 7) + (x << 1);
    float2 a0 = *(const float2*)s;
    float2 a1 = *(const float2*)(s + 64);
    dst[idx] = 0.25f * ((a0.x + a0.y) + (a1.x + a1.y));
}

// ---------------------------------------------------------------------------
extern "C" void kernel_launch(void* const* d_in, const int* in_sizes, int n_in,
                              void* d_out, int out_size) {
    const float* high = (const float*)d_in[0];
    const float* low  = (const float*)d_in[1];
    const float* qhw = (const float*)d_in[2];  const float* qhb = (const float*)d_in[3];
    const float* khw = (const float*)d_in[4];  const float* khb = (const float*)d_in[5];
    const float* vhw = (const float*)d_in[6];  const float* vhb = (const float*)d_in[7];
    const float* qlw = (const float*)d_in[8];  const float* qlb = (const float*)d_in[9];
    const float* klw = (const float*)d_in[10]; const float* klb = (const float*)d_in[11];
    const float* vlw = (const float*)d_in[12]; const float* vlb = (const float*)d_in[13];
    const float* ohw = (const float*)d_in[14]; const float* ohb = (const float*)d_in[15];
    const float* olw = (const float*)d_in[16]; const float* olb = (const float*)d_in[17];
    float* out = (float*)d_out;

    float* scr = nullptr;
    cudaGetSymbolAddress((void**)&scr, g_scratch);
    float* qh  = scr + OFF_QH;
    float* ah  = scr + OFF_AH;
    float* kls = scr + OFF_KLS;
    float* vls = scr + OFF_VLS;
    float* ql  = scr + OFF_QL;
    float* kh  = scr + OFF_KH;
    float* vh  = scr + OFF_VH;
    float* hd  = scr + OFF_HD;
    float* al  = scr + OFF_AL;

    // 1) downsample high 64->32
    down2x_k<<<(B * 128 * 1024 + 255) / 256, 256>>>(high, hd, B * 128 * 1024);

    // 2) ALL pre-attention convs in one launch (288 CTAs x B)
    {
        ConvBatch cb;
        cb.d[0] = {low, klw, klb, kls, 256, 1024, 16, 0,   256 * 1024, 256 * 1024};
        cb.d[1] = {low, vlw, vlb, vls, 256, 1024, 16, 32,  256 * 1024, 256 * 1024};
        cb.d[2] = {low, qlw, qlb, ql,  256, 1024, 16, 64,  256 * 1024, 256 * 1024};
        cb.d[3] = {hd, khw, khb, kh,   128, 1024, 16, 96,  128 * 1024, 256 * 1024};
        cb.d[4] = {hd, vhw, vhb, vh,   128, 1024, 16, 128, 128 * 1024, 256 * 1024};
        cb.d[5] = {high, qhw, qhb, qh, 128, 4096, 64, 160, 128 * 4096, 256 * 4096};
        cb.nd = 6;
        conv_mma_k<<<dim3(288, 1, B), 256>>>(cb);
    }

    // 3) bf16 KV planes (fused upsample + pack)
    prep_kv_k<<<10240, 256>>>();

    // 4) merged attention (high 512 + low 128 CTAs)
    attn2_k<<<640, 128>>>(qh, ah, ql, al);

    // 5) both output projections in one launch (96 CTAs x B)
    {
        ConvBatch cb;
        cb.d[0] = {ah, ohw, ohb, out, 256, 4096, 64, 0, 256 * 4096, 128 * 4096};
        cb.d[1] = {al, olw, olb, out + (size_t)B * 128 * 4096,
                   256, 1024, 16, 64, 256 * 1024, 256 * 1024};
        cb.nd = 2;
        conv_mma_k<<<dim3(96, 1, B), 256>>>(cb);
    }
}

// round 10
// speedup vs baseline: 7.2124x; 1.0064x over previous
#include <cuda_runtime.h>
#include <cuda_bf16.h>
#include <cstdint>
#include <math.h>

// ---------------------------------------------------------------------------
// CrossScaleAttention  (B=2, hidden=256, heads=8, head_dim=32)
// R10: attention restructured to 8 warps x 16 query rows (block 256) to halve
//      per-thread registers -> ~2x occupancy. Arithmetic identical to R9.
// ---------------------------------------------------------------------------

#define B 2
#define HID 256
#define NHEAD 8
#define HD 32
#define SCALE 0.17677669529663687f
#define QSCALE (SCALE * 1.4426950408889634f)   // fold log2(e): p = ex2(S)
#define KT 64

// ---------------- fp32 scratch ----------------
#define OFF_QH   0UL                 // [2,256,4096]
#define OFF_AH   2097152UL           // [2,256,4096]
#define OFF_KLS  4194304UL           // [2,256,1024]
#define OFF_VLS  4718592UL
#define OFF_QL   5242880UL
#define OFF_KH   5767168UL
#define OFF_VH   6291456UL
#define OFF_HD   6815744UL           // [2,128,1024]
#define OFF_AL   7077888UL           // [2,256,1024]
#define SCRATCH_FLOATS 7602176UL
__device__ float g_scratch[SCRATCH_FLOATS];

// ---------------- bf16 KV planes (u32 = bf16x2) ----------------
#define OKH_H 0UL
#define OVH_H 1048576UL
#define OKH_L 2097152UL
#define OVH_L 2359296UL
#define KVU_TOTAL 2621440UL
__device__ uint32_t g_kvu[KVU_TOTAL];

// ---------------- helpers ----------------
__device__ __forceinline__ uint32_t pack2rn(float f0, float f1) {
    uint32_t r;
    asm("cvt.rn.bf16x2.f32 %0, %1, %2;" : "=r"(r) : "f"(f1), "f"(f0));
    return r;
}
__device__ __forceinline__ void split2(float f0, float f1, uint32_t& hi, uint32_t& lo) {
    asm("cvt.rn.bf16x2.f32 %0, %1, %2;" : "=r"(hi) : "f"(f1), "f"(f0));
    float h0 = __uint_as_float(hi << 16);
    float h1 = __uint_as_float(hi & 0xFFFF0000u);
    float r0 = f0 - h0, r1 = f1 - h1;
    asm("cvt.rn.bf16x2.f32 %0, %1, %2;" : "=r"(lo) : "f"(r1), "f"(r0));
}

__device__ __forceinline__ void mma_bf16(float* c, const uint32_t* a,
                                         uint32_t b0, uint32_t b1) {
    asm volatile(
        "mma.sync.aligned.m16n8k16.row.col.f32.bf16.bf16.f32 "
        "{%0,%1,%2,%3}, {%4,%5,%6,%7}, {%8,%9}, {%0,%1,%2,%3};"
        : "+f"(c[0]), "+f"(c[1]), "+f"(c[2]), "+f"(c[3])
        : "r"(a[0]), "r"(a[1]), "r"(a[2]), "r"(a[3]), "r"(b0), "r"(b1));
}

__device__ __forceinline__ float ex2f(float x) {
    float y;
    asm("ex2.approx.f32 %0, %1;" : "=f"(y) : "f"(x));
    return y;
}

__device__ __forceinline__ uint32_t smem_u32p(const void* p) {
    uint32_t a;
    asm("{ .reg .u64 t; cvta.to.shared.u64 t, %1; cvt.u32.u64 %0, t; }" : "=r"(a) : "l"(p));
    return a;
}
__device__ __forceinline__ void cp16(uint32_t saddr, const void* g) {
    asm volatile("cp.async.ca.shared.global [%0], [%1], 16;" :: "r"(saddr), "l"(g) : "memory");
}
#define CP_COMMIT() asm volatile("cp.async.commit_group;" ::: "memory")
#define CP_WAIT0()  asm volatile("cp.async.wait_group 0;" ::: "memory")

// bilinear 2x upsample sample (32x32 -> 64x64, align_corners=False)
__device__ __forceinline__ float up_sample(const float* __restrict__ s, int y, int x) {
    int y0 = max((y - 1) >> 1, 0), y1 = min((y + 1) >> 1, 31);
    int x0 = max((x - 1) >> 1, 0), x1 = min((x + 1) >> 1, 31);
    float wy = (y & 1) ? 0.25f : 0.75f;
    float wx = (x & 1) ? 0.25f : 0.75f;
    float v00 = s[(y0 << 5) + x0], v01 = s[(y0 << 5) + x1];
    float v10 = s[(y1 << 5) + x0], v11 = s[(y1 << 5) + x1];
    float top = v00 + wx * (v01 - v00);
    float bot = v10 + wx * (v11 - v10);
    return top + wy * (bot - top);
}

// ---------------------------------------------------------------------------
// prep_kv: build bf16 KV planes (proven).
// ---------------------------------------------------------------------------
__global__ __launch_bounds__(256) void prep_kv_k() {
    const float* kls = g_scratch + OFF_KLS;
    const float* vls = g_scratch + OFF_VLS;
    const float* kh  = g_scratch + OFF_KH;
    const float* vh  = g_scratch + OFF_VH;
    int gid = blockIdx.x * 256 + threadIdx.x;

    if (gid < 1048576) {                 // high K: [bh][key 4096][dp 16]
        int dp = gid & 15, key = (gid >> 4) & 4095, bh = gid >> 16;
        int y = key >> 6, x = key & 63;
        const float* s = kls + (((size_t)(bh >> 3) * 256) + (bh & 7) * 32 + 2 * dp) * 1024;
        g_kvu[OKH_H + gid] = pack2rn(up_sample(s, y, x), up_sample(s + 1024, y, x));
    } else if (gid < 2097152) {          // high V: [bh][d 32][kp 2048]
        int g2 = gid - 1048576;
        int kp = g2 & 2047, d = (g2 >> 11) & 31, bh = g2 >> 16;
        int key = kp << 1;
        int y = key >> 6, x = key & 63;
        const float* s = vls + (((size_t)(bh >> 3) * 256) + (bh & 7) * 32 + d) * 1024;
        g_kvu[OVH_H + g2] = pack2rn(up_sample(s, y, x), up_sample(s, y, x + 1));
    } else if (gid < 2359296) {          // low K: [bh][key 1024][dp 16]
        int g3 = gid - 2097152;
        int dp = g3 & 15, key = (g3 >> 4) & 1023, bh = g3 >> 14;
        const float* s = kh + (((size_t)(bh >> 3) * 256) + (bh & 7) * 32 + 2 * dp) * 1024 + key;
        g_kvu[OKH_L + g3] = pack2rn(s[0], s[1024]);
    } else if (gid < 2621440) {          // low V: [bh][d 32][kp 512]
        int g4 = gid - 2359296;
        int kp = g4 & 511, d = (g4 >> 9) & 31, bh = g4 >> 14;
        const float* s = vh + (((size_t)(bh >> 3) * 256) + (bh & 7) * 32 + d) * 1024 + 2 * kp;
        g_kvu[OVH_L + g4] = pack2rn(s[0], s[1]);
    }
}

// ---------------------------------------------------------------------------
// Merged flash attention. Q/K/V/P bf16, fp32 exp/l/O accumulation.
// block 256 = 8 warps x 16 query rows. high: CTAs [0,512), low: [512,640).
// ---------------------------------------------------------------------------
__global__ __launch_bounds__(256) void attn2_k(const float* __restrict__ qH,
                                               float* __restrict__ oH,
                                               const float* __restrict__ qL,
                                               float* __restrict__ oL) {
    __shared__ __align__(16) uint32_t Ksm[2][64 * 20];
    __shared__ __align__(16) uint32_t Vsm[2][32 * 36];

    int tid = threadIdx.x;
    int w = tid >> 5, lane = tid & 31;
    int g = lane >> 2, tg = lane & 3;

    int cta = blockIdx.x;
    const float* q;
    float* out;
    const uint32_t *Kg, *Vg;
    int N, q0, bh;
    if (cta < 512) {
        N = 4096; bh = cta >> 5; q0 = (cta & 31) << 7;
        q = qH; out = oH;
        Kg = g_kvu + OKH_H + ((size_t)bh << 16);
        Vg = g_kvu + OVH_H + ((size_t)bh << 16);
    } else {
        int idx = cta - 512;
        N = 1024; bh = idx >> 3; q0 = (idx & 7) << 7;
        q = qL; out = oL;
        Kg = g_kvu + OKH_L + ((size_t)bh << 14);
        Vg = g_kvu + OVH_L + ((size_t)bh << 14);
    }
    size_t base = (size_t)32 * bh * N;
    int halfN = N >> 1;

    uint32_t ks0 = smem_u32p(&Ksm[0][0]);
    uint32_t vs0 = smem_u32p(&Vsm[0][0]);

    // ---- Q fragments: warp covers rows q0 + w*16 .. +15 ----
    uint32_t qf[2][4];
    #pragma unroll
    for (int kt = 0; kt < 2; kt++)
        #pragma unroll
        for (int r = 0; r < 4; r++) {
            int row = q0 + w * 16 + g + (r & 1) * 8;
            int d0 = kt * 16 + tg * 2 + (r >> 1) * 8;
            float f0 = q[base + (size_t)d0 * N + row] * QSCALE;
            float f1 = q[base + (size_t)(d0 + 1) * N + row] * QSCALE;
            qf[kt][r] = pack2rn(f0, f1);
        }

    auto load_tile = [&](int buf, int kv0) {
        int kp0 = kv0 >> 1;
        {   // K: 256 x 16B chunks, 1 per thread
            int key = tid >> 2, c4 = (tid & 3) << 2;
            cp16(ks0 + (uint32_t)(buf * 1280 + key * 20 + c4) * 4,
                 Kg + (size_t)(kv0 + key) * 16 + c4);
        }
        {   // V: 256 x 16B chunks, 1 per thread
            int d = tid >> 3, c = (tid & 7) << 2;
            cp16(vs0 + (uint32_t)(buf * 1152 + d * 36 + c) * 4,
                 Vg + (size_t)d * halfN + kp0 + c);
        }
        CP_COMMIT();
    };

    float O[4][4] = {};
    float lacc[2] = {};

    load_tile(0, 0);
    CP_WAIT0();
    __syncthreads();

    int T = N / KT;
    for (int it = 0; it < T; it++) {
        int buf = it & 1;
        if (it + 1 < T) load_tile(buf ^ 1, (it + 1) * KT);

        const uint32_t* Kh = Ksm[buf];
        const uint32_t* Vh = Vsm[buf];

        uint32_t pah[4];
        #pragma unroll
        for (int j = 0; j < 8; j++) {
            float S[4] = {0.f, 0.f, 0.f, 0.f};
            #pragma unroll
            for (int kt = 0; kt < 2; kt++) {
                int bi = (j * 8 + g) * 20 + kt * 8 + tg;
                mma_bf16(S, qf[kt], Kh[bi], Kh[bi + 4]);
            }
            float p0 = ex2f(S[0]), p1 = ex2f(S[1]);
            float p2 = ex2f(S[2]), p3 = ex2f(S[3]);
            lacc[0] += p0 + p1;
            lacc[1] += p2 + p3;
            int odd = j & 1;
            pah[odd * 2]     = pack2rn(p0, p1);
            pah[odd * 2 + 1] = pack2rn(p2, p3);
            if (odd) {
                int kt2 = j >> 1;
                #pragma unroll
                for (int jd = 0; jd < 4; jd++) {
                    int bi = (jd * 8 + g) * 36 + kt2 * 8 + tg;
                    mma_bf16(O[jd], pah, Vh[bi], Vh[bi + 4]);
                }
            }
        }

        if (it + 1 < T) CP_WAIT0();
        __syncthreads();
    }

    #pragma unroll
    for (int r = 0; r < 2; r++) {
        float l = lacc[r];
        l += __shfl_xor_sync(0xffffffffu, l, 1);
        l += __shfl_xor_sync(0xffffffffu, l, 2);
        lacc[r] = 1.0f / l;
    }

    int row0 = q0 + w * 16 + g;
    #pragma unroll
    for (int jd = 0; jd < 4; jd++) {
        int d0 = jd * 8 + tg * 2;
        out[base + (size_t)d0 * N + row0]           = O[jd][0] * lacc[0];
        out[base + (size_t)(d0 + 1) * N + row0]     = O[jd][1] * lacc[0];
        out[base + (size_t)d0 * N + row0 + 8]       = O[jd][2] * lacc[1];
        out[base + (size_t)(d0 + 1) * N + row0 + 8] = O[jd][3] * lacc[1];
    }
}

// ---------------------------------------------------------------------------
// Batched conv1x1 (proven): up to 6 GEMM outputs per launch.
// bf16 3-term split, BM=128, BN=64, BK=16, double-buffered.
// ---------------------------------------------------------------------------
struct ConvDesc {
    const float* x;
    const float* w;
    const float* bias;
    float* y;
    int C, P, nblocks, cta0, xbs, ybs;
};
struct ConvBatch {
    ConvDesc d[6];
    int nd;
};

__global__ __launch_bounds__(256) void conv_mma_k(ConvBatch args) {
    __shared__ uint32_t smW[2][2][1536];
    __shared__ uint32_t smX[2][2][768];

    int bx = blockIdx.x;
    int u = 0;
    #pragma unroll
    for (int i = 1; i < 6; i++)
        if (i < args.nd && bx >= args.d[i].cta0) u = i;
    const ConvDesc& D = args.d[u];
    int rem = bx - D.cta0;
    int m0 = (rem / D.nblocks) << 7;
    int n0 = (rem % D.nblocks) << 6;
    int b = blockIdx.z;
    int C = D.C, P = D.P;
    const float* X = D.x + (size_t)b * D.xbs;
    const float* W = D.w;
    const float* Bi = D.bias;
    float* Y = D.y + (size_t)b * D.ybs;
    int nch = C >> 4;

    int tid = threadIdx.x;
    int w = tid >> 5, lane = tid & 31, g = lane >> 2, tg = lane & 3;
    int wm = w >> 1, wn = w & 1;

    auto load = [&](int ch, int buf) {
        int c0 = ch << 4;
        {
            int m = tid >> 1, half = tid & 1;
            const float4* src = reinterpret_cast<const float4*>(
                W + (size_t)(m0 + m) * C + c0 + half * 8);
            float4 f0 = src[0], f1 = src[1];
            uint32_t* dh = &smW[buf][0][m * 12 + half * 4];
            uint32_t* dl = &smW[buf][1][m * 12 + half * 4];
            uint32_t h, l;
            split2(f0.x, f0.y, h, l); dh[0] = h; dl[0] = l;
            split2(f0.z, f0.w, h, l); dh[1] = h; dl[1] = l;
            split2(f1.x, f1.y, h, l); dh[2] = h; dl[2] = l;
            split2(f1.z, f1.w, h, l); dh[3] = h; dl[3] = l;
        }
        #pragma unroll
        for (int i = 0; i < 2; i++) {
            int idx = tid + (i << 8);
            int kp = idx >> 6, n = idx & 63;
            float f0 = X[(size_t)(c0 + 2 * kp) * P + n0 + n];
            float f1 = X[(size_t)(c0 + 2 * kp + 1) * P + n0 + n];
            uint32_t h, l;
            split2(f0, f1, h, l);
            smX[buf][0][n * 12 + kp] = h;
            smX[buf][1][n * 12 + kp] = l;
        }
    };

    float acc[2][4][4] = {};

    load(0, 0);
    __syncthreads();

    for (int ch = 0; ch < nch; ch++) {
        int buf = ch & 1;
        if (ch + 1 < nch) load(ch + 1, buf ^ 1);

        uint32_t ah[2][4], al[2][4];
        #pragma unroll
        for (int mt = 0; mt < 2; mt++)
            #pragma unroll
            for (int r = 0; r < 4; r++) {
                int row = wm * 32 + mt * 16 + g + ((r & 1) << 3);
                int kp = tg + ((r >> 1) << 2);
                ah[mt][r] = smW[buf][0][row * 12 + kp];
                al[mt][r] = smW[buf][1][row * 12 + kp];
            }
        #pragma unroll
        for (int nt = 0; nt < 4; nt++) {
            int nrow = wn * 32 + nt * 8 + g;
            uint32_t bh0 = smX[buf][0][nrow * 12 + tg];
            uint32_t bh1 = smX[buf][0][nrow * 12 + tg + 4];
            uint32_t bl0 = smX[buf][1][nrow * 12 + tg];
            uint32_t bl1 = smX[buf][1][nrow * 12 + tg + 4];
            #pragma unroll
            for (int mt = 0; mt < 2; mt++) {
                mma_bf16(acc[mt][nt], ah[mt], bh0, bh1);
                mma_bf16(acc[mt][nt], ah[mt], bl0, bl1);
                mma_bf16(acc[mt][nt], al[mt], bh0, bh1);
            }
        }
        __syncthreads();
    }

    #pragma unroll
    for (int mt = 0; mt < 2; mt++) {
        int mrow = m0 + wm * 32 + mt * 16 + g;
        float bb0 = Bi[mrow], bb1 = Bi[mrow + 8];
        #pragma unroll
        for (int nt = 0; nt < 4; nt++) {
            int col = n0 + wn * 32 + nt * 8 + tg * 2;
            float2 v0 = {acc[mt][nt][0] + bb0, acc[mt][nt][1] + bb0};
            float2 v1 = {acc[mt][nt][2] + bb1, acc[mt][nt][3] + bb1};
            *(float2*)&Y[(size_t)mrow * P + col] = v0;
            *(float2*)&Y[(size_t)(mrow + 8) * P + col] = v1;
        }
    }
}

// ---------------------------------------------------------------------------
// 2x downsample (64x64 -> 32x32): exact 2x2 mean
// ---------------------------------------------------------------------------
__global__ void down2x_k(const float* __restrict__ src, float* __restrict__ dst,
                         int total) {
    int idx = blockIdx.x * blockDim.x + threadIdx.x;
    if (idx >= total) return;
    int x = idx & 31, y = (idx >> 5) & 31, c = idx >> 10;
    const float* s = src + ((size_t)c << 12) + (y << 7) + (x << 1);
    float2 a0 = *(const float2*)s;
    float2 a1 = *(const float2*)(s + 64);
    dst[idx] = 0.25f * ((a0.x + a0.y) + (a1.x + a1.y));
}

// ---------------------------------------------------------------------------
extern "C" void kernel_launch(void* const* d_in, const int* in_sizes, int n_in,
                              void* d_out, int out_size) {
    const float* high = (const float*)d_in[0];
    const float* low  = (const float*)d_in[1];
    const float* qhw = (const float*)d_in[2];  const float* qhb = (const float*)d_in[3];
    const float* khw = (const float*)d_in[4];  const float* khb = (const float*)d_in[5];
    const float* vhw = (const float*)d_in[6];  const float* vhb = (const float*)d_in[7];
    const float* qlw = (const float*)d_in[8];  const float* qlb = (const float*)d_in[9];
    const float* klw = (const float*)d_in[10]; const float* klb = (const float*)d_in[11];
    const float* vlw = (const float*)d_in[12]; const float* vlb = (const float*)d_in[13];
    const float* ohw = (const float*)d_in[14]; const float* ohb = (const float*)d_in[15];
    const float* olw = (const float*)d_in[16]; const float* olb = (const float*)d_in[17];
    float* out = (float*)d_out;

    float* scr = nullptr;
    cudaGetSymbolAddress((void**)&scr, g_scratch);
    float* qh  = scr + OFF_QH;
    float* ah  = scr + OFF_AH;
    float* kls = scr + OFF_KLS;
    float* vls = scr + OFF_VLS;
    float* ql  = scr + OFF_QL;
    float* kh  = scr + OFF_KH;
    float* vh  = scr + OFF_VH;
    float* hd  = scr + OFF_HD;
    float* al  = scr + OFF_AL;

    // 1) downsample high 64->32
    down2x_k<<<(B * 128 * 1024 + 255) / 256, 256>>>(high, hd, B * 128 * 1024);

    // 2) ALL pre-attention convs in one launch (288 CTAs x B)
    {
        ConvBatch cb;
        cb.d[0] = {low, klw, klb, kls, 256, 1024, 16, 0,   256 * 1024, 256 * 1024};
        cb.d[1] = {low, vlw, vlb, vls, 256, 1024, 16, 32,  256 * 1024, 256 * 1024};
        cb.d[2] = {low, qlw, qlb, ql,  256, 1024, 16, 64,  256 * 1024, 256 * 1024};
        cb.d[3] = {hd, khw, khb, kh,   128, 1024, 16, 96,  128 * 1024, 256 * 1024};
        cb.d[4] = {hd, vhw, vhb, vh,   128, 1024, 16, 128, 128 * 1024, 256 * 1024};
        cb.d[5] = {high, qhw, qhb, qh, 128, 4096, 64, 160, 128 * 4096, 256 * 4096};
        cb.nd = 6;
        conv_mma_k<<<dim3(288, 1, B), 256>>>(cb);
    }

    // 3) bf16 KV planes (fused upsample + pack)
    prep_kv_k<<<10240, 256>>>();

    // 4) merged attention (high 512 + low 128 CTAs), 8 warps/CTA
    attn2_k<<<640, 256>>>(qh, ah, ql, al);

    // 5) both output projections in one launch (96 CTAs x B)
    {
        ConvBatch cb;
        cb.d[0] = {ah, ohw, ohb, out, 256, 4096, 64, 0, 256 * 4096, 128 * 4096};
        cb.d[1] = {al, olw, olb, out + (size_t)B * 128 * 4096,
                   256, 1024, 16, 64, 256 * 1024, 256 * 1024};
        cb.nd = 2;
        conv_mma_k<<<dim3(96, 1, B), 256>>>(cb);
    }
}

// round 11
// speedup vs baseline: 7.6732x; 1.0639x over previous
#include <cuda_runtime.h>
#include <cuda_bf16.h>
#include <cstdint>
#include <math.h>

// ---------------------------------------------------------------------------
// CrossScaleAttention  (B=2, hidden=256, heads=8, head_dim=32)
// R11: attention fragment loads via ldmatrix.x4 (1 instr replaces 4 LDS +
//      address math) -> per-tile issue count -33%. Arithmetic identical R10.
// ---------------------------------------------------------------------------

#define B 2
#define HID 256
#define NHEAD 8
#define HD 32
#define SCALE 0.17677669529663687f
#define QSCALE (SCALE * 1.4426950408889634f)   // fold log2(e): p = ex2(S)
#define KT 64

// ---------------- fp32 scratch ----------------
#define OFF_QH   0UL                 // [2,256,4096]
#define OFF_AH   2097152UL           // [2,256,4096]
#define OFF_KLS  4194304UL           // [2,256,1024]
#define OFF_VLS  4718592UL
#define OFF_QL   5242880UL
#define OFF_KH   5767168UL
#define OFF_VH   6291456UL
#define OFF_HD   6815744UL           // [2,128,1024]
#define OFF_AL   7077888UL           // [2,256,1024]
#define SCRATCH_FLOATS 7602176UL
__device__ float g_scratch[SCRATCH_FLOATS];

// ---------------- bf16 KV planes (u32 = bf16x2) ----------------
#define OKH_H 0UL
#define OVH_H 1048576UL
#define OKH_L 2097152UL
#define OVH_L 2359296UL
#define KVU_TOTAL 2621440UL
__device__ uint32_t g_kvu[KVU_TOTAL];

// ---------------- helpers ----------------
__device__ __forceinline__ uint32_t pack2rn(float f0, float f1) {
    uint32_t r;
    asm("cvt.rn.bf16x2.f32 %0, %1, %2;" : "=r"(r) : "f"(f1), "f"(f0));
    return r;
}
__device__ __forceinline__ void split2(float f0, float f1, uint32_t& hi, uint32_t& lo) {
    asm("cvt.rn.bf16x2.f32 %0, %1, %2;" : "=r"(hi) : "f"(f1), "f"(f0));
    float h0 = __uint_as_float(hi << 16);
    float h1 = __uint_as_float(hi & 0xFFFF0000u);
    float r0 = f0 - h0, r1 = f1 - h1;
    asm("cvt.rn.bf16x2.f32 %0, %1, %2;" : "=r"(lo) : "f"(r1), "f"(r0));
}

__device__ __forceinline__ void mma_bf16(float* c, const uint32_t* a,
                                         uint32_t b0, uint32_t b1) {
    asm volatile(
        "mma.sync.aligned.m16n8k16.row.col.f32.bf16.bf16.f32 "
        "{%0,%1,%2,%3}, {%4,%5,%6,%7}, {%8,%9}, {%0,%1,%2,%3};"
        : "+f"(c[0]), "+f"(c[1]), "+f"(c[2]), "+f"(c[3])
        : "r"(a[0]), "r"(a[1]), "r"(a[2]), "r"(a[3]), "r"(b0), "r"(b1));
}

__device__ __forceinline__ void ldsm_x4(uint32_t* r, uint32_t addr) {
    asm volatile("ldmatrix.sync.aligned.m8n8.x4.shared.b16 {%0,%1,%2,%3}, [%4];"
        : "=r"(r[0]), "=r"(r[1]), "=r"(r[2]), "=r"(r[3]) : "r"(addr));
}

__device__ __forceinline__ float ex2f(float x) {
    float y;
    asm("ex2.approx.f32 %0, %1;" : "=f"(y) : "f"(x));
    return y;
}

__device__ __forceinline__ uint32_t smem_u32p(const void* p) {
    uint32_t a;
    asm("{ .reg .u64 t; cvta.to.shared.u64 t, %1; cvt.u32.u64 %0, t; }" : "=r"(a) : "l"(p));
    return a;
}
__device__ __forceinline__ void cp16(uint32_t saddr, const void* g) {
    asm volatile("cp.async.ca.shared.global [%0], [%1], 16;" :: "r"(saddr), "l"(g) : "memory");
}
#define CP_COMMIT() asm volatile("cp.async.commit_group;" ::: "memory")
#define CP_WAIT0()  asm volatile("cp.async.wait_group 0;" ::: "memory")

// bilinear 2x upsample sample (32x32 -> 64x64, align_corners=False)
__device__ __forceinline__ float up_sample(const float* __restrict__ s, int y, int x) {
    int y0 = max((y - 1) >> 1, 0), y1 = min((y + 1) >> 1, 31);
    int x0 = max((x - 1) >> 1, 0), x1 = min((x + 1) >> 1, 31);
    float wy = (y & 1) ? 0.25f : 0.75f;
    float wx = (x & 1) ? 0.25f : 0.75f;
    float v00 = s[(y0 << 5) + x0], v01 = s[(y0 << 5) + x1];
    float v10 = s[(y1 << 5) + x0], v11 = s[(y1 << 5) + x1];
    float top = v00 + wx * (v01 - v00);
    float bot = v10 + wx * (v11 - v10);
    return top + wy * (bot - top);
}

// ---------------------------------------------------------------------------
// prep_kv: build bf16 KV planes (proven).
// ---------------------------------------------------------------------------
__global__ __launch_bounds__(256) void prep_kv_k() {
    const float* kls = g_scratch + OFF_KLS;
    const float* vls = g_scratch + OFF_VLS;
    const float* kh  = g_scratch + OFF_KH;
    const float* vh  = g_scratch + OFF_VH;
    int gid = blockIdx.x * 256 + threadIdx.x;

    if (gid < 1048576) {                 // high K: [bh][key 4096][dp 16]
        int dp = gid & 15, key = (gid >> 4) & 4095, bh = gid >> 16;
        int y = key >> 6, x = key & 63;
        const float* s = kls + (((size_t)(bh >> 3) * 256) + (bh & 7) * 32 + 2 * dp) * 1024;
        g_kvu[OKH_H + gid] = pack2rn(up_sample(s, y, x), up_sample(s + 1024, y, x));
    } else if (gid < 2097152) {          // high V: [bh][d 32][kp 2048]
        int g2 = gid - 1048576;
        int kp = g2 & 2047, d = (g2 >> 11) & 31, bh = g2 >> 16;
        int key = kp << 1;
        int y = key >> 6, x = key & 63;
        const float* s = vls + (((size_t)(bh >> 3) * 256) + (bh & 7) * 32 + d) * 1024;
        g_kvu[OVH_H + g2] = pack2rn(up_sample(s, y, x), up_sample(s, y, x + 1));
    } else if (gid < 2359296) {          // low K: [bh][key 1024][dp 16]
        int g3 = gid - 2097152;
        int dp = g3 & 15, key = (g3 >> 4) & 1023, bh = g3 >> 14;
        const float* s = kh + (((size_t)(bh >> 3) * 256) + (bh & 7) * 32 + 2 * dp) * 1024 + key;
        g_kvu[OKH_L + g3] = pack2rn(s[0], s[1024]);
    } else if (gid < 2621440) {          // low V: [bh][d 32][kp 512]
        int g4 = gid - 2359296;
        int kp = g4 & 511, d = (g4 >> 9) & 31, bh = g4 >> 14;
        const float* s = vh + (((size_t)(bh >> 3) * 256) + (bh & 7) * 32 + d) * 1024 + 2 * kp;
        g_kvu[OVH_L + g4] = pack2rn(s[0], s[1]);
    }
}

// ---------------------------------------------------------------------------
// Merged flash attention. Q/K/V/P bf16, fp32 exp/l/O accumulation.
// block 256 = 8 warps x 16 query rows. Fragment loads via ldmatrix.x4.
// K tile: [key 64][dp 16 pad 20] u32 (row 80B). V: [d 32][kp pad 36] (row 144B).
// ---------------------------------------------------------------------------
__global__ __launch_bounds__(256) void attn2_k(const float* __restrict__ qH,
                                               float* __restrict__ oH,
                                               const float* __restrict__ qL,
                                               float* __restrict__ oL) {
    __shared__ __align__(16) uint32_t Ksm[2][64 * 20];
    __shared__ __align__(16) uint32_t Vsm[2][32 * 36];

    int tid = threadIdx.x;
    int w = tid >> 5, lane = tid & 31;
    int g = lane >> 2, tg = lane & 3;

    int cta = blockIdx.x;
    const float* q;
    float* out;
    const uint32_t *Kg, *Vg;
    int N, q0, bh;
    if (cta < 512) {
        N = 4096; bh = cta >> 5; q0 = (cta & 31) << 7;
        q = qH; out = oH;
        Kg = g_kvu + OKH_H + ((size_t)bh << 16);
        Vg = g_kvu + OVH_H + ((size_t)bh << 16);
    } else {
        int idx = cta - 512;
        N = 1024; bh = idx >> 3; q0 = (idx & 7) << 7;
        q = qL; out = oL;
        Kg = g_kvu + OKH_L + ((size_t)bh << 14);
        Vg = g_kvu + OVH_L + ((size_t)bh << 14);
    }
    size_t base = (size_t)32 * bh * N;
    int halfN = N >> 1;

    uint32_t ks0 = smem_u32p(&Ksm[0][0]);
    uint32_t vs0 = smem_u32p(&Vsm[0][0]);

    // ldmatrix per-lane row addresses (bytes):
    // K: matrix m = lane>>3 selects 16B chunk m; row = lane&7 -> key j*8+row.
    uint32_t kfrag = ks0 + (lane & 7) * 80 + (lane >> 3) * 16;
    // V: matrix m: jd-half = lane>>4, chunk-half = (lane>>3)&1; row = d-row.
    uint32_t vfrag = vs0 + ((lane >> 4) * 8 + (lane & 7)) * 144 + ((lane >> 3) & 1) * 16;

    // ---- Q fragments: warp covers rows q0 + w*16 .. +15 ----
    uint32_t qf[2][4];
    #pragma unroll
    for (int kt = 0; kt < 2; kt++)
        #pragma unroll
        for (int r = 0; r < 4; r++) {
            int row = q0 + w * 16 + g + (r & 1) * 8;
            int d0 = kt * 16 + tg * 2 + (r >> 1) * 8;
            float f0 = q[base + (size_t)d0 * N + row] * QSCALE;
            float f1 = q[base + (size_t)(d0 + 1) * N + row] * QSCALE;
            qf[kt][r] = pack2rn(f0, f1);
        }

    auto load_tile = [&](int buf, int kv0) {
        int kp0 = kv0 >> 1;
        {   // K: 256 x 16B chunks, 1 per thread
            int key = tid >> 2, c4 = (tid & 3) << 2;
            cp16(ks0 + (uint32_t)(buf * 1280 + key * 20 + c4) * 4,
                 Kg + (size_t)(kv0 + key) * 16 + c4);
        }
        {   // V: 256 x 16B chunks, 1 per thread
            int d = tid >> 3, c = (tid & 7) << 2;
            cp16(vs0 + (uint32_t)(buf * 1152 + d * 36 + c) * 4,
                 Vg + (size_t)d * halfN + kp0 + c);
        }
        CP_COMMIT();
    };

    float O[4][4] = {};
    float lacc[2] = {};

    load_tile(0, 0);
    CP_WAIT0();
    __syncthreads();

    int T = N / KT;
    for (int it = 0; it < T; it++) {
        int buf = it & 1;
        if (it + 1 < T) load_tile(buf ^ 1, (it + 1) * KT);

        uint32_t kbase = buf * 5120;     // bytes: 1280 u32 per buf
        uint32_t vbase = buf * 4608;     // bytes: 1152 u32 per buf

        uint32_t pah[4];
        #pragma unroll
        for (int j = 0; j < 8; j++) {
            uint32_t kb[4];
            ldsm_x4(kb, kfrag + kbase + j * 640);   // 8 keys x 80B rows
            float S[4] = {0.f, 0.f, 0.f, 0.f};
            mma_bf16(S, qf[0], kb[0], kb[1]);
            mma_bf16(S, qf[1], kb[2], kb[3]);

            float p0 = ex2f(S[0]), p1 = ex2f(S[1]);
            float p2 = ex2f(S[2]), p3 = ex2f(S[3]);
            lacc[0] += p0 + p1;
            lacc[1] += p2 + p3;
            int odd = j & 1;
            pah[odd * 2]     = pack2rn(p0, p1);
            pah[odd * 2 + 1] = pack2rn(p2, p3);
            if (odd) {
                uint32_t va = vfrag + vbase + (uint32_t)(j >> 1) * 32;  // kt2*8 u32
                uint32_t vb[4];
                ldsm_x4(vb, va);                    // jd 0,1
                mma_bf16(O[0], pah, vb[0], vb[1]);
                mma_bf16(O[1], pah, vb[2], vb[3]);
                ldsm_x4(vb, va + 2304);             // jd 2,3 (+2*8*144 B)
                mma_bf16(O[2], pah, vb[0], vb[1]);
                mma_bf16(O[3], pah, vb[2], vb[3]);
            }
        }

        if (it + 1 < T) CP_WAIT0();
        __syncthreads();
    }

    #pragma unroll
    for (int r = 0; r < 2; r++) {
        float l = lacc[r];
        l += __shfl_xor_sync(0xffffffffu, l, 1);
        l += __shfl_xor_sync(0xffffffffu, l, 2);
        lacc[r] = 1.0f / l;
    }

    int row0 = q0 + w * 16 + g;
    #pragma unroll
    for (int jd = 0; jd < 4; jd++) {
        int d0 = jd * 8 + tg * 2;
        out[base + (size_t)d0 * N + row0]           = O[jd][0] * lacc[0];
        out[base + (size_t)(d0 + 1) * N + row0]     = O[jd][1] * lacc[0];
        out[base + (size_t)d0 * N + row0 + 8]       = O[jd][2] * lacc[1];
        out[base + (size_t)(d0 + 1) * N + row0 + 8] = O[jd][3] * lacc[1];
    }
}

// ---------------------------------------------------------------------------
// Batched conv1x1 (proven): up to 6 GEMM outputs per launch.
// bf16 3-term split, BM=128, BN=64, BK=16, double-buffered.
// ---------------------------------------------------------------------------
struct ConvDesc {
    const float* x;
    const float* w;
    const float* bias;
    float* y;
    int C, P, nblocks, cta0, xbs, ybs;
};
struct ConvBatch {
    ConvDesc d[6];
    int nd;
};

__global__ __launch_bounds__(256) void conv_mma_k(ConvBatch args) {
    __shared__ uint32_t smW[2][2][1536];
    __shared__ uint32_t smX[2][2][768];

    int bx = blockIdx.x;
    int u = 0;
    #pragma unroll
    for (int i = 1; i < 6; i++)
        if (i < args.nd && bx >= args.d[i].cta0) u = i;
    const ConvDesc& D = args.d[u];
    int rem = bx - D.cta0;
    int m0 = (rem / D.nblocks) << 7;
    int n0 = (rem % D.nblocks) << 6;
    int b = blockIdx.z;
    int C = D.C, P = D.P;
    const float* X = D.x + (size_t)b * D.xbs;
    const float* W = D.w;
    const float* Bi = D.bias;
    float* Y = D.y + (size_t)b * D.ybs;
    int nch = C >> 4;

    int tid = threadIdx.x;
    int w = tid >> 5, lane = tid & 31, g = lane >> 2, tg = lane & 3;
    int wm = w >> 1, wn = w & 1;

    auto load = [&](int ch, int buf) {
        int c0 = ch << 4;
        {
            int m = tid >> 1, half = tid & 1;
            const float4* src = reinterpret_cast<const float4*>(
                W + (size_t)(m0 + m) * C + c0 + half * 8);
            float4 f0 = src[0], f1 = src[1];
            uint32_t* dh = &smW[buf][0][m * 12 + half * 4];
            uint32_t* dl = &smW[buf][1][m * 12 + half * 4];
            uint32_t h, l;
            split2(f0.x, f0.y, h, l); dh[0] = h; dl[0] = l;
            split2(f0.z, f0.w, h, l); dh[1] = h; dl[1] = l;
            split2(f1.x, f1.y, h, l); dh[2] = h; dl[2] = l;
            split2(f1.z, f1.w, h, l); dh[3] = h; dl[3] = l;
        }
        #pragma unroll
        for (int i = 0; i < 2; i++) {
            int idx = tid + (i << 8);
            int kp = idx >> 6, n = idx & 63;
            float f0 = X[(size_t)(c0 + 2 * kp) * P + n0 + n];
            float f1 = X[(size_t)(c0 + 2 * kp + 1) * P + n0 + n];
            uint32_t h, l;
            split2(f0, f1, h, l);
            smX[buf][0][n * 12 + kp] = h;
            smX[buf][1][n * 12 + kp] = l;
        }
    };

    float acc[2][4][4] = {};

    load(0, 0);
    __syncthreads();

    for (int ch = 0; ch < nch; ch++) {
        int buf = ch & 1;
        if (ch + 1 < nch) load(ch + 1, buf ^ 1);

        uint32_t ah[2][4], al[2][4];
        #pragma unroll
        for (int mt = 0; mt < 2; mt++)
            #pragma unroll
            for (int r = 0; r < 4; r++) {
                int row = wm * 32 + mt * 16 + g + ((r & 1) << 3);
                int kp = tg + ((r >> 1) << 2);
                ah[mt][r] = smW[buf][0][row * 12 + kp];
                al[mt][r] = smW[buf][1][row * 12 + kp];
            }
        #pragma unroll
        for (int nt = 0; nt < 4; nt++) {
            int nrow = wn * 32 + nt * 8 + g;
            uint32_t bh0 = smX[buf][0][nrow * 12 + tg];
            uint32_t bh1 = smX[buf][0][nrow * 12 + tg + 4];
            uint32_t bl0 = smX[buf][1][nrow * 12 + tg];
            uint32_t bl1 = smX[buf][1][nrow * 12 + tg + 4];
            #pragma unroll
            for (int mt = 0; mt < 2; mt++) {
                mma_bf16(acc[mt][nt], ah[mt], bh0, bh1);
                mma_bf16(acc[mt][nt], ah[mt], bl0, bl1);
                mma_bf16(acc[mt][nt], al[mt], bh0, bh1);
            }
        }
        __syncthreads();
    }

    #pragma unroll
    for (int mt = 0; mt < 2; mt++) {
        int mrow = m0 + wm * 32 + mt * 16 + g;
        float bb0 = Bi[mrow], bb1 = Bi[mrow + 8];
        #pragma unroll
        for (int nt = 0; nt < 4; nt++) {
            int col = n0 + wn * 32 + nt * 8 + tg * 2;
            float2 v0 = {acc[mt][nt][0] + bb0, acc[mt][nt][1] + bb0};
            float2 v1 = {acc[mt][nt][2] + bb1, acc[mt][nt][3] + bb1};
            *(float2*)&Y[(size_t)mrow * P + col] = v0;
            *(float2*)&Y[(size_t)(mrow + 8) * P + col] = v1;
        }
    }
}

// ---------------------------------------------------------------------------
// 2x downsample (64x64 -> 32x32): exact 2x2 mean
// ---------------------------------------------------------------------------
__global__ void down2x_k(const float* __restrict__ src, float* __restrict__ dst,
                         int total) {
    int idx = blockIdx.x * blockDim.x + threadIdx.x;
    if (idx >= total) return;
    int x = idx & 31, y = (idx >> 5) & 31, c = idx >> 10;
    const float* s = src + ((size_t)c << 12) + (y << 7) + (x << 1);
    float2 a0 = *(const float2*)s;
    float2 a1 = *(const float2*)(s + 64);
    dst[idx] = 0.25f * ((a0.x + a0.y) + (a1.x + a1.y));
}

// ---------------------------------------------------------------------------
extern "C" void kernel_launch(void* const* d_in, const int* in_sizes, int n_in,
                              void* d_out, int out_size) {
    const float* high = (const float*)d_in[0];
    const float* low  = (const float*)d_in[1];
    const float* qhw = (const float*)d_in[2];  const float* qhb = (const float*)d_in[3];
    const float* khw = (const float*)d_in[4];  const float* khb = (const float*)d_in[5];
    const float* vhw = (const float*)d_in[6];  const float* vhb = (const float*)d_in[7];
    const float* qlw = (const float*)d_in[8];  const float* qlb = (const float*)d_in[9];
    const float* klw = (const float*)d_in[10]; const float* klb = (const float*)d_in[11];
    const float* vlw = (const float*)d_in[12]; const float* vlb = (const float*)d_in[13];
    const float* ohw = (const float*)d_in[14]; const float* ohb = (const float*)d_in[15];
    const float* olw = (const float*)d_in[16]; const float* olb = (const float*)d_in[17];
    float* out = (float*)d_out;

    float* scr = nullptr;
    cudaGetSymbolAddress((void**)&scr, g_scratch);
    float* qh  = scr + OFF_QH;
    float* ah  = scr + OFF_AH;
    float* kls = scr + OFF_KLS;
    float* vls = scr + OFF_VLS;
    float* ql  = scr + OFF_QL;
    float* kh  = scr + OFF_KH;
    float* vh  = scr + OFF_VH;
    float* hd  = scr + OFF_HD;
    float* al  = scr + OFF_AL;

    // 1) downsample high 64->32
    down2x_k<<<(B * 128 * 1024 + 255) / 256, 256>>>(high, hd, B * 128 * 1024);

    // 2) ALL pre-attention convs in one launch (288 CTAs x B)
    {
        ConvBatch cb;
        cb.d[0] = {low, klw, klb, kls, 256, 1024, 16, 0,   256 * 1024, 256 * 1024};
        cb.d[1] = {low, vlw, vlb, vls, 256, 1024, 16, 32,  256 * 1024, 256 * 1024};
        cb.d[2] = {low, qlw, qlb, ql,  256, 1024, 16, 64,  256 * 1024, 256 * 1024};
        cb.d[3] = {hd, khw, khb, kh,   128, 1024, 16, 96,  128 * 1024, 256 * 1024};
        cb.d[4] = {hd, vhw, vhb, vh,   128, 1024, 16, 128, 128 * 1024, 256 * 1024};
        cb.d[5] = {high, qhw, qhb, qh, 128, 4096, 64, 160, 128 * 4096, 256 * 4096};
        cb.nd = 6;
        conv_mma_k<<<dim3(288, 1, B), 256>>>(cb);
    }

    // 3) bf16 KV planes (fused upsample + pack)
    prep_kv_k<<<10240, 256>>>();

    // 4) merged attention (high 512 + low 128 CTAs), 8 warps/CTA
    attn2_k<<<640, 256>>>(qh, ah, ql, al);

    // 5) both output projections in one launch (96 CTAs x B)
    {
        ConvBatch cb;
        cb.d[0] = {ah, ohw, ohb, out, 256, 4096, 64, 0, 256 * 4096, 128 * 4096};
        cb.d[1] = {al, olw, olb, out + (size_t)B * 128 * 4096,
                   256, 1024, 16, 64, 256 * 1024, 256 * 1024};
        cb.nd = 2;
        conv_mma_k<<<dim3(96, 1, B), 256>>>(cb);
    }
}

// round 12
// speedup vs baseline: 8.1681x; 1.0645x over previous
#include <cuda_runtime.h>
#include <cuda_bf16.h>
#include <cstdint>
#include <math.h>

// ---------------------------------------------------------------------------
// CrossScaleAttention  (B=2, hidden=256, heads=8, head_dim=32)
// R12: softmax exp via ex2.approx.f16x2 (half the MUFU ops, P born packed),
//      P.V MMA in f16 kind (V planes f16 -> better precision than bf16),
//      row-sum l computed by an extra MMA against an all-ones B fragment
//      (kills per-j FADDs and the final shuffle reduce).
// ---------------------------------------------------------------------------

#define B 2
#define HID 256
#define NHEAD 8
#define HD 32
#define SCALE 0.17677669529663687f
#define QSCALE (SCALE * 1.4426950408889634f)   // fold log2(e): p = ex2(S)
#define KT 64
#define ONES_F16X2 0x3C003C00u

// ---------------- fp32 scratch ----------------
#define OFF_QH   0UL                 // [2,256,4096]
#define OFF_AH   2097152UL           // [2,256,4096]
#define OFF_KLS  4194304UL           // [2,256,1024]
#define OFF_VLS  4718592UL
#define OFF_QL   5242880UL
#define OFF_KH   5767168UL
#define OFF_VH   6291456UL
#define OFF_HD   6815744UL           // [2,128,1024]
#define OFF_AL   7077888UL           // [2,256,1024]
#define SCRATCH_FLOATS 7602176UL
__device__ float g_scratch[SCRATCH_FLOATS];

// ---------------- bf16/f16 KV planes (u32 = 2 packed) ----------------
#define OKH_H 0UL
#define OVH_H 1048576UL
#define OKH_L 2097152UL
#define OVH_L 2359296UL
#define KVU_TOTAL 2621440UL
__device__ uint32_t g_kvu[KVU_TOTAL];

// ---------------- helpers ----------------
__device__ __forceinline__ uint32_t pack2rn(float f0, float f1) {   // bf16x2
    uint32_t r;
    asm("cvt.rn.bf16x2.f32 %0, %1, %2;" : "=r"(r) : "f"(f1), "f"(f0));
    return r;
}
__device__ __forceinline__ uint32_t packf16(float f0, float f1) {   // f16x2
    uint32_t r;
    asm("cvt.rn.f16x2.f32 %0, %1, %2;" : "=r"(r) : "f"(f1), "f"(f0));
    return r;
}
__device__ __forceinline__ uint32_t ex2h2(uint32_t h2) {            // exp2 both halves
    uint32_t r;
    asm("ex2.approx.f16x2 %0, %1;" : "=r"(r) : "r"(h2));
    return r;
}
__device__ __forceinline__ void split2(float f0, float f1, uint32_t& hi, uint32_t& lo) {
    asm("cvt.rn.bf16x2.f32 %0, %1, %2;" : "=r"(hi) : "f"(f1), "f"(f0));
    float h0 = __uint_as_float(hi << 16);
    float h1 = __uint_as_float(hi & 0xFFFF0000u);
    float r0 = f0 - h0, r1 = f1 - h1;
    asm("cvt.rn.bf16x2.f32 %0, %1, %2;" : "=r"(lo) : "f"(r1), "f"(r0));
}

__device__ __forceinline__ void mma_bf16(float* c, const uint32_t* a,
                                         uint32_t b0, uint32_t b1) {
    asm volatile(
        "mma.sync.aligned.m16n8k16.row.col.f32.bf16.bf16.f32 "
        "{%0,%1,%2,%3}, {%4,%5,%6,%7}, {%8,%9}, {%0,%1,%2,%3};"
        : "+f"(c[0]), "+f"(c[1]), "+f"(c[2]), "+f"(c[3])
        : "r"(a[0]), "r"(a[1]), "r"(a[2]), "r"(a[3]), "r"(b0), "r"(b1));
}
__device__ __forceinline__ void mma_f16(float* c, const uint32_t* a,
                                        uint32_t b0, uint32_t b1) {
    asm volatile(
        "mma.sync.aligned.m16n8k16.row.col.f32.f16.f16.f32 "
        "{%0,%1,%2,%3}, {%4,%5,%6,%7}, {%8,%9}, {%0,%1,%2,%3};"
        : "+f"(c[0]), "+f"(c[1]), "+f"(c[2]), "+f"(c[3])
        : "r"(a[0]), "r"(a[1]), "r"(a[2]), "r"(a[3]), "r"(b0), "r"(b1));
}

__device__ __forceinline__ void ldsm_x4(uint32_t* r, uint32_t addr) {
    asm volatile("ldmatrix.sync.aligned.m8n8.x4.shared.b16 {%0,%1,%2,%3}, [%4];"
        : "=r"(r[0]), "=r"(r[1]), "=r"(r[2]), "=r"(r[3]) : "r"(addr));
}

__device__ __forceinline__ uint32_t smem_u32p(const void* p) {
    uint32_t a;
    asm("{ .reg .u64 t; cvta.to.shared.u64 t, %1; cvt.u32.u64 %0, t; }" : "=r"(a) : "l"(p));
    return a;
}
__device__ __forceinline__ void cp16(uint32_t saddr, const void* g) {
    asm volatile("cp.async.ca.shared.global [%0], [%1], 16;" :: "r"(saddr), "l"(g) : "memory");
}
#define CP_COMMIT() asm volatile("cp.async.commit_group;" ::: "memory")
#define CP_WAIT0()  asm volatile("cp.async.wait_group 0;" ::: "memory")

// bilinear 2x upsample sample (32x32 -> 64x64, align_corners=False)
__device__ __forceinline__ float up_sample(const float* __restrict__ s, int y, int x) {
    int y0 = max((y - 1) >> 1, 0), y1 = min((y + 1) >> 1, 31);
    int x0 = max((x - 1) >> 1, 0), x1 = min((x + 1) >> 1, 31);
    float wy = (y & 1) ? 0.25f : 0.75f;
    float wx = (x & 1) ? 0.25f : 0.75f;
    float v00 = s[(y0 << 5) + x0], v01 = s[(y0 << 5) + x1];
    float v10 = s[(y1 << 5) + x0], v11 = s[(y1 << 5) + x1];
    float top = v00 + wx * (v01 - v00);
    float bot = v10 + wx * (v11 - v10);
    return top + wy * (bot - top);
}

// ---------------------------------------------------------------------------
// prep_kv: K planes bf16, V planes f16.
// ---------------------------------------------------------------------------
__global__ __launch_bounds__(256) void prep_kv_k() {
    const float* kls = g_scratch + OFF_KLS;
    const float* vls = g_scratch + OFF_VLS;
    const float* kh  = g_scratch + OFF_KH;
    const float* vh  = g_scratch + OFF_VH;
    int gid = blockIdx.x * 256 + threadIdx.x;

    if (gid < 1048576) {                 // high K: [bh][key 4096][dp 16] bf16
        int dp = gid & 15, key = (gid >> 4) & 4095, bh = gid >> 16;
        int y = key >> 6, x = key & 63;
        const float* s = kls + (((size_t)(bh >> 3) * 256) + (bh & 7) * 32 + 2 * dp) * 1024;
        g_kvu[OKH_H + gid] = pack2rn(up_sample(s, y, x), up_sample(s + 1024, y, x));
    } else if (gid < 2097152) {          // high V: [bh][d 32][kp 2048] f16
        int g2 = gid - 1048576;
        int kp = g2 & 2047, d = (g2 >> 11) & 31, bh = g2 >> 16;
        int key = kp << 1;
        int y = key >> 6, x = key & 63;
        const float* s = vls + (((size_t)(bh >> 3) * 256) + (bh & 7) * 32 + d) * 1024;
        g_kvu[OVH_H + g2] = packf16(up_sample(s, y, x), up_sample(s, y, x + 1));
    } else if (gid < 2359296) {          // low K: [bh][key 1024][dp 16] bf16
        int g3 = gid - 2097152;
        int dp = g3 & 15, key = (g3 >> 4) & 1023, bh = g3 >> 14;
        const float* s = kh + (((size_t)(bh >> 3) * 256) + (bh & 7) * 32 + 2 * dp) * 1024 + key;
        g_kvu[OKH_L + g3] = pack2rn(s[0], s[1024]);
    } else if (gid < 2621440) {          // low V: [bh][d 32][kp 512] f16
        int g4 = gid - 2359296;
        int kp = g4 & 511, d = (g4 >> 9) & 31, bh = g4 >> 14;
        const float* s = vh + (((size_t)(bh >> 3) * 256) + (bh & 7) * 32 + d) * 1024 + 2 * kp;
        g_kvu[OVH_L + g4] = packf16(s[0], s[1]);
    }
}

// ---------------------------------------------------------------------------
// Merged flash attention. Q/K bf16, P/V f16, fp32 accum; exp via ex2.f16x2;
// l via all-ones MMA. block 256 = 8 warps x 16 query rows.
// ---------------------------------------------------------------------------
__global__ __launch_bounds__(256) void attn2_k(const float* __restrict__ qH,
                                               float* __restrict__ oH,
                                               const float* __restrict__ qL,
                                               float* __restrict__ oL) {
    __shared__ __align__(16) uint32_t Ksm[2][64 * 20];
    __shared__ __align__(16) uint32_t Vsm[2][32 * 36];

    int tid = threadIdx.x;
    int w = tid >> 5, lane = tid & 31;
    int g = lane >> 2, tg = lane & 3;

    int cta = blockIdx.x;
    const float* q;
    float* out;
    const uint32_t *Kg, *Vg;
    int N, q0, bh;
    if (cta < 512) {
        N = 4096; bh = cta >> 5; q0 = (cta & 31) << 7;
        q = qH; out = oH;
        Kg = g_kvu + OKH_H + ((size_t)bh << 16);
        Vg = g_kvu + OVH_H + ((size_t)bh << 16);
    } else {
        int idx = cta - 512;
        N = 1024; bh = idx >> 3; q0 = (idx & 7) << 7;
        q = qL; out = oL;
        Kg = g_kvu + OKH_L + ((size_t)bh << 14);
        Vg = g_kvu + OVH_L + ((size_t)bh << 14);
    }
    size_t base = (size_t)32 * bh * N;
    int halfN = N >> 1;

    uint32_t ks0 = smem_u32p(&Ksm[0][0]);
    uint32_t vs0 = smem_u32p(&Vsm[0][0]);

    uint32_t kfrag = ks0 + (lane & 7) * 80 + (lane >> 3) * 16;
    uint32_t vfrag = vs0 + ((lane >> 4) * 8 + (lane & 7)) * 144 + ((lane >> 3) & 1) * 16;

    // ---- Q fragments (bf16, QSCALE folded) ----
    uint32_t qf[2][4];
    #pragma unroll
    for (int kt = 0; kt < 2; kt++)
        #pragma unroll
        for (int r = 0; r < 4; r++) {
            int row = q0 + w * 16 + g + (r & 1) * 8;
            int d0 = kt * 16 + tg * 2 + (r >> 1) * 8;
            float f0 = q[base + (size_t)d0 * N + row] * QSCALE;
            float f1 = q[base + (size_t)(d0 + 1) * N + row] * QSCALE;
            qf[kt][r] = pack2rn(f0, f1);
        }

    auto load_tile = [&](int buf, int kv0) {
        int kp0 = kv0 >> 1;
        {
            int key = tid >> 2, c4 = (tid & 3) << 2;
            cp16(ks0 + (uint32_t)(buf * 1280 + key * 20 + c4) * 4,
                 Kg + (size_t)(kv0 + key) * 16 + c4);
        }
        {
            int d = tid >> 3, c = (tid & 7) << 2;
            cp16(vs0 + (uint32_t)(buf * 1152 + d * 36 + c) * 4,
                 Vg + (size_t)d * halfN + kp0 + c);
        }
        CP_COMMIT();
    };

    float O[4][4] = {};
    float lc[4] = {};

    load_tile(0, 0);
    CP_WAIT0();
    __syncthreads();

    int T = N / KT;
    for (int it = 0; it < T; it++) {
        int buf = it & 1;
        if (it + 1 < T) load_tile(buf ^ 1, (it + 1) * KT);

        uint32_t kbase = buf * 5120;     // bytes
        uint32_t vbase = buf * 4608;     // bytes

        uint32_t pah[4];
        #pragma unroll
        for (int j = 0; j < 8; j++) {
            uint32_t kb[4];
            ldsm_x4(kb, kfrag + kbase + j * 640);
            float S[4] = {0.f, 0.f, 0.f, 0.f};
            mma_bf16(S, qf[0], kb[0], kb[1]);
            mma_bf16(S, qf[1], kb[2], kb[3]);

            int odd = j & 1;
            pah[odd * 2]     = ex2h2(packf16(S[0], S[1]));
            pah[odd * 2 + 1] = ex2h2(packf16(S[2], S[3]));
            if (odd) {
                mma_f16(lc, pah, ONES_F16X2, ONES_F16X2);   // row sums
                uint32_t va = vfrag + vbase + (uint32_t)(j >> 1) * 32;
                uint32_t vb[4];
                ldsm_x4(vb, va);
                mma_f16(O[0], pah, vb[0], vb[1]);
                mma_f16(O[1], pah, vb[2], vb[3]);
                ldsm_x4(vb, va + 2304);
                mma_f16(O[2], pah, vb[0], vb[1]);
                mma_f16(O[3], pah, vb[2], vb[3]);
            }
        }

        if (it + 1 < T) CP_WAIT0();
        __syncthreads();
    }

    // lc[0] = row-g sum (all lanes identical), lc[2] = row-(g+8) sum
    float inv0 = 1.0f / lc[0];
    float inv1 = 1.0f / lc[2];

    int row0 = q0 + w * 16 + g;
    #pragma unroll
    for (int jd = 0; jd < 4; jd++) {
        int d0 = jd * 8 + tg * 2;
        out[base + (size_t)d0 * N + row0]           = O[jd][0] * inv0;
        out[base + (size_t)(d0 + 1) * N + row0]     = O[jd][1] * inv0;
        out[base + (size_t)d0 * N + row0 + 8]       = O[jd][2] * inv1;
        out[base + (size_t)(d0 + 1) * N + row0 + 8] = O[jd][3] * inv1;
    }
}

// ---------------------------------------------------------------------------
// Batched conv1x1 (proven): up to 6 GEMM outputs per launch.
// bf16 3-term split, BM=128, BN=64, BK=16, double-buffered.
// ---------------------------------------------------------------------------
struct ConvDesc {
    const float* x;
    const float* w;
    const float* bias;
    float* y;
    int C, P, nblocks, cta0, xbs, ybs;
};
struct ConvBatch {
    ConvDesc d[6];
    int nd;
};

__global__ __launch_bounds__(256) void conv_mma_k(ConvBatch args) {
    __shared__ uint32_t smW[2][2][1536];
    __shared__ uint32_t smX[2][2][768];

    int bx = blockIdx.x;
    int u = 0;
    #pragma unroll
    for (int i = 1; i < 6; i++)
        if (i < args.nd && bx >= args.d[i].cta0) u = i;
    const ConvDesc& D = args.d[u];
    int rem = bx - D.cta0;
    int m0 = (rem / D.nblocks) << 7;
    int n0 = (rem % D.nblocks) << 6;
    int b = blockIdx.z;
    int C = D.C, P = D.P;
    const float* X = D.x + (size_t)b * D.xbs;
    const float* W = D.w;
    const float* Bi = D.bias;
    float* Y = D.y + (size_t)b * D.ybs;
    int nch = C >> 4;

    int tid = threadIdx.x;
    int w = tid >> 5, lane = tid & 31, g = lane >> 2, tg = lane & 3;
    int wm = w >> 1, wn = w & 1;

    auto load = [&](int ch, int buf) {
        int c0 = ch << 4;
        {
            int m = tid >> 1, half = tid & 1;
            const float4* src = reinterpret_cast<const float4*>(
                W + (size_t)(m0 + m) * C + c0 + half * 8);
            float4 f0 = src[0], f1 = src[1];
            uint32_t* dh = &smW[buf][0][m * 12 + half * 4];
            uint32_t* dl = &smW[buf][1][m * 12 + half * 4];
            uint32_t h, l;
            split2(f0.x, f0.y, h, l); dh[0] = h; dl[0] = l;
            split2(f0.z, f0.w, h, l); dh[1] = h; dl[1] = l;
            split2(f1.x, f1.y, h, l); dh[2] = h; dl[2] = l;
            split2(f1.z, f1.w, h, l); dh[3] = h; dl[3] = l;
        }
        #pragma unroll
        for (int i = 0; i < 2; i++) {
            int idx = tid + (i << 8);
            int kp = idx >> 6, n = idx & 63;
            float f0 = X[(size_t)(c0 + 2 * kp) * P + n0 + n];
            float f1 = X[(size_t)(c0 + 2 * kp + 1) * P + n0 + n];
            uint32_t h, l;
            split2(f0, f1, h, l);
            smX[buf][0][n * 12 + kp] = h;
            smX[buf][1][n * 12 + kp] = l;
        }
    };

    float acc[2][4][4] = {};

    load(0, 0);
    __syncthreads();

    for (int ch = 0; ch < nch; ch++) {
        int buf = ch & 1;
        if (ch + 1 < nch) load(ch + 1, buf ^ 1);

        uint32_t ah[2][4], al[2][4];
        #pragma unroll
        for (int mt = 0; mt < 2; mt++)
            #pragma unroll
            for (int r = 0; r < 4; r++) {
                int row = wm * 32 + mt * 16 + g + ((r & 1) << 3);
                int kp = tg + ((r >> 1) << 2);
                ah[mt][r] = smW[buf][0][row * 12 + kp];
                al[mt][r] = smW[buf][1][row * 12 + kp];
            }
        #pragma unroll
        for (int nt = 0; nt < 4; nt++) {
            int nrow = wn * 32 + nt * 8 + g;
            uint32_t bh0 = smX[buf][0][nrow * 12 + tg];
            uint32_t bh1 = smX[buf][0][nrow * 12 + tg + 4];
            uint32_t bl0 = smX[buf][1][nrow * 12 + tg];
            uint32_t bl1 = smX[buf][1][nrow * 12 + tg + 4];
            #pragma unroll
            for (int mt = 0; mt < 2; mt++) {
                mma_bf16(acc[mt][nt], ah[mt], bh0, bh1);
                mma_bf16(acc[mt][nt], ah[mt], bl0, bl1);
                mma_bf16(acc[mt][nt], al[mt], bh0, bh1);
            }
        }
        __syncthreads();
    }

    #pragma unroll
    for (int mt = 0; mt < 2; mt++) {
        int mrow = m0 + wm * 32 + mt * 16 + g;
        float bb0 = Bi[mrow], bb1 = Bi[mrow + 8];
        #pragma unroll
        for (int nt = 0; nt < 4; nt++) {
            int col = n0 + wn * 32 + nt * 8 + tg * 2;
            float2 v0 = {acc[mt][nt][0] + bb0, acc[mt][nt][1] + bb0};
            float2 v1 = {acc[mt][nt][2] + bb1, acc[mt][nt][3] + bb1};
            *(float2*)&Y[(size_t)mrow * P + col] = v0;
            *(float2*)&Y[(size_t)(mrow + 8) * P + col] = v1;
        }
    }
}

// ---------------------------------------------------------------------------
// 2x downsample (64x64 -> 32x32): exact 2x2 mean
// ---------------------------------------------------------------------------
__global__ void down2x_k(const float* __restrict__ src, float* __restrict__ dst,
                         int total) {
    int idx = blockIdx.x * blockDim.x + threadIdx.x;
    if (idx >= total) return;
    int x = idx & 31, y = (idx >> 5) & 31, c = idx >> 10;
    const float* s = src + ((size_t)c << 12) + (y << 7) + (x << 1);
    float2 a0 = *(const float2*)s;
    float2 a1 = *(const float2*)(s + 64);
    dst[idx] = 0.25f * ((a0.x + a0.y) + (a1.x + a1.y));
}

// ---------------------------------------------------------------------------
extern "C" void kernel_launch(void* const* d_in, const int* in_sizes, int n_in,
                              void* d_out, int out_size) {
    const float* high = (const float*)d_in[0];
    const float* low  = (const float*)d_in[1];
    const float* qhw = (const float*)d_in[2];  const float* qhb = (const float*)d_in[3];
    const float* khw = (const float*)d_in[4];  const float* khb = (const float*)d_in[5];
    const float* vhw = (const float*)d_in[6];  const float* vhb = (const float*)d_in[7];
    const float* qlw = (const float*)d_in[8];  const float* qlb = (const float*)d_in[9];
    const float* klw = (const float*)d_in[10]; const float* klb = (const float*)d_in[11];
    const float* vlw = (const float*)d_in[12]; const float* vlb = (const float*)d_in[13];
    const float* ohw = (const float*)d_in[14]; const float* ohb = (const float*)d_in[15];
    const float* olw = (const float*)d_in[16]; const float* olb = (const float*)d_in[17];
    float* out = (float*)d_out;

    float* scr = nullptr;
    cudaGetSymbolAddress((void**)&scr, g_scratch);
    float* qh  = scr + OFF_QH;
    float* ah  = scr + OFF_AH;
    float* kls = scr + OFF_KLS;
    float* vls = scr + OFF_VLS;
    float* ql  = scr + OFF_QL;
    float* kh  = scr + OFF_KH;
    float* vh  = scr + OFF_VH;
    float* hd  = scr + OFF_HD;
    float* al  = scr + OFF_AL;

    // 1) downsample high 64->32
    down2x_k<<<(B * 128 * 1024 + 255) / 256, 256>>>(high, hd, B * 128 * 1024);

    // 2) ALL pre-attention convs in one launch (288 CTAs x B)
    {
        ConvBatch cb;
        cb.d[0] = {low, klw, klb, kls, 256, 1024, 16, 0,   256 * 1024, 256 * 1024};
        cb.d[1] = {low, vlw, vlb, vls, 256, 1024, 16, 32,  256 * 1024, 256 * 1024};
        cb.d[2] = {low, qlw, qlb, ql,  256, 1024, 16, 64,  256 * 1024, 256 * 1024};
        cb.d[3] = {hd, khw, khb, kh,   128, 1024, 16, 96,  128 * 1024, 256 * 1024};
        cb.d[4] = {hd, vhw, vhb, vh,   128, 1024, 16, 128, 128 * 1024, 256 * 1024};
        cb.d[5] = {high, qhw, qhb, qh, 128, 4096, 64, 160, 128 * 4096, 256 * 4096};
        cb.nd = 6;
        conv_mma_k<<<dim3(288, 1, B), 256>>>(cb);
    }

    // 3) KV planes (K bf16, V f16; fused upsample + pack)
    prep_kv_k<<<10240, 256>>>();

    // 4) merged attention (high 512 + low 128 CTAs), 8 warps/CTA
    attn2_k<<<640, 256>>>(qh, ah, ql, al);

    // 5) both output projections in one launch (96 CTAs x B)
    {
        ConvBatch cb;
        cb.d[0] = {ah, ohw, ohb, out, 256, 4096, 64, 0, 256 * 4096, 128 * 4096};
        cb.d[1] = {al, olw, olb, out + (size_t)B * 128 * 4096,
                   256, 1024, 16, 64, 256 * 1024, 256 * 1024};
        cb.nd = 2;
        conv_mma_k<<<dim3(96, 1, B), 256>>>(cb);
    }
}

// round 13
// speedup vs baseline: 8.4623x; 1.0360x over previous
#include <cuda_runtime.h>
#include <cuda_bf16.h>
#include <cstdint>
#include <math.h>

// ---------------------------------------------------------------------------
// CrossScaleAttention  (B=2, hidden=256, heads=8, head_dim=32)
// R13: attention back to 32 q-rows/warp (4 warps, block 128) with j-outer /
//      mt-inner loop so each ldmatrix K/V fragment is reused by both m-tiles
//      -> smem read traffic (the measured L1 bottleneck) halves.
//      Arithmetic identical to R12 (Q/K bf16, P/V f16, l via ones-MMA).
// ---------------------------------------------------------------------------

#define B 2
#define HID 256
#define NHEAD 8
#define HD 32
#define SCALE 0.17677669529663687f
#define QSCALE (SCALE * 1.4426950408889634f)   // fold log2(e): p = ex2(S)
#define KT 64
#define ONES_F16X2 0x3C003C00u

// ---------------- fp32 scratch ----------------
#define OFF_QH   0UL                 // [2,256,4096]
#define OFF_AH   2097152UL           // [2,256,4096]
#define OFF_KLS  4194304UL           // [2,256,1024]
#define OFF_VLS  4718592UL
#define OFF_QL   5242880UL
#define OFF_KH   5767168UL
#define OFF_VH   6291456UL
#define OFF_HD   6815744UL           // [2,128,1024]
#define OFF_AL   7077888UL           // [2,256,1024]
#define SCRATCH_FLOATS 7602176UL
__device__ float g_scratch[SCRATCH_FLOATS];

// ---------------- bf16/f16 KV planes (u32 = 2 packed) ----------------
#define OKH_H 0UL
#define OVH_H 1048576UL
#define OKH_L 2097152UL
#define OVH_L 2359296UL
#define KVU_TOTAL 2621440UL
__device__ uint32_t g_kvu[KVU_TOTAL];

// ---------------- helpers ----------------
__device__ __forceinline__ uint32_t pack2rn(float f0, float f1) {   // bf16x2
    uint32_t r;
    asm("cvt.rn.bf16x2.f32 %0, %1, %2;" : "=r"(r) : "f"(f1), "f"(f0));
    return r;
}
__device__ __forceinline__ uint32_t packf16(float f0, float f1) {   // f16x2
    uint32_t r;
    asm("cvt.rn.f16x2.f32 %0, %1, %2;" : "=r"(r) : "f"(f1), "f"(f0));
    return r;
}
__device__ __forceinline__ uint32_t ex2h2(uint32_t h2) {            // exp2 both halves
    uint32_t r;
    asm("ex2.approx.f16x2 %0, %1;" : "=r"(r) : "r"(h2));
    return r;
}
__device__ __forceinline__ void split2(float f0, float f1, uint32_t& hi, uint32_t& lo) {
    asm("cvt.rn.bf16x2.f32 %0, %1, %2;" : "=r"(hi) : "f"(f1), "f"(f0));
    float h0 = __uint_as_float(hi << 16);
    float h1 = __uint_as_float(hi & 0xFFFF0000u);
    float r0 = f0 - h0, r1 = f1 - h1;
    asm("cvt.rn.bf16x2.f32 %0, %1, %2;" : "=r"(lo) : "f"(r1), "f"(r0));
}

__device__ __forceinline__ void mma_bf16(float* c, const uint32_t* a,
                                         uint32_t b0, uint32_t b1) {
    asm volatile(
        "mma.sync.aligned.m16n8k16.row.col.f32.bf16.bf16.f32 "
        "{%0,%1,%2,%3}, {%4,%5,%6,%7}, {%8,%9}, {%0,%1,%2,%3};"
        : "+f"(c[0]), "+f"(c[1]), "+f"(c[2]), "+f"(c[3])
        : "r"(a[0]), "r"(a[1]), "r"(a[2]), "r"(a[3]), "r"(b0), "r"(b1));
}
__device__ __forceinline__ void mma_f16(float* c, const uint32_t* a,
                                        uint32_t b0, uint32_t b1) {
    asm volatile(
        "mma.sync.aligned.m16n8k16.row.col.f32.f16.f16.f32 "
        "{%0,%1,%2,%3}, {%4,%5,%6,%7}, {%8,%9}, {%0,%1,%2,%3};"
        : "+f"(c[0]), "+f"(c[1]), "+f"(c[2]), "+f"(c[3])
        : "r"(a[0]), "r"(a[1]), "r"(a[2]), "r"(a[3]), "r"(b0), "r"(b1));
}

__device__ __forceinline__ void ldsm_x4(uint32_t* r, uint32_t addr) {
    asm volatile("ldmatrix.sync.aligned.m8n8.x4.shared.b16 {%0,%1,%2,%3}, [%4];"
        : "=r"(r[0]), "=r"(r[1]), "=r"(r[2]), "=r"(r[3]) : "r"(addr));
}

__device__ __forceinline__ uint32_t smem_u32p(const void* p) {
    uint32_t a;
    asm("{ .reg .u64 t; cvta.to.shared.u64 t, %1; cvt.u32.u64 %0, t; }" : "=r"(a) : "l"(p));
    return a;
}
__device__ __forceinline__ void cp16(uint32_t saddr, const void* g) {
    asm volatile("cp.async.ca.shared.global [%0], [%1], 16;" :: "r"(saddr), "l"(g) : "memory");
}
#define CP_COMMIT() asm volatile("cp.async.commit_group;" ::: "memory")
#define CP_WAIT0()  asm volatile("cp.async.wait_group 0;" ::: "memory")

// bilinear 2x upsample sample (32x32 -> 64x64, align_corners=False)
__device__ __forceinline__ float up_sample(const float* __restrict__ s, int y, int x) {
    int y0 = max((y - 1) >> 1, 0), y1 = min((y + 1) >> 1, 31);
    int x0 = max((x - 1) >> 1, 0), x1 = min((x + 1) >> 1, 31);
    float wy = (y & 1) ? 0.25f : 0.75f;
    float wx = (x & 1) ? 0.25f : 0.75f;
    float v00 = s[(y0 << 5) + x0], v01 = s[(y0 << 5) + x1];
    float v10 = s[(y1 << 5) + x0], v11 = s[(y1 << 5) + x1];
    float top = v00 + wx * (v01 - v00);
    float bot = v10 + wx * (v11 - v10);
    return top + wy * (bot - top);
}

// ---------------------------------------------------------------------------
// prep_kv: K planes bf16, V planes f16 (proven).
// ---------------------------------------------------------------------------
__global__ __launch_bounds__(256) void prep_kv_k() {
    const float* kls = g_scratch + OFF_KLS;
    const float* vls = g_scratch + OFF_VLS;
    const float* kh  = g_scratch + OFF_KH;
    const float* vh  = g_scratch + OFF_VH;
    int gid = blockIdx.x * 256 + threadIdx.x;

    if (gid < 1048576) {                 // high K: [bh][key 4096][dp 16] bf16
        int dp = gid & 15, key = (gid >> 4) & 4095, bh = gid >> 16;
        int y = key >> 6, x = key & 63;
        const float* s = kls + (((size_t)(bh >> 3) * 256) + (bh & 7) * 32 + 2 * dp) * 1024;
        g_kvu[OKH_H + gid] = pack2rn(up_sample(s, y, x), up_sample(s + 1024, y, x));
    } else if (gid < 2097152) {          // high V: [bh][d 32][kp 2048] f16
        int g2 = gid - 1048576;
        int kp = g2 & 2047, d = (g2 >> 11) & 31, bh = g2 >> 16;
        int key = kp << 1;
        int y = key >> 6, x = key & 63;
        const float* s = vls + (((size_t)(bh >> 3) * 256) + (bh & 7) * 32 + d) * 1024;
        g_kvu[OVH_H + g2] = packf16(up_sample(s, y, x), up_sample(s, y, x + 1));
    } else if (gid < 2359296) {          // low K: [bh][key 1024][dp 16] bf16
        int g3 = gid - 2097152;
        int dp = g3 & 15, key = (g3 >> 4) & 1023, bh = g3 >> 14;
        const float* s = kh + (((size_t)(bh >> 3) * 256) + (bh & 7) * 32 + 2 * dp) * 1024 + key;
        g_kvu[OKH_L + g3] = pack2rn(s[0], s[1024]);
    } else if (gid < 2621440) {          // low V: [bh][d 32][kp 512] f16
        int g4 = gid - 2359296;
        int kp = g4 & 511, d = (g4 >> 9) & 31, bh = g4 >> 14;
        const float* s = vh + (((size_t)(bh >> 3) * 256) + (bh & 7) * 32 + d) * 1024 + 2 * kp;
        g_kvu[OVH_L + g4] = packf16(s[0], s[1]);
    }
}

// ---------------------------------------------------------------------------
// Merged flash attention. Q/K bf16, P/V f16, fp32 accum; exp via ex2.f16x2;
// l via all-ones MMA. block 128 = 4 warps x 32 query rows; K/V fragments
// loaded once per j and shared across both m-tiles.
// ---------------------------------------------------------------------------
__global__ __launch_bounds__(128) void attn2_k(const float* __restrict__ qH,
                                               float* __restrict__ oH,
                                               const float* __restrict__ qL,
                                               float* __restrict__ oL) {
    __shared__ __align__(16) uint32_t Ksm[2][64 * 20];
    __shared__ __align__(16) uint32_t Vsm[2][32 * 36];

    int tid = threadIdx.x;
    int w = tid >> 5, lane = tid & 31;
    int g = lane >> 2, tg = lane & 3;

    int cta = blockIdx.x;
    const float* q;
    float* out;
    const uint32_t *Kg, *Vg;
    int N, q0, bh;
    if (cta < 512) {
        N = 4096; bh = cta >> 5; q0 = (cta & 31) << 7;
        q = qH; out = oH;
        Kg = g_kvu + OKH_H + ((size_t)bh << 16);
        Vg = g_kvu + OVH_H + ((size_t)bh << 16);
    } else {
        int idx = cta - 512;
        N = 1024; bh = idx >> 3; q0 = (idx & 7) << 7;
        q = qL; out = oL;
        Kg = g_kvu + OKH_L + ((size_t)bh << 14);
        Vg = g_kvu + OVH_L + ((size_t)bh << 14);
    }
    size_t base = (size_t)32 * bh * N;
    int halfN = N >> 1;

    uint32_t ks0 = smem_u32p(&Ksm[0][0]);
    uint32_t vs0 = smem_u32p(&Vsm[0][0]);

    uint32_t kfrag = ks0 + (lane & 7) * 80 + (lane >> 3) * 16;
    uint32_t vfrag = vs0 + ((lane >> 4) * 8 + (lane & 7)) * 144 + ((lane >> 3) & 1) * 16;

    // ---- Q fragments (bf16, QSCALE folded); warp covers rows q0+w*32..+31 ----
    uint32_t qf[2][2][4];
    #pragma unroll
    for (int mt = 0; mt < 2; mt++)
        #pragma unroll
        for (int kt = 0; kt < 2; kt++)
            #pragma unroll
            for (int r = 0; r < 4; r++) {
                int row = q0 + w * 32 + mt * 16 + g + (r & 1) * 8;
                int d0 = kt * 16 + tg * 2 + (r >> 1) * 8;
                float f0 = q[base + (size_t)d0 * N + row] * QSCALE;
                float f1 = q[base + (size_t)(d0 + 1) * N + row] * QSCALE;
                qf[mt][kt][r] = pack2rn(f0, f1);
            }

    auto load_tile = [&](int buf, int kv0) {
        int kp0 = kv0 >> 1;
        #pragma unroll
        for (int i = 0; i < 2; i++) {        // K: 256 x 16B, 2 per thread
            int id = tid + (i << 7);
            int key = id >> 2, c4 = (id & 3) << 2;
            cp16(ks0 + (uint32_t)(buf * 1280 + key * 20 + c4) * 4,
                 Kg + (size_t)(kv0 + key) * 16 + c4);
        }
        #pragma unroll
        for (int i = 0; i < 2; i++) {        // V: 256 x 16B, 2 per thread
            int id = tid + (i << 7);
            int d = id >> 3, c = (id & 7) << 2;
            cp16(vs0 + (uint32_t)(buf * 1152 + d * 36 + c) * 4,
                 Vg + (size_t)d * halfN + kp0 + c);
        }
        CP_COMMIT();
    };

    float O[2][4][4] = {};
    float lc[2][4] = {};

    load_tile(0, 0);
    CP_WAIT0();
    __syncthreads();

    int T = N / KT;
    for (int it = 0; it < T; it++) {
        int buf = it & 1;
        if (it + 1 < T) load_tile(buf ^ 1, (it + 1) * KT);

        uint32_t kbase = buf * 5120;     // bytes
        uint32_t vbase = buf * 4608;     // bytes

        uint32_t pah[2][4];
        #pragma unroll
        for (int j = 0; j < 8; j++) {
            uint32_t kb[4];
            ldsm_x4(kb, kfrag + kbase + j * 640);   // shared by both m-tiles
            int odd = j & 1;
            #pragma unroll
            for (int mt = 0; mt < 2; mt++) {
                float S[4] = {0.f, 0.f, 0.f, 0.f};
                mma_bf16(S, qf[mt][0], kb[0], kb[1]);
                mma_bf16(S, qf[mt][1], kb[2], kb[3]);
                pah[mt][odd * 2]     = ex2h2(packf16(S[0], S[1]));
                pah[mt][odd * 2 + 1] = ex2h2(packf16(S[2], S[3]));
            }
            if (odd) {
                uint32_t va = vfrag + vbase + (uint32_t)(j >> 1) * 32;
                uint32_t vb[4];
                ldsm_x4(vb, va);                    // jd 0,1 — shared by both mt
                mma_f16(lc[0], pah[0], ONES_F16X2, ONES_F16X2);
                mma_f16(lc[1], pah[1], ONES_F16X2, ONES_F16X2);
                mma_f16(O[0][0], pah[0], vb[0], vb[1]);
                mma_f16(O[0][1], pah[0], vb[2], vb[3]);
                mma_f16(O[1][0], pah[1], vb[0], vb[1]);
                mma_f16(O[1][1], pah[1], vb[2], vb[3]);
                ldsm_x4(vb, va + 2304);             // jd 2,3
                mma_f16(O[0][2], pah[0], vb[0], vb[1]);
                mma_f16(O[0][3], pah[0], vb[2], vb[3]);
                mma_f16(O[1][2], pah[1], vb[0], vb[1]);
                mma_f16(O[1][3], pah[1], vb[2], vb[3]);
            }
        }

        if (it + 1 < T) CP_WAIT0();
        __syncthreads();
    }

    #pragma unroll
    for (int mt = 0; mt < 2; mt++) {
        float inv0 = 1.0f / lc[mt][0];
        float inv1 = 1.0f / lc[mt][2];
        int row0 = q0 + w * 32 + mt * 16 + g;
        #pragma unroll
        for (int jd = 0; jd < 4; jd++) {
            int d0 = jd * 8 + tg * 2;
            out[base + (size_t)d0 * N + row0]           = O[mt][jd][0] * inv0;
            out[base + (size_t)(d0 + 1) * N + row0]     = O[mt][jd][1] * inv0;
            out[base + (size_t)d0 * N + row0 + 8]       = O[mt][jd][2] * inv1;
            out[base + (size_t)(d0 + 1) * N + row0 + 8] = O[mt][jd][3] * inv1;
        }
    }
}

// ---------------------------------------------------------------------------
// Batched conv1x1 (proven): up to 6 GEMM outputs per launch.
// bf16 3-term split, BM=128, BN=64, BK=16, double-buffered.
// ---------------------------------------------------------------------------
struct ConvDesc {
    const float* x;
    const float* w;
    const float* bias;
    float* y;
    int C, P, nblocks, cta0, xbs, ybs;
};
struct ConvBatch {
    ConvDesc d[6];
    int nd;
};

__global__ __launch_bounds__(256) void conv_mma_k(ConvBatch args) {
    __shared__ uint32_t smW[2][2][1536];
    __shared__ uint32_t smX[2][2][768];

    int bx = blockIdx.x;
    int u = 0;
    #pragma unroll
    for (int i = 1; i < 6; i++)
        if (i < args.nd && bx >= args.d[i].cta0) u = i;
    const ConvDesc& D = args.d[u];
    int rem = bx - D.cta0;
    int m0 = (rem / D.nblocks) << 7;
    int n0 = (rem % D.nblocks) << 6;
    int b = blockIdx.z;
    int C = D.C, P = D.P;
    const float* X = D.x + (size_t)b * D.xbs;
    const float* W = D.w;
    const float* Bi = D.bias;
    float* Y = D.y + (size_t)b * D.ybs;
    int nch = C >> 4;

    int tid = threadIdx.x;
    int w = tid >> 5, lane = tid & 31, g = lane >> 2, tg = lane & 3;
    int wm = w >> 1, wn = w & 1;

    auto load = [&](int ch, int buf) {
        int c0 = ch << 4;
        {
            int m = tid >> 1, half = tid & 1;
            const float4* src = reinterpret_cast<const float4*>(
                W + (size_t)(m0 + m) * C + c0 + half * 8);
            float4 f0 = src[0], f1 = src[1];
            uint32_t* dh = &smW[buf][0][m * 12 + half * 4];
            uint32_t* dl = &smW[buf][1][m * 12 + half * 4];
            uint32_t h, l;
            split2(f0.x, f0.y, h, l); dh[0] = h; dl[0] = l;
            split2(f0.z, f0.w, h, l); dh[1] = h; dl[1] = l;
            split2(f1.x, f1.y, h, l); dh[2] = h; dl[2] = l;
            split2(f1.z, f1.w, h, l); dh[3] = h; dl[3] = l;
        }
        #pragma unroll
        for (int i = 0; i < 2; i++) {
            int idx = tid + (i << 8);
            int kp = idx >> 6, n = idx & 63;
            float f0 = X[(size_t)(c0 + 2 * kp) * P + n0 + n];
            float f1 = X[(size_t)(c0 + 2 * kp + 1) * P + n0 + n];
            uint32_t h, l;
            split2(f0, f1, h, l);
            smX[buf][0][n * 12 + kp] = h;
            smX[buf][1][n * 12 + kp] = l;
        }
    };

    float acc[2][4][4] = {};

    load(0, 0);
    __syncthreads();

    for (int ch = 0; ch < nch; ch++) {
        int buf = ch & 1;
        if (ch + 1 < nch) load(ch + 1, buf ^ 1);

        uint32_t ah[2][4], al[2][4];
        #pragma unroll
        for (int mt = 0; mt < 2; mt++)
            #pragma unroll
            for (int r = 0; r < 4; r++) {
                int row = wm * 32 + mt * 16 + g + ((r & 1) << 3);
                int kp = tg + ((r >> 1) << 2);
                ah[mt][r] = smW[buf][0][row * 12 + kp];
                al[mt][r] = smW[buf][1][row * 12 + kp];
            }
        #pragma unroll
        for (int nt = 0; nt < 4; nt++) {
            int nrow = wn * 32 + nt * 8 + g;
            uint32_t bh0 = smX[buf][0][nrow * 12 + tg];
            uint32_t bh1 = smX[buf][0][nrow * 12 + tg + 4];
            uint32_t bl0 = smX[buf][1][nrow * 12 + tg];
            uint32_t bl1 = smX[buf][1][nrow * 12 + tg + 4];
            #pragma unroll
            for (int mt = 0; mt < 2; mt++) {
                mma_bf16(acc[mt][nt], ah[mt], bh0, bh1);
                mma_bf16(acc[mt][nt], ah[mt], bl0, bl1);
                mma_bf16(acc[mt][nt], al[mt], bh0, bh1);
            }
        }
        __syncthreads();
    }

    #pragma unroll
    for (int mt = 0; mt < 2; mt++) {
        int mrow = m0 + wm * 32 + mt * 16 + g;
        float bb0 = Bi[mrow], bb1 = Bi[mrow + 8];
        #pragma unroll
        for (int nt = 0; nt < 4; nt++) {
            int col = n0 + wn * 32 + nt * 8 + tg * 2;
            float2 v0 = {acc[mt][nt][0] + bb0, acc[mt][nt][1] + bb0};
            float2 v1 = {acc[mt][nt][2] + bb1, acc[mt][nt][3] + bb1};
            *(float2*)&Y[(size_t)mrow * P + col] = v0;
            *(float2*)&Y[(size_t)(mrow + 8) * P + col] = v1;
        }
    }
}

// ---------------------------------------------------------------------------
// 2x downsample (64x64 -> 32x32): exact 2x2 mean
// ---------------------------------------------------------------------------
__global__ void down2x_k(const float* __restrict__ src, float* __restrict__ dst,
                         int total) {
    int idx = blockIdx.x * blockDim.x + threadIdx.x;
    if (idx >= total) return;
    int x = idx & 31, y = (idx >> 5) & 31, c = idx >> 10;
    const float* s = src + ((size_t)c << 12) + (y << 7) + (x << 1);
    float2 a0 = *(const float2*)s;
    float2 a1 = *(const float2*)(s + 64);
    dst[idx] = 0.25f * ((a0.x + a0.y) + (a1.x + a1.y));
}

// ---------------------------------------------------------------------------
extern "C" void kernel_launch(void* const* d_in, const int* in_sizes, int n_in,
                              void* d_out, int out_size) {
    const float* high = (const float*)d_in[0];
    const float* low  = (const float*)d_in[1];
    const float* qhw = (const float*)d_in[2];  const float* qhb = (const float*)d_in[3];
    const float* khw = (const float*)d_in[4];  const float* khb = (const float*)d_in[5];
    const float* vhw = (const float*)d_in[6];  const float* vhb = (const float*)d_in[7];
    const float* qlw = (const float*)d_in[8];  const float* qlb = (const float*)d_in[9];
    const float* klw = (const float*)d_in[10]; const float* klb = (const float*)d_in[11];
    const float* vlw = (const float*)d_in[12]; const float* vlb = (const float*)d_in[13];
    const float* ohw = (const float*)d_in[14]; const float* ohb = (const float*)d_in[15];
    const float* olw = (const float*)d_in[16]; const float* olb = (const float*)d_in[17];
    float* out = (float*)d_out;

    float* scr = nullptr;
    cudaGetSymbolAddress((void**)&scr, g_scratch);
    float* qh  = scr + OFF_QH;
    float* ah  = scr + OFF_AH;
    float* kls = scr + OFF_KLS;
    float* vls = scr + OFF_VLS;
    float* ql  = scr + OFF_QL;
    float* kh  = scr + OFF_KH;
    float* vh  = scr + OFF_VH;
    float* hd  = scr + OFF_HD;
    float* al  = scr + OFF_AL;

    // 1) downsample high 64->32
    down2x_k<<<(B * 128 * 1024 + 255) / 256, 256>>>(high, hd, B * 128 * 1024);

    // 2) ALL pre-attention convs in one launch (288 CTAs x B)
    {
        ConvBatch cb;
        cb.d[0] = {low, klw, klb, kls, 256, 1024, 16, 0,   256 * 1024, 256 * 1024};
        cb.d[1] = {low, vlw, vlb, vls, 256, 1024, 16, 32,  256 * 1024, 256 * 1024};
        cb.d[2] = {low, qlw, qlb, ql,  256, 1024, 16, 64,  256 * 1024, 256 * 1024};
        cb.d[3] = {hd, khw, khb, kh,   128, 1024, 16, 96,  128 * 1024, 256 * 1024};
        cb.d[4] = {hd, vhw, vhb, vh,   128, 1024, 16, 128, 128 * 1024, 256 * 1024};
        cb.d[5] = {high, qhw, qhb, qh, 128, 4096, 64, 160, 128 * 4096, 256 * 4096};
        cb.nd = 6;
        conv_mma_k<<<dim3(288, 1, B), 256>>>(cb);
    }

    // 3) KV planes (K bf16, V f16; fused upsample + pack)
    prep_kv_k<<<10240, 256>>>();

    // 4) merged attention (high 512 + low 128 CTAs), 4 warps/CTA, 32 rows/warp
    attn2_k<<<640, 128>>>(qh, ah, ql, al);

    // 5) both output projections in one launch (96 CTAs x B)
    {
        ConvBatch cb;
        cb.d[0] = {ah, ohw, ohb, out, 256, 4096, 64, 0, 256 * 4096, 128 * 4096};
        cb.d[1] = {al, olw, olb, out + (size_t)B * 128 * 4096,
                   256, 1024, 16, 64, 256 * 1024, 256 * 1024};
        cb.nd = 2;
        conv_mma_k<<<dim3(96, 1, B), 256>>>(cb);
    }
}

// round 14
// speedup vs baseline: 8.7156x; 1.0299x over previous
#include <cuda_runtime.h>
#include <cuda_bf16.h>
#include <cstdint>
#include <math.h>

// ---------------------------------------------------------------------------
// CrossScaleAttention  (B=2, hidden=256, heads=8, head_dim=32)
// R14: attention KV tile doubled to KT=128 -> half the barriers/waits, double
//      the ILP window per tile. Arithmetic identical to R13 (Q/K bf16, P/V
//      f16, l via ones-MMA, ldmatrix fragment loads shared across m-tiles).
// ---------------------------------------------------------------------------

#define B 2
#define HID 256
#define NHEAD 8
#define HD 32
#define SCALE 0.17677669529663687f
#define QSCALE (SCALE * 1.4426950408889634f)   // fold log2(e): p = ex2(S)
#define KT 128
#define ONES_F16X2 0x3C003C00u

// ---------------- fp32 scratch ----------------
#define OFF_QH   0UL                 // [2,256,4096]
#define OFF_AH   2097152UL           // [2,256,4096]
#define OFF_KLS  4194304UL           // [2,256,1024]
#define OFF_VLS  4718592UL
#define OFF_QL   5242880UL
#define OFF_KH   5767168UL
#define OFF_VH   6291456UL
#define OFF_HD   6815744UL           // [2,128,1024]
#define OFF_AL   7077888UL           // [2,256,1024]
#define SCRATCH_FLOATS 7602176UL
__device__ float g_scratch[SCRATCH_FLOATS];

// ---------------- bf16/f16 KV planes (u32 = 2 packed) ----------------
#define OKH_H 0UL
#define OVH_H 1048576UL
#define OKH_L 2097152UL
#define OVH_L 2359296UL
#define KVU_TOTAL 2621440UL
__device__ uint32_t g_kvu[KVU_TOTAL];

// ---------------- helpers ----------------
__device__ __forceinline__ uint32_t pack2rn(float f0, float f1) {   // bf16x2
    uint32_t r;
    asm("cvt.rn.bf16x2.f32 %0, %1, %2;" : "=r"(r) : "f"(f1), "f"(f0));
    return r;
}
__device__ __forceinline__ uint32_t packf16(float f0, float f1) {   // f16x2
    uint32_t r;
    asm("cvt.rn.f16x2.f32 %0, %1, %2;" : "=r"(r) : "f"(f1), "f"(f0));
    return r;
}
__device__ __forceinline__ uint32_t ex2h2(uint32_t h2) {            // exp2 both halves
    uint32_t r;
    asm("ex2.approx.f16x2 %0, %1;" : "=r"(r) : "r"(h2));
    return r;
}
__device__ __forceinline__ void split2(float f0, float f1, uint32_t& hi, uint32_t& lo) {
    asm("cvt.rn.bf16x2.f32 %0, %1, %2;" : "=r"(hi) : "f"(f1), "f"(f0));
    float h0 = __uint_as_float(hi << 16);
    float h1 = __uint_as_float(hi & 0xFFFF0000u);
    float r0 = f0 - h0, r1 = f1 - h1;
    asm("cvt.rn.bf16x2.f32 %0, %1, %2;" : "=r"(lo) : "f"(r1), "f"(r0));
}

__device__ __forceinline__ void mma_bf16(float* c, const uint32_t* a,
                                         uint32_t b0, uint32_t b1) {
    asm volatile(
        "mma.sync.aligned.m16n8k16.row.col.f32.bf16.bf16.f32 "
        "{%0,%1,%2,%3}, {%4,%5,%6,%7}, {%8,%9}, {%0,%1,%2,%3};"
        : "+f"(c[0]), "+f"(c[1]), "+f"(c[2]), "+f"(c[3])
        : "r"(a[0]), "r"(a[1]), "r"(a[2]), "r"(a[3]), "r"(b0), "r"(b1));
}
__device__ __forceinline__ void mma_f16(float* c, const uint32_t* a,
                                        uint32_t b0, uint32_t b1) {
    asm volatile(
        "mma.sync.aligned.m16n8k16.row.col.f32.f16.f16.f32 "
        "{%0,%1,%2,%3}, {%4,%5,%6,%7}, {%8,%9}, {%0,%1,%2,%3};"
        : "+f"(c[0]), "+f"(c[1]), "+f"(c[2]), "+f"(c[3])
        : "r"(a[0]), "r"(a[1]), "r"(a[2]), "r"(a[3]), "r"(b0), "r"(b1));
}

__device__ __forceinline__ void ldsm_x4(uint32_t* r, uint32_t addr) {
    asm volatile("ldmatrix.sync.aligned.m8n8.x4.shared.b16 {%0,%1,%2,%3}, [%4];"
        : "=r"(r[0]), "=r"(r[1]), "=r"(r[2]), "=r"(r[3]) : "r"(addr));
}

__device__ __forceinline__ uint32_t smem_u32p(const void* p) {
    uint32_t a;
    asm("{ .reg .u64 t; cvta.to.shared.u64 t, %1; cvt.u32.u64 %0, t; }" : "=r"(a) : "l"(p));
    return a;
}
__device__ __forceinline__ void cp16(uint32_t saddr, const void* g) {
    asm volatile("cp.async.ca.shared.global [%0], [%1], 16;" :: "r"(saddr), "l"(g) : "memory");
}
#define CP_COMMIT() asm volatile("cp.async.commit_group;" ::: "memory")
#define CP_WAIT0()  asm volatile("cp.async.wait_group 0;" ::: "memory")

// bilinear 2x upsample sample (32x32 -> 64x64, align_corners=False)
__device__ __forceinline__ float up_sample(const float* __restrict__ s, int y, int x) {
    int y0 = max((y - 1) >> 1, 0), y1 = min((y + 1) >> 1, 31);
    int x0 = max((x - 1) >> 1, 0), x1 = min((x + 1) >> 1, 31);
    float wy = (y & 1) ? 0.25f : 0.75f;
    float wx = (x & 1) ? 0.25f : 0.75f;
    float v00 = s[(y0 << 5) + x0], v01 = s[(y0 << 5) + x1];
    float v10 = s[(y1 << 5) + x0], v11 = s[(y1 << 5) + x1];
    float top = v00 + wx * (v01 - v00);
    float bot = v10 + wx * (v11 - v10);
    return top + wy * (bot - top);
}

// ---------------------------------------------------------------------------
// prep_kv: K planes bf16, V planes f16 (proven).
// ---------------------------------------------------------------------------
__global__ __launch_bounds__(256) void prep_kv_k() {
    const float* kls = g_scratch + OFF_KLS;
    const float* vls = g_scratch + OFF_VLS;
    const float* kh  = g_scratch + OFF_KH;
    const float* vh  = g_scratch + OFF_VH;
    int gid = blockIdx.x * 256 + threadIdx.x;

    if (gid < 1048576) {                 // high K: [bh][key 4096][dp 16] bf16
        int dp = gid & 15, key = (gid >> 4) & 4095, bh = gid >> 16;
        int y = key >> 6, x = key & 63;
        const float* s = kls + (((size_t)(bh >> 3) * 256) + (bh & 7) * 32 + 2 * dp) * 1024;
        g_kvu[OKH_H + gid] = pack2rn(up_sample(s, y, x), up_sample(s + 1024, y, x));
    } else if (gid < 2097152) {          // high V: [bh][d 32][kp 2048] f16
        int g2 = gid - 1048576;
        int kp = g2 & 2047, d = (g2 >> 11) & 31, bh = g2 >> 16;
        int key = kp << 1;
        int y = key >> 6, x = key & 63;
        const float* s = vls + (((size_t)(bh >> 3) * 256) + (bh & 7) * 32 + d) * 1024;
        g_kvu[OVH_H + g2] = packf16(up_sample(s, y, x), up_sample(s, y, x + 1));
    } else if (gid < 2359296) {          // low K: [bh][key 1024][dp 16] bf16
        int g3 = gid - 2097152;
        int dp = g3 & 15, key = (g3 >> 4) & 1023, bh = g3 >> 14;
        const float* s = kh + (((size_t)(bh >> 3) * 256) + (bh & 7) * 32 + 2 * dp) * 1024 + key;
        g_kvu[OKH_L + g3] = pack2rn(s[0], s[1024]);
    } else if (gid < 2621440) {          // low V: [bh][d 32][kp 512] f16
        int g4 = gid - 2359296;
        int kp = g4 & 511, d = (g4 >> 9) & 31, bh = g4 >> 14;
        const float* s = vh + (((size_t)(bh >> 3) * 256) + (bh & 7) * 32 + d) * 1024 + 2 * kp;
        g_kvu[OVH_L + g4] = packf16(s[0], s[1]);
    }
}

// ---------------------------------------------------------------------------
// Merged flash attention. Q/K bf16, P/V f16, fp32 accum; exp via ex2.f16x2;
// l via all-ones MMA. block 128 = 4 warps x 32 query rows; KT=128.
// K tile: [key 128][dp 16 pad 20] u32. V tile: [d 32][kp 64 pad 68] u32.
// ---------------------------------------------------------------------------
__global__ __launch_bounds__(128) void attn2_k(const float* __restrict__ qH,
                                               float* __restrict__ oH,
                                               const float* __restrict__ qL,
                                               float* __restrict__ oL) {
    __shared__ __align__(16) uint32_t Ksm[2][128 * 20];   // 20480 B
    __shared__ __align__(16) uint32_t Vsm[2][32 * 68];    // 17408 B

    int tid = threadIdx.x;
    int w = tid >> 5, lane = tid & 31;
    int g = lane >> 2, tg = lane & 3;

    int cta = blockIdx.x;
    const float* q;
    float* out;
    const uint32_t *Kg, *Vg;
    int N, q0, bh;
    if (cta < 512) {
        N = 4096; bh = cta >> 5; q0 = (cta & 31) << 7;
        q = qH; out = oH;
        Kg = g_kvu + OKH_H + ((size_t)bh << 16);
        Vg = g_kvu + OVH_H + ((size_t)bh << 16);
    } else {
        int idx = cta - 512;
        N = 1024; bh = idx >> 3; q0 = (idx & 7) << 7;
        q = qL; out = oL;
        Kg = g_kvu + OKH_L + ((size_t)bh << 14);
        Vg = g_kvu + OVH_L + ((size_t)bh << 14);
    }
    size_t base = (size_t)32 * bh * N;
    int halfN = N >> 1;

    uint32_t ks0 = smem_u32p(&Ksm[0][0]);
    uint32_t vs0 = smem_u32p(&Vsm[0][0]);

    uint32_t kfrag = ks0 + (lane & 7) * 80 + (lane >> 3) * 16;
    uint32_t vfrag = vs0 + ((lane >> 4) * 8 + (lane & 7)) * 272 + ((lane >> 3) & 1) * 16;

    // ---- Q fragments (bf16, QSCALE folded); warp covers rows q0+w*32..+31 ----
    uint32_t qf[2][2][4];
    #pragma unroll
    for (int mt = 0; mt < 2; mt++)
        #pragma unroll
        for (int kt = 0; kt < 2; kt++)
            #pragma unroll
            for (int r = 0; r < 4; r++) {
                int row = q0 + w * 32 + mt * 16 + g + (r & 1) * 8;
                int d0 = kt * 16 + tg * 2 + (r >> 1) * 8;
                float f0 = q[base + (size_t)d0 * N + row] * QSCALE;
                float f1 = q[base + (size_t)(d0 + 1) * N + row] * QSCALE;
                qf[mt][kt][r] = pack2rn(f0, f1);
            }

    auto load_tile = [&](int buf, int kv0) {
        int kp0 = kv0 >> 1;
        #pragma unroll
        for (int i = 0; i < 4; i++) {        // K: 512 x 16B, 4 per thread
            int id = tid + (i << 7);
            int key = id >> 2, c4 = (id & 3) << 2;
            cp16(ks0 + (uint32_t)(buf * 2560 + key * 20 + c4) * 4,
                 Kg + (size_t)(kv0 + key) * 16 + c4);
        }
        #pragma unroll
        for (int i = 0; i < 4; i++) {        // V: 512 x 16B, 4 per thread
            int id = tid + (i << 7);
            int d = id >> 4, c = (id & 15) << 2;
            cp16(vs0 + (uint32_t)(buf * 2176 + d * 68 + c) * 4,
                 Vg + (size_t)d * halfN + kp0 + c);
        }
        CP_COMMIT();
    };

    float O[2][4][4] = {};
    float lc[2][4] = {};

    load_tile(0, 0);
    CP_WAIT0();
    __syncthreads();

    int T = N / KT;
    for (int it = 0; it < T; it++) {
        int buf = it & 1;
        if (it + 1 < T) load_tile(buf ^ 1, (it + 1) * KT);

        uint32_t kbase = buf * 10240;    // bytes
        uint32_t vbase = buf * 8704;     // bytes

        uint32_t pah[2][4];
        #pragma unroll
        for (int j = 0; j < 16; j++) {
            uint32_t kb[4];
            ldsm_x4(kb, kfrag + kbase + j * 640);   // shared by both m-tiles
            int odd = j & 1;
            #pragma unroll
            for (int mt = 0; mt < 2; mt++) {
                float S[4] = {0.f, 0.f, 0.f, 0.f};
                mma_bf16(S, qf[mt][0], kb[0], kb[1]);
                mma_bf16(S, qf[mt][1], kb[2], kb[3]);
                pah[mt][odd * 2]     = ex2h2(packf16(S[0], S[1]));
                pah[mt][odd * 2 + 1] = ex2h2(packf16(S[2], S[3]));
            }
            if (odd) {
                uint32_t va = vfrag + vbase + (uint32_t)(j >> 1) * 32;
                uint32_t vb[4];
                ldsm_x4(vb, va);                    // jd 0,1 — shared by both mt
                mma_f16(lc[0], pah[0], ONES_F16X2, ONES_F16X2);
                mma_f16(lc[1], pah[1], ONES_F16X2, ONES_F16X2);
                mma_f16(O[0][0], pah[0], vb[0], vb[1]);
                mma_f16(O[0][1], pah[0], vb[2], vb[3]);
                mma_f16(O[1][0], pah[1], vb[0], vb[1]);
                mma_f16(O[1][1], pah[1], vb[2], vb[3]);
                ldsm_x4(vb, va + 4352);             // jd 2,3 (+16 rows * 272B)
                mma_f16(O[0][2], pah[0], vb[0], vb[1]);
                mma_f16(O[0][3], pah[0], vb[2], vb[3]);
                mma_f16(O[1][2], pah[1], vb[0], vb[1]);
                mma_f16(O[1][3], pah[1], vb[2], vb[3]);
            }
        }

        if (it + 1 < T) CP_WAIT0();
        __syncthreads();
    }

    #pragma unroll
    for (int mt = 0; mt < 2; mt++) {
        float inv0 = 1.0f / lc[mt][0];
        float inv1 = 1.0f / lc[mt][2];
        int row0 = q0 + w * 32 + mt * 16 + g;
        #pragma unroll
        for (int jd = 0; jd < 4; jd++) {
            int d0 = jd * 8 + tg * 2;
            out[base + (size_t)d0 * N + row0]           = O[mt][jd][0] * inv0;
            out[base + (size_t)(d0 + 1) * N + row0]     = O[mt][jd][1] * inv0;
            out[base + (size_t)d0 * N + row0 + 8]       = O[mt][jd][2] * inv1;
            out[base + (size_t)(d0 + 1) * N + row0 + 8] = O[mt][jd][3] * inv1;
        }
    }
}

// ---------------------------------------------------------------------------
// Batched conv1x1 (proven): up to 6 GEMM outputs per launch.
// bf16 3-term split, BM=128, BN=64, BK=16, double-buffered.
// ---------------------------------------------------------------------------
struct ConvDesc {
    const float* x;
    const float* w;
    const float* bias;
    float* y;
    int C, P, nblocks, cta0, xbs, ybs;
};
struct ConvBatch {
    ConvDesc d[6];
    int nd;
};

__global__ __launch_bounds__(256) void conv_mma_k(ConvBatch args) {
    __shared__ uint32_t smW[2][2][1536];
    __shared__ uint32_t smX[2][2][768];

    int bx = blockIdx.x;
    int u = 0;
    #pragma unroll
    for (int i = 1; i < 6; i++)
        if (i < args.nd && bx >= args.d[i].cta0) u = i;
    const ConvDesc& D = args.d[u];
    int rem = bx - D.cta0;
    int m0 = (rem / D.nblocks) << 7;
    int n0 = (rem % D.nblocks) << 6;
    int b = blockIdx.z;
    int C = D.C, P = D.P;
    const float* X = D.x + (size_t)b * D.xbs;
    const float* W = D.w;
    const float* Bi = D.bias;
    float* Y = D.y + (size_t)b * D.ybs;
    int nch = C >> 4;

    int tid = threadIdx.x;
    int w = tid >> 5, lane = tid & 31, g = lane >> 2, tg = lane & 3;
    int wm = w >> 1, wn = w & 1;

    auto load = [&](int ch, int buf) {
        int c0 = ch << 4;
        {
            int m = tid >> 1, half = tid & 1;
            const float4* src = reinterpret_cast<const float4*>(
                W + (size_t)(m0 + m) * C + c0 + half * 8);
            float4 f0 = src[0], f1 = src[1];
            uint32_t* dh = &smW[buf][0][m * 12 + half * 4];
            uint32_t* dl = &smW[buf][1][m * 12 + half * 4];
            uint32_t h, l;
            split2(f0.x, f0.y, h, l); dh[0] = h; dl[0] = l;
            split2(f0.z, f0.w, h, l); dh[1] = h; dl[1] = l;
            split2(f1.x, f1.y, h, l); dh[2] = h; dl[2] = l;
            split2(f1.z, f1.w, h, l); dh[3] = h; dl[3] = l;
        }
        #pragma unroll
        for (int i = 0; i < 2; i++) {
            int idx = tid + (i << 8);
            int kp = idx >> 6, n = idx & 63;
            float f0 = X[(size_t)(c0 + 2 * kp) * P + n0 + n];
            float f1 = X[(size_t)(c0 + 2 * kp + 1) * P + n0 + n];
            uint32_t h, l;
            split2(f0, f1, h, l);
            smX[buf][0][n * 12 + kp] = h;
            smX[buf][1][n * 12 + kp] = l;
        }
    };

    float acc[2][4][4] = {};

    load(0, 0);
    __syncthreads();

    for (int ch = 0; ch < nch; ch++) {
        int buf = ch & 1;
        if (ch + 1 < nch) load(ch + 1, buf ^ 1);

        uint32_t ah[2][4], al[2][4];
        #pragma unroll
        for (int mt = 0; mt < 2; mt++)
            #pragma unroll
            for (int r = 0; r < 4; r++) {
                int row = wm * 32 + mt * 16 + g + ((r & 1) << 3);
                int kp = tg + ((r >> 1) << 2);
                ah[mt][r] = smW[buf][0][row * 12 + kp];
                al[mt][r] = smW[buf][1][row * 12 + kp];
            }
        #pragma unroll
        for (int nt = 0; nt < 4; nt++) {
            int nrow = wn * 32 + nt * 8 + g;
            uint32_t bh0 = smX[buf][0][nrow * 12 + tg];
            uint32_t bh1 = smX[buf][0][nrow * 12 + tg + 4];
            uint32_t bl0 = smX[buf][1][nrow * 12 + tg];
            uint32_t bl1 = smX[buf][1][nrow * 12 + tg + 4];
            #pragma unroll
            for (int mt = 0; mt < 2; mt++) {
                mma_bf16(acc[mt][nt], ah[mt], bh0, bh1);
                mma_bf16(acc[mt][nt], ah[mt], bl0, bl1);
                mma_bf16(acc[mt][nt], al[mt], bh0, bh1);
            }
        }
        __syncthreads();
    }

    #pragma unroll
    for (int mt = 0; mt < 2; mt++) {
        int mrow = m0 + wm * 32 + mt * 16 + g;
        float bb0 = Bi[mrow], bb1 = Bi[mrow + 8];
        #pragma unroll
        for (int nt = 0; nt < 4; nt++) {
            int col = n0 + wn * 32 + nt * 8 + tg * 2;
            float2 v0 = {acc[mt][nt][0] + bb0, acc[mt][nt][1] + bb0};
            float2 v1 = {acc[mt][nt][2] + bb1, acc[mt][nt][3] + bb1};
            *(float2*)&Y[(size_t)mrow * P + col] = v0;
            *(float2*)&Y[(size_t)(mrow + 8) * P + col] = v1;
        }
    }
}

// ---------------------------------------------------------------------------
// 2x downsample (64x64 -> 32x32): exact 2x2 mean
// ---------------------------------------------------------------------------
__global__ void down2x_k(const float* __restrict__ src, float* __restrict__ dst,
                         int total) {
    int idx = blockIdx.x * blockDim.x + threadIdx.x;
    if (idx >= total) return;
    int x = idx & 31, y = (idx >> 5) & 31, c = idx >> 10;
    const float* s = src + ((size_t)c << 12) + (y << 7) + (x << 1);
    float2 a0 = *(const float2*)s;
    float2 a1 = *(const float2*)(s + 64);
    dst[idx] = 0.25f * ((a0.x + a0.y) + (a1.x + a1.y));
}

// ---------------------------------------------------------------------------
extern "C" void kernel_launch(void* const* d_in, const int* in_sizes, int n_in,
                              void* d_out, int out_size) {
    const float* high = (const float*)d_in[0];
    const float* low  = (const float*)d_in[1];
    const float* qhw = (const float*)d_in[2];  const float* qhb = (const float*)d_in[3];
    const float* khw = (const float*)d_in[4];  const float* khb = (const float*)d_in[5];
    const float* vhw = (const float*)d_in[6];  const float* vhb = (const float*)d_in[7];
    const float* qlw = (const float*)d_in[8];  const float* qlb = (const float*)d_in[9];
    const float* klw = (const float*)d_in[10]; const float* klb = (const float*)d_in[11];
    const float* vlw = (const float*)d_in[12]; const float* vlb = (const float*)d_in[13];
    const float* ohw = (const float*)d_in[14]; const float* ohb = (const float*)d_in[15];
    const float* olw = (const float*)d_in[16]; const float* olb = (const float*)d_in[17];
    float* out = (float*)d_out;

    float* scr = nullptr;
    cudaGetSymbolAddress((void**)&scr, g_scratch);
    float* qh  = scr + OFF_QH;
    float* ah  = scr + OFF_AH;
    float* kls = scr + OFF_KLS;
    float* vls = scr + OFF_VLS;
    float* ql  = scr + OFF_QL;
    float* kh  = scr + OFF_KH;
    float* vh  = scr + OFF_VH;
    float* hd  = scr + OFF_HD;
    float* al  = scr + OFF_AL;

    // 1) downsample high 64->32
    down2x_k<<<(B * 128 * 1024 + 255) / 256, 256>>>(high, hd, B * 128 * 1024);

    // 2) ALL pre-attention convs in one launch (288 CTAs x B)
    {
        ConvBatch cb;
        cb.d[0] = {low, klw, klb, kls, 256, 1024, 16, 0,   256 * 1024, 256 * 1024};
        cb.d[1] = {low, vlw, vlb, vls, 256, 1024, 16, 32,  256 * 1024, 256 * 1024};
        cb.d[2] = {low, qlw, qlb, ql,  256, 1024, 16, 64,  256 * 1024, 256 * 1024};
        cb.d[3] = {hd, khw, khb, kh,   128, 1024, 16, 96,  128 * 1024, 256 * 1024};
        cb.d[4] = {hd, vhw, vhb, vh,   128, 1024, 16, 128, 128 * 1024, 256 * 1024};
        cb.d[5] = {high, qhw, qhb, qh, 128, 4096, 64, 160, 128 * 4096, 256 * 4096};
        cb.nd = 6;
        conv_mma_k<<<dim3(288, 1, B), 256>>>(cb);
    }

    // 3) KV planes (K bf16, V f16; fused upsample + pack)
    prep_kv_k<<<10240, 256>>>();

    // 4) merged attention (high 512 + low 128 CTAs), 4 warps/CTA, KT=128
    attn2_k<<<640, 128>>>(qh, ah, ql, al);

    // 5) both output projections in one launch (96 CTAs x B)
    {
        ConvBatch cb;
        cb.d[0] = {ah, ohw, ohb, out, 256, 4096, 64, 0, 256 * 4096, 128 * 4096};
        cb.d[1] = {al, olw, olb, out + (size_t)B * 128 * 4096,
                   256, 1024, 16, 64, 256 * 1024, 256 * 1024};
        cb.nd = 2;
        conv_mma_k<<<dim3(96, 1, B), 256>>>(cb);
    }
}